// round 8
// baseline (speedup 1.0000x reference)
#include <cuda_runtime.h>
#include <math.h>

#define N_NODES 8192
#define N_EDGES 65536

typedef unsigned long long ull;

// ---------------- scratch (static device globals; no runtime alloc) ----------------
__device__ float g_S   [N_NODES*64];
__device__ float g_V   [N_NODES*192];
__device__ float g_EDN [N_EDGES];
__device__ float g_TP  [(size_t)N_EDGES*320];
__device__ float g_WM  [(size_t)N_EDGES*832];
__device__ float g_MS  [N_NODES*320];
__device__ float g_MV  [N_NODES*1536];
__device__ float g_AI  [N_NODES*10];          // attrs / (dens+1)
__device__ float g_MSP [N_NODES*64];
__device__ float g_MVP [N_NODES*192];
__device__ int   g_CNT [N_NODES];
__device__ int   g_CUR [N_NODES];
__device__ int   g_OFF [N_NODES+1];
__device__ int   g_SORT[N_EDGES];

__device__ __forceinline__ ull bcast(float f) {
    unsigned int u = __float_as_uint(f);
    ull r;
    asm("mov.b64 %0, {%1, %1};" : "=l"(r) : "r"(u));
    return r;
}
__device__ __forceinline__ ull pack2(float a, float b) {
    return ((ull)__float_as_uint(b) << 32) | __float_as_uint(a);
}
__device__ __forceinline__ void fma2(ull& acc, ull a, ull b) {
    asm("fma.rn.f32x2 %0, %1, %2, %0;" : "+l"(acc) : "l"(a), "l"(b));
}
__device__ __forceinline__ float lo2(ull v) { return __uint_as_float((unsigned int)v); }
__device__ __forceinline__ float hi2(ull v) { return __uint_as_float((unsigned int)(v >> 32)); }
__device__ __forceinline__ float silu(float v) { return v / (1.f + __expf(-v)); }

// ================= fused edge-path kernel (256 threads) =================
// 128 edges per block, 256 threads: 4 rows x 8 cols per thread.
// Activations in smem [k][row]; each layer output is the next layer's A tile.
#define LDH 132
#define SM_MLP ((2*64*LDH + 64*68) * 4)   // hA + hB + Bs = 85 KB

__device__ __forceinline__ void stage_B(float* Bs, const float* __restrict__ src,
                                        int srcStride, int rows, int tid)
{
    for (int i = tid; i < rows * 16; i += 256) {
        int kk = i >> 4, c = (i & 15) * 4;
        *(float4*)(Bs + kk * 68 + c) = *(const float4*)(src + (size_t)kk * srcStride + c);
    }
}

template<int K>
__device__ __forceinline__ void tile_mm(const float* hsrc, const float* Bs,
                                        ull* acc, int tx, int ty)
{
#pragma unroll
    for (int i = 0; i < 16; i++) acc[i] = 0ull;
#pragma unroll 4
    for (int kk = 0; kk < K; kk++) {
        ulonglong2 aA = *(const ulonglong2*)(hsrc + kk * LDH + ty * 4);
        const float4* bp = (const float4*)(Bs + kk * 68 + tx * 8);
        float4 b0 = bp[0], b1 = bp[1];
        ull bb[8];
        bb[0] = bcast(b0.x); bb[1] = bcast(b0.y);
        bb[2] = bcast(b0.z); bb[3] = bcast(b0.w);
        bb[4] = bcast(b1.x); bb[5] = bcast(b1.y);
        bb[6] = bcast(b1.z); bb[7] = bcast(b1.w);
#pragma unroll
        for (int c = 0; c < 8; c++) {
            fma2(acc[c],     aA.x, bb[c]);
            fma2(acc[8 + c], aA.y, bb[c]);
        }
    }
}

// write 4x8 thread tile to global rows (edge-major, row stride rs)
__device__ __forceinline__ void write_gmem(float* dst, int rs, const ull* acc,
                                           float alpha, int tx, int ty)
{
#pragma unroll
    for (int rp = 0; rp < 2; rp++) {
        int r = ty * 4 + rp * 2;
        float* c0 = dst + (size_t)r * rs + tx * 8;
        float* c1 = c0 + rs;
        float4 l0, l1, h0, h1;
        l0.x = lo2(acc[rp*8+0]) * alpha; h0.x = hi2(acc[rp*8+0]) * alpha;
        l0.y = lo2(acc[rp*8+1]) * alpha; h0.y = hi2(acc[rp*8+1]) * alpha;
        l0.z = lo2(acc[rp*8+2]) * alpha; h0.z = hi2(acc[rp*8+2]) * alpha;
        l0.w = lo2(acc[rp*8+3]) * alpha; h0.w = hi2(acc[rp*8+3]) * alpha;
        l1.x = lo2(acc[rp*8+4]) * alpha; h1.x = hi2(acc[rp*8+4]) * alpha;
        l1.y = lo2(acc[rp*8+5]) * alpha; h1.y = hi2(acc[rp*8+5]) * alpha;
        l1.z = lo2(acc[rp*8+6]) * alpha; h1.z = hi2(acc[rp*8+6]) * alpha;
        l1.w = lo2(acc[rp*8+7]) * alpha; h1.w = hi2(acc[rp*8+7]) * alpha;
        *(float4*)(c0)     = l0;
        *(float4*)(c0 + 4) = l1;
        *(float4*)(c1)     = h0;
        *(float4*)(c1 + 4) = h1;
    }
}

// write 4x8 thread tile to smem h-layout [col][row] with silu(alpha*x)
__device__ __forceinline__ void write_h(float* hdst, const ull* acc,
                                        float alpha, int tx, int ty)
{
#pragma unroll
    for (int rp = 0; rp < 2; rp++) {
        int r = ty * 4 + rp * 2;
#pragma unroll
        for (int c = 0; c < 8; c++) {
            float v0 = silu(lo2(acc[rp*8+c]) * alpha);
            float v1 = silu(hi2(acc[rp*8+c]) * alpha);
            *(ull*)(hdst + (tx * 8 + c) * LDH + r) = pack2(v0, v1);
        }
    }
}

__global__ void __launch_bounds__(256) k_mlp(
    const float* __restrict__ EF, const float* __restrict__ MI,
    const int* __restrict__ EI,
    const float* __restrict__ w0, const float* __restrict__ w1,
    const float* __restrict__ w2, const float* __restrict__ w3,
    const float* __restrict__ magw)
{
    extern __shared__ float sm[];
    float* hA = sm;                    // [64][LDH]
    float* hB = sm + 64 * LDH;         // [64][LDH]
    float* Bs = sm + 2 * 64 * LDH;     // [64][68]

    const int tid = threadIdx.x;
    const int tx = tid & 7, ty = tid >> 3;   // ty 0..31
    const size_t e0 = (size_t)blockIdx.x * 128;

    // stage efm into hA rows 0..15 (threads <128: edge_feats; >=128: maginv[sender])
    {
        int le = tid & 127;
        size_t e = e0 + le;
        if (tid < 128) {
            float4 a = *(const float4*)(EF + e * 8);
            float4 b = *(const float4*)(EF + e * 8 + 4);
            hA[0*LDH+le]=a.x; hA[1*LDH+le]=a.y; hA[2*LDH+le]=a.z; hA[3*LDH+le]=a.w;
            hA[4*LDH+le]=b.x; hA[5*LDH+le]=b.y; hA[6*LDH+le]=b.z; hA[7*LDH+le]=b.w;
        } else {
            int snd = EI[e];
            float4 c = *(const float4*)(MI + (size_t)snd * 8);
            float4 d = *(const float4*)(MI + (size_t)snd * 8 + 4);
            hA[ 8*LDH+le]=c.x; hA[ 9*LDH+le]=c.y; hA[10*LDH+le]=c.z; hA[11*LDH+le]=c.w;
            hA[12*LDH+le]=d.x; hA[13*LDH+le]=d.y; hA[14*LDH+le]=d.z; hA[15*LDH+le]=d.w;
        }
    }
    __syncthreads();

    ull acc[16];

    // ---- MLP layer 0: hB = silu(efm @ w0 / 4) ----
    stage_B(Bs, w0, 64, 16, tid);
    __syncthreads();
    tile_mm<16>(hA, Bs, acc, tx, ty);
    write_h(hB, acc, 0.25f, tx, ty);
    __syncthreads();

    // ---- magw projection: WM[e, j*64+c] = efm @ magw / 4 ----
    for (int j = 0; j < 13; j++) {
        stage_B(Bs, magw + j * 64, 832, 16, tid);
        __syncthreads();
        tile_mm<16>(hA, Bs, acc, tx, ty);
        write_gmem(g_WM + e0 * 832 + j * 64, 832, acc, 0.25f, tx, ty);
        __syncthreads();
    }

    // ---- MLP layer 1: hA = silu(hB @ w1 / 8) ----
    stage_B(Bs, w1, 64, 64, tid);
    __syncthreads();
    tile_mm<64>(hB, Bs, acc, tx, ty);
    write_h(hA, acc, 0.125f, tx, ty);
    __syncthreads();

    // ---- MLP layer 2: hB = silu(hA @ w2 / 8) ----
    stage_B(Bs, w2, 64, 64, tid);
    __syncthreads();
    tile_mm<64>(hA, Bs, acc, tx, ty);
    write_h(hB, acc, 0.125f, tx, ty);
    __syncthreads();

    // ---- TP projection: TP[e, j*64+c] = hB @ w3 / 8 ----
    for (int j = 0; j < 5; j++) {
        stage_B(Bs, w3 + j * 64, 320, 64, tid);
        __syncthreads();
        tile_mm<64>(hB, Bs, acc, tx, ty);
        write_gmem(g_TP + e0 * 320 + j * 64, 320, acc, 0.125f, tx, ty);
        __syncthreads();
    }
}

// ================= register-blocked GEMM (node side) =================
template<int RB, int KT, bool SKIP>
__global__ void __launch_bounds__(128) gemmk(
    const float* __restrict__ A, long ars, int acs, long azs,
    const float* __restrict__ B0, const float* __restrict__ Bz, int brs,
    float* __restrict__ C, long crs, int ccs, long czs,
    int K, float alpha, int act,
    const float* __restrict__ MSP, const float* __restrict__ MVP)
{
    const int LDA = RB + 4;
    const int RPT = RB / 16;
    const int PPT = RPT / 2;
    __shared__ float As[KT*(RB+4)];
    __shared__ float Bs[KT*68];

    const int tid = threadIdx.x;
    const int tx = tid & 7;
    const int ty = tid >> 3;
    const long row0 = (long)blockIdx.x * RB;
    const int  col0 = blockIdx.y * 64;
    const int  z = blockIdx.z;
    const float* __restrict__ B = (z == 0) ? B0 : Bz;
    C += (long)z * czs;

    const int arow = tid & (RB - 1);
    const int kseg = (RB == 128) ? 0 : ((tid >> 6) * (KT / 2));
    const int KPT  = (RB == 128) ? KT : KT / 2;

    const float* Arow;
    const float* ai = 0;
    if (SKIP) {
        Arow = (z == 0) ? (MSP + (row0 + arow) * 64)
                        : (MVP + (row0 + arow) * 192 + (z - 1) * 64);
        ai = g_AI + (row0 + arow) * 10;
    } else {
        Arow = A + (long)z * azs + (row0 + arow) * ars;
    }

    ull acc[PPT * 8];
#pragma unroll
    for (int i = 0; i < PPT * 8; i++) acc[i] = 0ull;

    for (int k0 = 0; k0 < K; k0 += KT) {
        if (SKIP) {
#pragma unroll 8
            for (int c = 0; c < KPT; c++) {
                int k = k0 + kseg + c;
                int u = (k * 6554) >> 16;
                int v = k - u * 10;
                As[(kseg + c) * LDA + arow] = Arow[u] * ai[v];
            }
        } else if (acs == 1) {
#pragma unroll
            for (int c = 0; c < KPT / 4; c++) {
                int kk = kseg + c * 4;
                float4 val = make_float4(0.f, 0.f, 0.f, 0.f);
                if (k0 + kk < K)
                    val = *(const float4*)(Arow + k0 + kk);
                As[(kk + 0) * LDA + arow] = val.x;
                As[(kk + 1) * LDA + arow] = val.y;
                As[(kk + 2) * LDA + arow] = val.z;
                As[(kk + 3) * LDA + arow] = val.w;
            }
        } else {
#pragma unroll 8
            for (int c = 0; c < KPT; c++) {
                int kk = kseg + c;
                float v = 0.f;
                if (k0 + kk < K) v = Arow[(long)(k0 + kk) * acs];
                As[kk * LDA + arow] = v;
            }
        }
#pragma unroll
        for (int j = 0; j < KT / 8; j++) {
            int kk = (tid >> 4) + j * 8;
            int c  = (tid & 15) * 4;
            float4 val = make_float4(0.f, 0.f, 0.f, 0.f);
            if (k0 + kk < K)
                val = *(const float4*)(B + (size_t)(k0 + kk) * brs + col0 + c);
            *(float4*)(Bs + kk * 68 + c) = val;
        }
        __syncthreads();

#pragma unroll 4
        for (int kk = 0; kk < KT; kk++) {
            ull ar[PPT];
            {
                const ulonglong2* ap = (const ulonglong2*)(As + kk * LDA + ty * RPT);
                ulonglong2 t0 = ap[0];
                ar[0] = t0.x; ar[1] = t0.y;
                if (RB == 128) {
                    ulonglong2 t1 = ap[1];
                    ar[2] = t1.x; ar[3] = t1.y;
                }
            }
            const float4* bp = (const float4*)(Bs + kk * 68 + tx * 8);
            float4 b0 = bp[0], b1 = bp[1];
            ull bb[8];
            bb[0] = bcast(b0.x); bb[1] = bcast(b0.y);
            bb[2] = bcast(b0.z); bb[3] = bcast(b0.w);
            bb[4] = bcast(b1.x); bb[5] = bcast(b1.y);
            bb[6] = bcast(b1.z); bb[7] = bcast(b1.w);
#pragma unroll
            for (int c = 0; c < 8; c++)
#pragma unroll
                for (int p = 0; p < PPT; p++)
                    fma2(acc[p * 8 + c], ar[p], bb[c]);
        }
        __syncthreads();
    }

#pragma unroll
    for (int rp = 0; rp < PPT; rp++) {
        long r = row0 + ty * RPT + rp * 2;
        float lo[8], hi[8];
#pragma unroll
        for (int c = 0; c < 8; c++) {
            ull av = acc[rp * 8 + c];
            float v0 = lo2(av) * alpha;
            float v1 = hi2(av) * alpha;
            if (act) { v0 = silu(v0); v1 = silu(v1); }
            lo[c] = v0; hi[c] = v1;
        }
        if (ccs == 1) {
            float* c0 = C + r * crs + col0 + tx * 8;
            float* c1 = c0 + crs;
            *(float4*)(c0)     = make_float4(lo[0], lo[1], lo[2], lo[3]);
            *(float4*)(c0 + 4) = make_float4(lo[4], lo[5], lo[6], lo[7]);
            *(float4*)(c1)     = make_float4(hi[0], hi[1], hi[2], hi[3]);
            *(float4*)(c1 + 4) = make_float4(hi[4], hi[5], hi[6], hi[7]);
        } else {
#pragma unroll
            for (int c = 0; c < 8; c++) {
                long col = (long)(col0 + tx * 8 + c) * ccs;
                C[r * crs + col] = lo[c];
                C[(r + 1) * crs + col] = hi[c];
            }
        }
    }
}

// ---------------- counting sort by receiver (hist fused with density) ----------------
__global__ void k_zero()
{
    int i = blockIdx.x * 256 + threadIdx.x;
    if (i < N_NODES) { g_CNT[i] = 0; g_CUR[i] = 0; }
}
__global__ void k_hist(const int* __restrict__ EI, const float* __restrict__ EF,
                       const float* __restrict__ DW)
{
    int e = blockIdx.x * 256 + threadIdx.x;
    atomicAdd(&g_CNT[EI[N_EDGES + e]], 1);
    float d = 0.f;
#pragma unroll
    for (int i = 0; i < 8; i++) d += EF[e * 8 + i] * DW[i];
    d *= 0.3535533905932738f;                     // 1/sqrt(8)
    g_EDN[e] = tanhf(d * d);
}
__global__ void k_scan()
{
    __shared__ int part[1024];
    int t = threadIdx.x;
    int loc[8]; int s = 0;
#pragma unroll
    for (int j = 0; j < 8; j++) { loc[j] = s; s += g_CNT[t * 8 + j]; }
    part[t] = s;
    __syncthreads();
    for (int off = 1; off < 1024; off <<= 1) {
        int v = (t >= off) ? part[t - off] : 0;
        __syncthreads();
        part[t] += v;
        __syncthreads();
    }
    int excl = part[t] - s;
#pragma unroll
    for (int j = 0; j < 8; j++) g_OFF[t * 8 + j] = excl + loc[j];
    if (t == 1023) g_OFF[N_NODES] = part[1023];
}
__global__ void k_scatter(const int* __restrict__ EI)
{
    int e = blockIdx.x * 256 + threadIdx.x;
    int r = EI[N_EDGES + e];
    int p = g_OFF[r] + atomicAdd(&g_CUR[r], 1);
    g_SORT[p] = e;
}

// ---------------- per-node edge combine + segment reduction (pipelined) ----------------
__global__ void __launch_bounds__(64) k_mm(const float* __restrict__ EA,
                                           const float* __restrict__ MA,
                                           const int* __restrict__ EI,
                                           const float* __restrict__ ATTR)
{
    const int n = blockIdx.x;
    const int u = threadIdx.x;
    const int beg = g_OFF[n], end = g_OFF[n + 1];

    float as0 = 0, as1 = 0, as2 = 0, as3 = 0, as4 = 0;
    float av[8][3];
#pragma unroll
    for (int j = 0; j < 8; j++)
#pragma unroll
        for (int i = 0; i < 3; i++) av[j][i] = 0.f;
    float dens = 0.f;

    const float I3 = 0.5773502691896258f;   // 1/sqrt(3)
    const float I2 = 0.7071067811865476f;   // 1/sqrt(2)

    // current-edge payload registers (software pipeline)
    float4 ea_c = make_float4(0,0,0,0), ma_c = make_float4(0,0,0,0);
    float xs_c = 0, vx_c = 0, vy_c = 0, vz_c = 0, ed_c = 0;
    float t_c[5], w_c[13];
    int e1 = 0, s1 = 0;
#pragma unroll
    for (int i = 0; i < 5; i++) t_c[i] = 0.f;
#pragma unroll
    for (int i = 0; i < 13; i++) w_c[i] = 0.f;

    if (beg < end) {
        int ec = g_SORT[beg]; int sc = EI[ec];
        ea_c = *(const float4*)(EA + (size_t)ec * 4);
        ma_c = *(const float4*)(MA + (size_t)sc * 4);
        xs_c = g_S[(size_t)sc * 64 + u];
        const float* vp = g_V + (size_t)sc * 192 + u;
        vx_c = vp[0]; vy_c = vp[64]; vz_c = vp[128];
        const float* tp = g_TP + (size_t)ec * 320 + u;
#pragma unroll
        for (int i = 0; i < 5; i++) t_c[i] = tp[i * 64];
        const float* wm = g_WM + (size_t)ec * 832 + u;
#pragma unroll
        for (int i = 0; i < 13; i++) w_c[i] = wm[i * 64];
        ed_c = g_EDN[ec];
        if (beg + 1 < end) { e1 = g_SORT[beg + 1]; s1 = EI[e1]; }
    }

    for (int q = beg; q < end; q++) {
        // ---- issue next edge's payload loads (overlap with compute) ----
        float4 ea_n = make_float4(0,0,0,0), ma_n = make_float4(0,0,0,0);
        float xs_n = 0, vx_n = 0, vy_n = 0, vz_n = 0, ed_n = 0;
        float t_n[5], w_n[13];
#pragma unroll
        for (int i = 0; i < 5; i++) t_n[i] = 0.f;
#pragma unroll
        for (int i = 0; i < 13; i++) w_n[i] = 0.f;
        int e2 = 0, s2 = 0;
        if (q + 1 < end) {
            ea_n = *(const float4*)(EA + (size_t)e1 * 4);
            ma_n = *(const float4*)(MA + (size_t)s1 * 4);
            xs_n = g_S[(size_t)s1 * 64 + u];
            const float* vp = g_V + (size_t)s1 * 192 + u;
            vx_n = vp[0]; vy_n = vp[64]; vz_n = vp[128];
            const float* tp = g_TP + (size_t)e1 * 320 + u;
#pragma unroll
            for (int i = 0; i < 5; i++) t_n[i] = tp[i * 64];
            const float* wm = g_WM + (size_t)e1 * 832 + u;
#pragma unroll
            for (int i = 0; i < 13; i++) w_n[i] = wm[i * 64];
            ed_n = g_EDN[e1];
            if (q + 2 < end) { e2 = g_SORT[q + 2]; s2 = EI[e2]; }
        }

        // ---- compute with current payload ----
        const float y0 = ea_c.x, yx = ea_c.y, yy = ea_c.z, yz = ea_c.w;
        const float m0 = ma_c.x, mx = ma_c.y, my = ma_c.z, mz = ma_c.w;
        const float xs = xs_c, vx = vx_c, vy = vy_c, vz = vz_c;

        const float ms0 = t_c[0] * xs * y0;
        const float A0x = t_c[1] * xs * yx, A0y = t_c[1] * xs * yy, A0z = t_c[1] * xs * yz;
        const float B0x = t_c[2] * vx * y0, B0y = t_c[2] * vy * y0, B0z = t_c[2] * vz * y0;
        const float ms1 = t_c[3] * (vx * yx + vy * yy + vz * yz) * I3;
        const float cx = vy * yz - vz * yy;
        const float cy = vz * yx - vx * yz;
        const float cz = vx * yy - vy * yx;
        const float C0x = t_c[4] * cx * I2, C0y = t_c[4] * cy * I2, C0z = t_c[4] * cz * I2;

        as0 += w_c[0] * ms0 * m0;
        { float w_ = w_c[1] * ms0;  av[0][0] += w_ * mx; av[0][1] += w_ * my; av[0][2] += w_ * mz; }
        as1 += w_c[2] * ms1 * m0;
        { float w_ = w_c[3] * ms1;  av[1][0] += w_ * mx; av[1][1] += w_ * my; av[1][2] += w_ * mz; }

        { float w_ = w_c[4] * m0;   av[2][0] += w_ * A0x; av[2][1] += w_ * A0y; av[2][2] += w_ * A0z; }
        as2 += w_c[5] * (A0x * mx + A0y * my + A0z * mz) * I3;
        { float w_ = w_c[6] * I2;
          av[3][0] += w_ * (A0y * mz - A0z * my);
          av[3][1] += w_ * (A0z * mx - A0x * mz);
          av[3][2] += w_ * (A0x * my - A0y * mx); }

        { float w_ = w_c[7] * m0;   av[4][0] += w_ * B0x; av[4][1] += w_ * B0y; av[4][2] += w_ * B0z; }
        as3 += w_c[8] * (B0x * mx + B0y * my + B0z * mz) * I3;
        { float w_ = w_c[9] * I2;
          av[5][0] += w_ * (B0y * mz - B0z * my);
          av[5][1] += w_ * (B0z * mx - B0x * mz);
          av[5][2] += w_ * (B0x * my - B0y * mx); }

        { float w_ = w_c[10] * m0;  av[6][0] += w_ * C0x; av[6][1] += w_ * C0y; av[6][2] += w_ * C0z; }
        as4 += w_c[11] * (C0x * mx + C0y * my + C0z * mz) * I3;
        { float w_ = w_c[12] * I2;
          av[7][0] += w_ * (C0y * mz - C0z * my);
          av[7][1] += w_ * (C0z * mx - C0x * mz);
          av[7][2] += w_ * (C0x * my - C0y * mx); }

        dens += ed_c;

        // ---- rotate pipeline ----
        ea_c = ea_n; ma_c = ma_n;
        xs_c = xs_n; vx_c = vx_n; vy_c = vy_n; vz_c = vz_n; ed_c = ed_n;
#pragma unroll
        for (int i = 0; i < 5; i++) t_c[i] = t_n[i];
#pragma unroll
        for (int i = 0; i < 13; i++) w_c[i] = w_n[i];
        e1 = e2; s1 = s2;
    }

    const size_t b = (size_t)n * 320 + u;
    g_MS[b]       = as0;
    g_MS[b + 64]  = as1;
    g_MS[b + 128] = as2;
    g_MS[b + 192] = as3;
    g_MS[b + 256] = as4;
    const size_t bv = (size_t)n * 1536 + u;
#pragma unroll
    for (int i = 0; i < 3; i++)
#pragma unroll
        for (int j = 0; j < 8; j++)
            g_MV[bv + i * 512 + j * 64] = av[j][i];
    if (u < 10) g_AI[n * 10 + u] = ATTR[n * 10 + u] / (dens + 1.f);
}

// ---------------- launcher ----------------
extern "C" void kernel_launch(void* const* d_in, const int* in_sizes, int n_in,
                              void* d_out, int out_size)
{
    (void)in_sizes; (void)n_in; (void)out_size;
    const float* node_attrs = (const float*)d_in[0];
    const float* node_feats = (const float*)d_in[1];
    const float* edge_attrs = (const float*)d_in[2];
    const float* edge_feats = (const float*)d_in[3];
    const int*   edge_index = (const int*)  d_in[4];
    const float* maginv     = (const float*)d_in[5];
    const float* magattr    = (const float*)d_in[6];
    const float* Wups       = (const float*)d_in[7];
    const float* Wupv       = (const float*)d_in[8];
    const float* w0         = (const float*)d_in[9];
    const float* w1         = (const float*)d_in[10];
    const float* w2         = (const float*)d_in[11];
    const float* w3         = (const float*)d_in[12];
    const float* magw       = (const float*)d_in[13];
    const float* densw      = (const float*)d_in[14];
    const float* lins       = (const float*)d_in[15];
    const float* linv       = (const float*)d_in[16];
    const float* skips      = (const float*)d_in[17];
    const float* skipv      = (const float*)d_in[18];
    float* out = (float*)d_out;

    float *pS, *pV, *pMS, *pMV, *pMSP, *pMVP;
    cudaGetSymbolAddress((void**)&pS,   g_S);
    cudaGetSymbolAddress((void**)&pV,   g_V);
    cudaGetSymbolAddress((void**)&pMS,  g_MS);
    cudaGetSymbolAddress((void**)&pMV,  g_MV);
    cudaGetSymbolAddress((void**)&pMSP, g_MSP);
    cudaGetSymbolAddress((void**)&pMVP, g_MVP);

    cudaFuncSetAttribute(k_mlp, cudaFuncAttributeMaxDynamicSharedMemorySize, SM_MLP);

    const float a8   = 0.125f;
    const float a320 = 1.f / sqrtf(320.f);
    const float a512 = 1.f / sqrtf(512.f);
    const float a640 = 1.f / sqrtf(640.f);

    // sort bookkeeping first so k_mlp lands in profile slot 3
    k_zero   <<<N_NODES/256, 256>>>();                                   // 0
    k_hist   <<<N_EDGES/256, 256>>>(edge_index, edge_feats, densw);      // 1
    k_scan   <<<1, 1024>>>();                                            // 2

    // fused edge path: efm + MLP + WM + TP in one kernel                // 3 (profiled)
    k_mlp<<<N_EDGES/128, 256, SM_MLP>>>(edge_feats, maginv, edge_index,
                                        w0, w1, w2, w3, magw);

    k_scatter<<<N_EDGES/256, 256>>>(edge_index);                         // 4

    // node up-projection
    gemmk<64,32,false><<<dim3(N_NODES/64, 1, 1), 128>>>(node_feats, 256, 1, 0, Wups, Wups, 64,
                                                        pS, 64, 1, 0, 64, a8, 0, 0, 0);
    gemmk<64,32,false><<<dim3(N_NODES/64, 1, 3), 128>>>(node_feats + 64, 256, 3, 1, Wupv, Wupv, 64,
                                                        pV, 192, 1, 64, 64, a8, 0, 0, 0);

    // per-node tensor-product combine + segment reduction (+ g_AI)
    k_mm<<<N_NODES, 64>>>(edge_attrs, magattr, edge_index, node_attrs);

    // lin_s / lin_v
    gemmk<64,32,false><<<dim3(N_NODES/64, 1, 1), 128>>>(pMS, 320, 1, 0, lins, lins, 64,
                                                        pMSP, 64, 1, 0, 320, a320, 0, 0, 0);
    gemmk<64,32,false><<<dim3(N_NODES/64, 1, 3), 128>>>(pMV, 1536, 1, 512, linv, linv, 64,
                                                        pMVP, 192, 1, 64, 512, a512, 0, 0, 0);

    // skip einsum: coefficients built on the fly in A-staging
    gemmk<64,32,true><<<dim3(N_NODES/64, 1, 4), 128>>>(0, 0, 0, 0, skips, skipv, 64,
                                                       out, 256, 4, 1, 640, a640, 0, pMSP, pMVP);
}

// round 9
// speedup vs baseline: 1.0656x; 1.0656x over previous
#include <cuda_runtime.h>
#include <math.h>

#define N_NODES 8192
#define N_EDGES 65536

typedef unsigned long long ull;

// ---------------- scratch (static device globals; zero-initialized) ----------------
__device__ float g_S   [N_NODES*64];
__device__ float g_V   [N_NODES*192];
__device__ float g_EDN [N_EDGES];
__device__ float g_TP  [(size_t)N_EDGES*320];   // sorted-order
__device__ float g_WM  [(size_t)N_EDGES*832];   // sorted-order
__device__ float g_MS  [N_NODES*320];
__device__ float g_MV  [N_NODES*1536];
__device__ float g_AI  [N_NODES*10];
__device__ float g_MSP [N_NODES*64];
__device__ float g_MVP [N_NODES*192];
__device__ int   g_CNT [N_NODES];
__device__ int   g_CUR [N_NODES];
__device__ int   g_OFF [N_NODES+1];
__device__ int   g_SORT[N_EDGES];
__device__ int   g_SNDS[N_EDGES];               // sender id, sorted order
__device__ float4 g_EAS[N_EDGES];               // edge_attrs, sorted order
__device__ float g_EDNS[N_EDGES];               // density, sorted order

__device__ __forceinline__ ull bcast(float f) {
    unsigned int u = __float_as_uint(f);
    ull r;
    asm("mov.b64 %0, {%1, %1};" : "=l"(r) : "r"(u));
    return r;
}
__device__ __forceinline__ ull pack2(float a, float b) {
    return ((ull)__float_as_uint(b) << 32) | __float_as_uint(a);
}
__device__ __forceinline__ void fma2(ull& acc, ull a, ull b) {
    asm("fma.rn.f32x2 %0, %1, %2, %0;" : "+l"(acc) : "l"(a), "l"(b));
}
__device__ __forceinline__ float lo2(ull v) { return __uint_as_float((unsigned int)v); }
__device__ __forceinline__ float hi2(ull v) { return __uint_as_float((unsigned int)(v >> 32)); }
__device__ __forceinline__ float silu(float v) { return v / (1.f + __expf(-v)); }

// ================= fused edge-path kernel (128 threads, sorted output) =================
#define LDH 132
#define SM_MLP ((2*64*LDH + 64*68) * 4)   // hA + hB + Bs = 85 KB

__device__ __forceinline__ void stage_B(float* Bs, const float* __restrict__ src,
                                        int srcStride, int rows, int tid)
{
    for (int j = 0; j < rows / 8; j++) {
        int kk = (tid >> 4) + j * 8;
        int c  = (tid & 15) * 4;
        *(float4*)(Bs + kk * 68 + c) = *(const float4*)(src + (size_t)kk * srcStride + c);
    }
}

template<int K>
__device__ __forceinline__ void tile_mm(const float* hsrc, const float* Bs,
                                        ull* acc, int tx, int ty)
{
#pragma unroll
    for (int i = 0; i < 32; i++) acc[i] = 0ull;
#pragma unroll 4
    for (int kk = 0; kk < K; kk++) {
        const ulonglong2* ap = (const ulonglong2*)(hsrc + kk * LDH + ty * 8);
        ulonglong2 aA = ap[0];
        ulonglong2 aB = ap[1];
        const float4* bp = (const float4*)(Bs + kk * 68 + tx * 8);
        float4 b0 = bp[0], b1 = bp[1];
        ull bb[8];
        bb[0] = bcast(b0.x); bb[1] = bcast(b0.y);
        bb[2] = bcast(b0.z); bb[3] = bcast(b0.w);
        bb[4] = bcast(b1.x); bb[5] = bcast(b1.y);
        bb[6] = bcast(b1.z); bb[7] = bcast(b1.w);
#pragma unroll
        for (int c = 0; c < 8; c++) {
            fma2(acc[c],      aA.x, bb[c]);
            fma2(acc[8 + c],  aA.y, bb[c]);
            fma2(acc[16 + c], aB.x, bb[c]);
            fma2(acc[24 + c], aB.y, bb[c]);
        }
    }
}

__device__ __forceinline__ void write_gmem(float* dst, int rs, const ull* acc,
                                           float alpha, int tx, int ty)
{
#pragma unroll
    for (int rp = 0; rp < 4; rp++) {
        int r = ty * 8 + rp * 2;
        float* c0 = dst + (size_t)r * rs + tx * 8;
        float* c1 = c0 + rs;
        float4 l0, l1, h0, h1;
        l0.x = lo2(acc[rp*8+0]) * alpha; h0.x = hi2(acc[rp*8+0]) * alpha;
        l0.y = lo2(acc[rp*8+1]) * alpha; h0.y = hi2(acc[rp*8+1]) * alpha;
        l0.z = lo2(acc[rp*8+2]) * alpha; h0.z = hi2(acc[rp*8+2]) * alpha;
        l0.w = lo2(acc[rp*8+3]) * alpha; h0.w = hi2(acc[rp*8+3]) * alpha;
        l1.x = lo2(acc[rp*8+4]) * alpha; h1.x = hi2(acc[rp*8+4]) * alpha;
        l1.y = lo2(acc[rp*8+5]) * alpha; h1.y = hi2(acc[rp*8+5]) * alpha;
        l1.z = lo2(acc[rp*8+6]) * alpha; h1.z = hi2(acc[rp*8+6]) * alpha;
        l1.w = lo2(acc[rp*8+7]) * alpha; h1.w = hi2(acc[rp*8+7]) * alpha;
        *(float4*)(c0)     = l0;
        *(float4*)(c0 + 4) = l1;
        *(float4*)(c1)     = h0;
        *(float4*)(c1 + 4) = h1;
    }
}

__device__ __forceinline__ void write_h(float* hdst, const ull* acc,
                                        float alpha, int tx, int ty)
{
#pragma unroll
    for (int rp = 0; rp < 4; rp++) {
        int r = ty * 8 + rp * 2;
#pragma unroll
        for (int c = 0; c < 8; c++) {
            float v0 = silu(lo2(acc[rp*8+c]) * alpha);
            float v1 = silu(hi2(acc[rp*8+c]) * alpha);
            *(ull*)(hdst + (tx * 8 + c) * LDH + r) = pack2(v0, v1);
        }
    }
}

__global__ void __launch_bounds__(128) k_mlp(
    const float* __restrict__ EF, const float* __restrict__ MI,
    const int* __restrict__ EI,
    const float* __restrict__ w0, const float* __restrict__ w1,
    const float* __restrict__ w2, const float* __restrict__ w3,
    const float* __restrict__ magw)
{
    extern __shared__ float sm[];
    float* hA = sm;
    float* hB = sm + 64 * LDH;
    float* Bs = sm + 2 * 64 * LDH;

    const int tid = threadIdx.x;
    const int tx = tid & 7, ty = tid >> 3;
    const size_t e0 = (size_t)blockIdx.x * 128;

    // stage efm for SORTED edge position e0+tid
    {
        int eid = g_SORT[e0 + tid];
        float4 a = *(const float4*)(EF + (size_t)eid * 8);
        float4 b = *(const float4*)(EF + (size_t)eid * 8 + 4);
        int snd = EI[eid];
        float4 c = *(const float4*)(MI + (size_t)snd * 8);
        float4 d = *(const float4*)(MI + (size_t)snd * 8 + 4);
        hA[ 0*LDH+tid]=a.x; hA[ 1*LDH+tid]=a.y; hA[ 2*LDH+tid]=a.z; hA[ 3*LDH+tid]=a.w;
        hA[ 4*LDH+tid]=b.x; hA[ 5*LDH+tid]=b.y; hA[ 6*LDH+tid]=b.z; hA[ 7*LDH+tid]=b.w;
        hA[ 8*LDH+tid]=c.x; hA[ 9*LDH+tid]=c.y; hA[10*LDH+tid]=c.z; hA[11*LDH+tid]=c.w;
        hA[12*LDH+tid]=d.x; hA[13*LDH+tid]=d.y; hA[14*LDH+tid]=d.z; hA[15*LDH+tid]=d.w;
    }
    __syncthreads();

    ull acc[32];

    // ---- MLP layer 0 ----
    stage_B(Bs, w0, 64, 16, tid);
    __syncthreads();
    tile_mm<16>(hA, Bs, acc, tx, ty);
    write_h(hB, acc, 0.25f, tx, ty);
    __syncthreads();

    // ---- magw projection (writes in sorted order) ----
    for (int j = 0; j < 13; j++) {
        stage_B(Bs, magw + j * 64, 832, 16, tid);
        __syncthreads();
        tile_mm<16>(hA, Bs, acc, tx, ty);
        write_gmem(g_WM + e0 * 832 + j * 64, 832, acc, 0.25f, tx, ty);
        __syncthreads();
    }

    // ---- MLP layers 1, 2 ----
    stage_B(Bs, w1, 64, 64, tid);
    __syncthreads();
    tile_mm<64>(hB, Bs, acc, tx, ty);
    write_h(hA, acc, 0.125f, tx, ty);
    __syncthreads();

    stage_B(Bs, w2, 64, 64, tid);
    __syncthreads();
    tile_mm<64>(hA, Bs, acc, tx, ty);
    write_h(hB, acc, 0.125f, tx, ty);
    __syncthreads();

    // ---- TP projection (sorted order) ----
    for (int j = 0; j < 5; j++) {
        stage_B(Bs, w3 + j * 64, 320, 64, tid);
        __syncthreads();
        tile_mm<64>(hB, Bs, acc, tx, ty);
        write_gmem(g_TP + e0 * 320 + j * 64, 320, acc, 0.125f, tx, ty);
        __syncthreads();
    }
}

// ================= register-blocked GEMM (node side) =================
template<int RB, int KT, bool SKIP>
__global__ void __launch_bounds__(128) gemmk(
    const float* __restrict__ A, long ars, int acs, long azs,
    const float* __restrict__ B0, const float* __restrict__ Bz, int brs,
    float* __restrict__ C, long crs, int ccs, long czs,
    int K, float alpha, int act,
    const float* __restrict__ MSP, const float* __restrict__ MVP)
{
    const int LDA = RB + 4;
    const int RPT = RB / 16;
    const int PPT = RPT / 2;
    __shared__ float As[KT*(RB+4)];
    __shared__ float Bs[KT*68];

    const int tid = threadIdx.x;
    const int tx = tid & 7;
    const int ty = tid >> 3;
    const long row0 = (long)blockIdx.x * RB;
    const int  col0 = blockIdx.y * 64;
    const int  z = blockIdx.z;
    const float* __restrict__ B = (z == 0) ? B0 : Bz;
    C += (long)z * czs;

    const int arow = tid & (RB - 1);
    const int kseg = (RB == 128) ? 0 : ((tid >> 6) * (KT / 2));
    const int KPT  = (RB == 128) ? KT : KT / 2;

    const float* Arow;
    const float* ai = 0;
    if (SKIP) {
        Arow = (z == 0) ? (MSP + (row0 + arow) * 64)
                        : (MVP + (row0 + arow) * 192 + (z - 1) * 64);
        ai = g_AI + (row0 + arow) * 10;
    } else {
        Arow = A + (long)z * azs + (row0 + arow) * ars;
    }

    ull acc[PPT * 8];
#pragma unroll
    for (int i = 0; i < PPT * 8; i++) acc[i] = 0ull;

    for (int k0 = 0; k0 < K; k0 += KT) {
        if (SKIP) {
#pragma unroll 8
            for (int c = 0; c < KPT; c++) {
                int k = k0 + kseg + c;
                int u = (k * 6554) >> 16;
                int v = k - u * 10;
                As[(kseg + c) * LDA + arow] = Arow[u] * ai[v];
            }
        } else if (acs == 1) {
#pragma unroll
            for (int c = 0; c < KPT / 4; c++) {
                int kk = kseg + c * 4;
                float4 val = make_float4(0.f, 0.f, 0.f, 0.f);
                if (k0 + kk < K)
                    val = *(const float4*)(Arow + k0 + kk);
                As[(kk + 0) * LDA + arow] = val.x;
                As[(kk + 1) * LDA + arow] = val.y;
                As[(kk + 2) * LDA + arow] = val.z;
                As[(kk + 3) * LDA + arow] = val.w;
            }
        } else {
#pragma unroll 8
            for (int c = 0; c < KPT; c++) {
                int kk = kseg + c;
                float v = 0.f;
                if (k0 + kk < K) v = Arow[(long)(k0 + kk) * acs];
                As[kk * LDA + arow] = v;
            }
        }
#pragma unroll
        for (int j = 0; j < KT / 8; j++) {
            int kk = (tid >> 4) + j * 8;
            int c  = (tid & 15) * 4;
            float4 val = make_float4(0.f, 0.f, 0.f, 0.f);
            if (k0 + kk < K)
                val = *(const float4*)(B + (size_t)(k0 + kk) * brs + col0 + c);
            *(float4*)(Bs + kk * 68 + c) = val;
        }
        __syncthreads();

#pragma unroll 4
        for (int kk = 0; kk < KT; kk++) {
            ull ar[PPT];
            {
                const ulonglong2* ap = (const ulonglong2*)(As + kk * LDA + ty * RPT);
                ulonglong2 t0 = ap[0];
                ar[0] = t0.x; ar[1] = t0.y;
                if (RB == 128) {
                    ulonglong2 t1 = ap[1];
                    ar[2] = t1.x; ar[3] = t1.y;
                }
            }
            const float4* bp = (const float4*)(Bs + kk * 68 + tx * 8);
            float4 b0 = bp[0], b1 = bp[1];
            ull bb[8];
            bb[0] = bcast(b0.x); bb[1] = bcast(b0.y);
            bb[2] = bcast(b0.z); bb[3] = bcast(b0.w);
            bb[4] = bcast(b1.x); bb[5] = bcast(b1.y);
            bb[6] = bcast(b1.z); bb[7] = bcast(b1.w);
#pragma unroll
            for (int c = 0; c < 8; c++)
#pragma unroll
                for (int p = 0; p < PPT; p++)
                    fma2(acc[p * 8 + c], ar[p], bb[c]);
        }
        __syncthreads();
    }

#pragma unroll
    for (int rp = 0; rp < PPT; rp++) {
        long r = row0 + ty * RPT + rp * 2;
        float lo[8], hi[8];
#pragma unroll
        for (int c = 0; c < 8; c++) {
            ull av = acc[rp * 8 + c];
            float v0 = lo2(av) * alpha;
            float v1 = hi2(av) * alpha;
            if (act) { v0 = silu(v0); v1 = silu(v1); }
            lo[c] = v0; hi[c] = v1;
        }
        if (ccs == 1) {
            float* c0 = C + r * crs + col0 + tx * 8;
            float* c1 = c0 + crs;
            *(float4*)(c0)     = make_float4(lo[0], lo[1], lo[2], lo[3]);
            *(float4*)(c0 + 4) = make_float4(lo[4], lo[5], lo[6], lo[7]);
            *(float4*)(c1)     = make_float4(hi[0], hi[1], hi[2], hi[3]);
            *(float4*)(c1 + 4) = make_float4(hi[4], hi[5], hi[6], hi[7]);
        } else {
#pragma unroll
            for (int c = 0; c < 8; c++) {
                long col = (long)(col0 + tx * 8 + c) * ccs;
                C[r * crs + col] = lo[c];
                C[(r + 1) * crs + col] = hi[c];
            }
        }
    }
}

// ---------------- sort: hist(+density) -> scan(re-zero CNT) -> scatter(+sorted copies) ----
__global__ void k_hist(const int* __restrict__ EI, const float* __restrict__ EF,
                       const float* __restrict__ DW)
{
    int e = blockIdx.x * 256 + threadIdx.x;
    atomicAdd(&g_CNT[EI[N_EDGES + e]], 1);
    float d = 0.f;
#pragma unroll
    for (int i = 0; i < 8; i++) d += EF[e * 8 + i] * DW[i];
    d *= 0.3535533905932738f;
    g_EDN[e] = tanhf(d * d);
}
__global__ void k_scan()
{
    __shared__ int part[1024];
    int t = threadIdx.x;
    int loc[8]; int s = 0;
#pragma unroll
    for (int j = 0; j < 8; j++) { loc[j] = s; s += g_CNT[t * 8 + j]; }
    part[t] = s;
    __syncthreads();
    for (int off = 1; off < 1024; off <<= 1) {
        int v = (t >= off) ? part[t - off] : 0;
        __syncthreads();
        part[t] += v;
        __syncthreads();
    }
    int excl = part[t] - s;
#pragma unroll
    for (int j = 0; j < 8; j++) {
        g_OFF[t * 8 + j] = excl + loc[j];
        g_CNT[t * 8 + j] = 0;            // re-zero for next graph replay
    }
    if (t == 1023) g_OFF[N_NODES] = part[1023];
}
__global__ void k_scatter(const int* __restrict__ EI, const float* __restrict__ EA)
{
    int e = blockIdx.x * 256 + threadIdx.x;
    int r = EI[N_EDGES + e];
    int p = g_OFF[r] + atomicAdd(&g_CUR[r], 1);
    g_SORT[p] = e;
    g_SNDS[p] = EI[e];
    g_EAS[p]  = *(const float4*)(EA + (size_t)e * 4);
    g_EDNS[p] = g_EDN[e];
}

// ---------------- per-node combine: sequential TP/WM/EA/EDN, pipelined node gathers ----
__global__ void __launch_bounds__(64) k_mm(const float* __restrict__ MA,
                                           const float* __restrict__ ATTR)
{
    const int n = blockIdx.x;
    const int u = threadIdx.x;
    const int beg = g_OFF[n], end = g_OFF[n + 1];

    float as0 = 0, as1 = 0, as2 = 0, as3 = 0, as4 = 0;
    float av[8][3];
#pragma unroll
    for (int j = 0; j < 8; j++)
#pragma unroll
        for (int i = 0; i < 3; i++) av[j][i] = 0.f;
    float dens = 0.f;

    const float I3 = 0.5773502691896258f;
    const float I2 = 0.7071067811865476f;

    // pipelined node-payload (random gathers): ma, xs, v
    float4 ma_c = make_float4(0,0,0,0);
    float xs_c = 0, vx_c = 0, vy_c = 0, vz_c = 0;
    if (beg < end) {
        int sc = g_SNDS[beg];
        ma_c = *(const float4*)(MA + (size_t)sc * 4);
        xs_c = g_S[(size_t)sc * 64 + u];
        const float* vp = g_V + (size_t)sc * 192 + u;
        vx_c = vp[0]; vy_c = vp[64]; vz_c = vp[128];
    }

    for (int q = beg; q < end; q++) {
        // prefetch next node payload
        float4 ma_n = make_float4(0,0,0,0);
        float xs_n = 0, vx_n = 0, vy_n = 0, vz_n = 0;
        if (q + 1 < end) {
            int sn = g_SNDS[q + 1];
            ma_n = *(const float4*)(MA + (size_t)sn * 4);
            xs_n = g_S[(size_t)sn * 64 + u];
            const float* vp = g_V + (size_t)sn * 192 + u;
            vx_n = vp[0]; vy_n = vp[64]; vz_n = vp[128];
        }

        // sequential payload
        const float4 eav = g_EAS[q];
        const float y0 = eav.x, yx = eav.y, yy = eav.z, yz = eav.w;
        const float* tp = g_TP + (size_t)q * 320 + u;
        const float t0 = tp[0], t1 = tp[64], t2 = tp[128], t3 = tp[192], t4 = tp[256];
        const float* wm = g_WM + (size_t)q * 832 + u;

        const float m0 = ma_c.x, mx = ma_c.y, my = ma_c.z, mz = ma_c.w;
        const float xs = xs_c, vx = vx_c, vy = vy_c, vz = vz_c;

        const float ms0 = t0 * xs * y0;
        const float A0x = t1 * xs * yx, A0y = t1 * xs * yy, A0z = t1 * xs * yz;
        const float B0x = t2 * vx * y0, B0y = t2 * vy * y0, B0z = t2 * vz * y0;
        const float ms1 = t3 * (vx * yx + vy * yy + vz * yz) * I3;
        const float cx = vy * yz - vz * yy;
        const float cy = vz * yx - vx * yz;
        const float cz = vx * yy - vy * yx;
        const float C0x = t4 * cx * I2, C0y = t4 * cy * I2, C0z = t4 * cz * I2;

        as0 += wm[0] * ms0 * m0;
        { float w_ = wm[64] * ms0;  av[0][0] += w_ * mx; av[0][1] += w_ * my; av[0][2] += w_ * mz; }
        as1 += wm[128] * ms1 * m0;
        { float w_ = wm[192] * ms1; av[1][0] += w_ * mx; av[1][1] += w_ * my; av[1][2] += w_ * mz; }

        { float w_ = wm[256] * m0;  av[2][0] += w_ * A0x; av[2][1] += w_ * A0y; av[2][2] += w_ * A0z; }
        as2 += wm[320] * (A0x * mx + A0y * my + A0z * mz) * I3;
        { float w_ = wm[384] * I2;
          av[3][0] += w_ * (A0y * mz - A0z * my);
          av[3][1] += w_ * (A0z * mx - A0x * mz);
          av[3][2] += w_ * (A0x * my - A0y * mx); }

        { float w_ = wm[448] * m0;  av[4][0] += w_ * B0x; av[4][1] += w_ * B0y; av[4][2] += w_ * B0z; }
        as3 += wm[512] * (B0x * mx + B0y * my + B0z * mz) * I3;
        { float w_ = wm[576] * I2;
          av[5][0] += w_ * (B0y * mz - B0z * my);
          av[5][1] += w_ * (B0z * mx - B0x * mz);
          av[5][2] += w_ * (B0x * my - B0y * mx); }

        { float w_ = wm[640] * m0;  av[6][0] += w_ * C0x; av[6][1] += w_ * C0y; av[6][2] += w_ * C0z; }
        as4 += wm[704] * (C0x * mx + C0y * my + C0z * mz) * I3;
        { float w_ = wm[768] * I2;
          av[7][0] += w_ * (C0y * mz - C0z * my);
          av[7][1] += w_ * (C0z * mx - C0x * mz);
          av[7][2] += w_ * (C0x * my - C0y * mx); }

        dens += g_EDNS[q];

        ma_c = ma_n; xs_c = xs_n; vx_c = vx_n; vy_c = vy_n; vz_c = vz_n;
    }

    const size_t b = (size_t)n * 320 + u;
    g_MS[b]       = as0;
    g_MS[b + 64]  = as1;
    g_MS[b + 128] = as2;
    g_MS[b + 192] = as3;
    g_MS[b + 256] = as4;
    const size_t bv = (size_t)n * 1536 + u;
#pragma unroll
    for (int i = 0; i < 3; i++)
#pragma unroll
        for (int j = 0; j < 8; j++)
            g_MV[bv + i * 512 + j * 64] = av[j][i];
    if (u < 10) g_AI[n * 10 + u] = ATTR[n * 10 + u] / (dens + 1.f);
    if (u == 0) g_CUR[n] = 0;          // re-zero for next graph replay
}

// ---------------- launcher ----------------
extern "C" void kernel_launch(void* const* d_in, const int* in_sizes, int n_in,
                              void* d_out, int out_size)
{
    (void)in_sizes; (void)n_in; (void)out_size;
    const float* node_attrs = (const float*)d_in[0];
    const float* node_feats = (const float*)d_in[1];
    const float* edge_attrs = (const float*)d_in[2];
    const float* edge_feats = (const float*)d_in[3];
    const int*   edge_index = (const int*)  d_in[4];
    const float* maginv     = (const float*)d_in[5];
    const float* magattr    = (const float*)d_in[6];
    const float* Wups       = (const float*)d_in[7];
    const float* Wupv       = (const float*)d_in[8];
    const float* w0         = (const float*)d_in[9];
    const float* w1         = (const float*)d_in[10];
    const float* w2         = (const float*)d_in[11];
    const float* w3         = (const float*)d_in[12];
    const float* magw       = (const float*)d_in[13];
    const float* densw      = (const float*)d_in[14];
    const float* lins       = (const float*)d_in[15];
    const float* linv       = (const float*)d_in[16];
    const float* skips      = (const float*)d_in[17];
    const float* skipv      = (const float*)d_in[18];
    float* out = (float*)d_out;

    float *pS, *pV, *pMS, *pMV, *pMSP, *pMVP;
    cudaGetSymbolAddress((void**)&pS,   g_S);
    cudaGetSymbolAddress((void**)&pV,   g_V);
    cudaGetSymbolAddress((void**)&pMS,  g_MS);
    cudaGetSymbolAddress((void**)&pMV,  g_MV);
    cudaGetSymbolAddress((void**)&pMSP, g_MSP);
    cudaGetSymbolAddress((void**)&pMVP, g_MVP);

    cudaFuncSetAttribute(k_mlp, cudaFuncAttributeMaxDynamicSharedMemorySize, SM_MLP);

    const float a8   = 0.125f;
    const float a320 = 1.f / sqrtf(320.f);
    const float a512 = 1.f / sqrtf(512.f);
    const float a640 = 1.f / sqrtf(640.f);

    // sort first (hist/scan/scatter), then k_mlp at profile slot 3
    k_hist   <<<N_EDGES/256, 256>>>(edge_index, edge_feats, densw);      // 0
    k_scan   <<<1, 1024>>>();                                            // 1
    k_scatter<<<N_EDGES/256, 256>>>(edge_index, edge_attrs);             // 2

    k_mlp<<<N_EDGES/128, 128, SM_MLP>>>(edge_feats, maginv, edge_index,
                                        w0, w1, w2, w3, magw);           // 3 (profiled)

    // node up-projection
    gemmk<64,32,false><<<dim3(N_NODES/64, 1, 1), 128>>>(node_feats, 256, 1, 0, Wups, Wups, 64,
                                                        pS, 64, 1, 0, 64, a8, 0, 0, 0);
    gemmk<64,32,false><<<dim3(N_NODES/64, 1, 3), 128>>>(node_feats + 64, 256, 3, 1, Wupv, Wupv, 64,
                                                        pV, 192, 1, 64, 64, a8, 0, 0, 0);

    // per-node tensor-product combine + segment reduction
    k_mm<<<N_NODES, 64>>>(magattr, node_attrs);

    // lin_s / lin_v
    gemmk<64,32,false><<<dim3(N_NODES/64, 1, 1), 128>>>(pMS, 320, 1, 0, lins, lins, 64,
                                                        pMSP, 64, 1, 0, 320, a320, 0, 0, 0);
    gemmk<64,32,false><<<dim3(N_NODES/64, 1, 3), 128>>>(pMV, 1536, 1, 512, linv, linv, 64,
                                                        pMVP, 192, 1, 64, 512, a512, 0, 0, 0);

    // skip einsum
    gemmk<64,32,true><<<dim3(N_NODES/64, 1, 4), 128>>>(0, 0, 0, 0, skips, skipv, 64,
                                                       out, 256, 4, 1, 640, a640, 0, pMSP, pMVP);
}

// round 10
// speedup vs baseline: 1.1021x; 1.0343x over previous
#include <cuda_runtime.h>
#include <math.h>

#define N_NODES 8192
#define N_EDGES 65536

typedef unsigned long long ull;

// ---------------- scratch (static device globals; zero-initialized) ----------------
__device__ float g_S   [N_NODES*64];
__device__ float g_V   [N_NODES*192];
__device__ float g_EDN [N_EDGES];
__device__ float g_TP  [(size_t)N_EDGES*320];   // sorted-order
__device__ float g_WM  [(size_t)N_EDGES*832];   // sorted-order
__device__ float g_MS  [N_NODES*320];
__device__ float g_MV  [N_NODES*1536];
__device__ float g_AI  [N_NODES*10];
__device__ float g_MSP [N_NODES*64];
__device__ float g_MVP [N_NODES*192];
__device__ int   g_CNT [N_NODES];
__device__ int   g_CUR [N_NODES];
__device__ int   g_OFF [N_NODES+1];
__device__ int   g_SORT[N_EDGES];
__device__ int   g_SNDS[N_EDGES];
__device__ float4 g_EAS[N_EDGES];
__device__ float g_EDNS[N_EDGES];

__device__ __forceinline__ ull bcast(float f) {
    unsigned int u = __float_as_uint(f);
    ull r;
    asm("mov.b64 %0, {%1, %1};" : "=l"(r) : "r"(u));
    return r;
}
__device__ __forceinline__ ull pack2(float a, float b) {
    return ((ull)__float_as_uint(b) << 32) | __float_as_uint(a);
}
__device__ __forceinline__ void fma2(ull& acc, ull a, ull b) {
    asm("fma.rn.f32x2 %0, %1, %2, %0;" : "+l"(acc) : "l"(a), "l"(b));
}
__device__ __forceinline__ float lo2(ull v) { return __uint_as_float((unsigned int)v); }
__device__ __forceinline__ float hi2(ull v) { return __uint_as_float((unsigned int)(v >> 32)); }
__device__ __forceinline__ float silu(float v) { return v / (1.f + __expf(-v)); }

// ================= fused edge-path kernel (128 thr, double-buffered weights) ========
#define LDH 132
#define BSZE (64*68)
#define SM_MLP ((2*64*LDH + 2*BSZE) * 4)   // hA + hB + 2x Bs = 102 KB

__device__ __forceinline__ void stage_B(float* Bs, const float* __restrict__ src,
                                        int srcStride, int rows, int tid)
{
    for (int j = 0; j < rows / 8; j++) {
        int kk = (tid >> 4) + j * 8;
        int c  = (tid & 15) * 4;
        *(float4*)(Bs + kk * 68 + c) = *(const float4*)(src + (size_t)kk * srcStride + c);
    }
}

template<int K>
__device__ __forceinline__ void tile_mm(const float* hsrc, const float* Bs,
                                        ull* acc, int tx, int ty)
{
#pragma unroll
    for (int i = 0; i < 32; i++) acc[i] = 0ull;
#pragma unroll 4
    for (int kk = 0; kk < K; kk++) {
        const ulonglong2* ap = (const ulonglong2*)(hsrc + kk * LDH + ty * 8);
        ulonglong2 aA = ap[0];
        ulonglong2 aB = ap[1];
        const float4* bp = (const float4*)(Bs + kk * 68 + tx * 8);
        float4 b0 = bp[0], b1 = bp[1];
        ull bb[8];
        bb[0] = bcast(b0.x); bb[1] = bcast(b0.y);
        bb[2] = bcast(b0.z); bb[3] = bcast(b0.w);
        bb[4] = bcast(b1.x); bb[5] = bcast(b1.y);
        bb[6] = bcast(b1.z); bb[7] = bcast(b1.w);
#pragma unroll
        for (int c = 0; c < 8; c++) {
            fma2(acc[c],      aA.x, bb[c]);
            fma2(acc[8 + c],  aA.y, bb[c]);
            fma2(acc[16 + c], aB.x, bb[c]);
            fma2(acc[24 + c], aB.y, bb[c]);
        }
    }
}

__device__ __forceinline__ void write_gmem(float* dst, int rs, const ull* acc,
                                           float alpha, int tx, int ty)
{
#pragma unroll
    for (int rp = 0; rp < 4; rp++) {
        int r = ty * 8 + rp * 2;
        float* c0 = dst + (size_t)r * rs + tx * 8;
        float* c1 = c0 + rs;
        float4 l0, l1, h0, h1;
        l0.x = lo2(acc[rp*8+0]) * alpha; h0.x = hi2(acc[rp*8+0]) * alpha;
        l0.y = lo2(acc[rp*8+1]) * alpha; h0.y = hi2(acc[rp*8+1]) * alpha;
        l0.z = lo2(acc[rp*8+2]) * alpha; h0.z = hi2(acc[rp*8+2]) * alpha;
        l0.w = lo2(acc[rp*8+3]) * alpha; h0.w = hi2(acc[rp*8+3]) * alpha;
        l1.x = lo2(acc[rp*8+4]) * alpha; h1.x = hi2(acc[rp*8+4]) * alpha;
        l1.y = lo2(acc[rp*8+5]) * alpha; h1.y = hi2(acc[rp*8+5]) * alpha;
        l1.z = lo2(acc[rp*8+6]) * alpha; h1.z = hi2(acc[rp*8+6]) * alpha;
        l1.w = lo2(acc[rp*8+7]) * alpha; h1.w = hi2(acc[rp*8+7]) * alpha;
        *(float4*)(c0)     = l0;
        *(float4*)(c0 + 4) = l1;
        *(float4*)(c1)     = h0;
        *(float4*)(c1 + 4) = h1;
    }
}

__device__ __forceinline__ void write_h(float* hdst, const ull* acc,
                                        float alpha, int tx, int ty)
{
#pragma unroll
    for (int rp = 0; rp < 4; rp++) {
        int r = ty * 8 + rp * 2;
#pragma unroll
        for (int c = 0; c < 8; c++) {
            float v0 = silu(lo2(acc[rp*8+c]) * alpha);
            float v1 = silu(hi2(acc[rp*8+c]) * alpha);
            *(ull*)(hdst + (tx * 8 + c) * LDH + r) = pack2(v0, v1);
        }
    }
}

__global__ void __launch_bounds__(128) k_mlp(
    const float* __restrict__ EF, const float* __restrict__ MI,
    const int* __restrict__ EI,
    const float* __restrict__ w0, const float* __restrict__ w1,
    const float* __restrict__ w2, const float* __restrict__ w3,
    const float* __restrict__ magw)
{
    extern __shared__ float sm[];
    float* hA  = sm;
    float* hB  = sm + 64 * LDH;
    float* Bs0 = sm + 2 * 64 * LDH;
    float* Bs1 = Bs0 + BSZE;

    const int tid = threadIdx.x;
    const int tx = tid & 7, ty = tid >> 3;
    const size_t e0 = (size_t)blockIdx.x * 128;

    // stage efm for SORTED edge position e0+tid
    {
        int eid = g_SORT[e0 + tid];
        float4 a = *(const float4*)(EF + (size_t)eid * 8);
        float4 b = *(const float4*)(EF + (size_t)eid * 8 + 4);
        int snd = EI[eid];
        float4 c = *(const float4*)(MI + (size_t)snd * 8);
        float4 d = *(const float4*)(MI + (size_t)snd * 8 + 4);
        hA[ 0*LDH+tid]=a.x; hA[ 1*LDH+tid]=a.y; hA[ 2*LDH+tid]=a.z; hA[ 3*LDH+tid]=a.w;
        hA[ 4*LDH+tid]=b.x; hA[ 5*LDH+tid]=b.y; hA[ 6*LDH+tid]=b.z; hA[ 7*LDH+tid]=b.w;
        hA[ 8*LDH+tid]=c.x; hA[ 9*LDH+tid]=c.y; hA[10*LDH+tid]=c.z; hA[11*LDH+tid]=c.w;
        hA[12*LDH+tid]=d.x; hA[13*LDH+tid]=d.y; hA[14*LDH+tid]=d.z; hA[15*LDH+tid]=d.w;
    }
    stage_B(Bs0, w0, 64, 16, tid);        // tile 0 = w0
    __syncthreads();

    ull acc[32];
    float* cur = Bs0;
    float* nxt = Bs1;

    // ---- layer 0: hB = silu(efm @ w0 / 4); prefetch magw j=0 ----
    stage_B(nxt, magw, 832, 16, tid);
    tile_mm<16>(hA, cur, acc, tx, ty);
    write_h(hB, acc, 0.25f, tx, ty);
    __syncthreads();
    { float* t = cur; cur = nxt; nxt = t; }

    // ---- magw projection ×13 (prefetch next tile; after j=12 prefetch w1) ----
    for (int j = 0; j < 13; j++) {
        if (j < 12) stage_B(nxt, magw + (j + 1) * 64, 832, 16, tid);
        else        stage_B(nxt, w1, 64, 64, tid);
        tile_mm<16>(hA, cur, acc, tx, ty);
        write_gmem(g_WM + e0 * 832 + j * 64, 832, acc, 0.25f, tx, ty);
        __syncthreads();
        { float* t = cur; cur = nxt; nxt = t; }
    }

    // ---- layer 1: hA = silu(hB @ w1 / 8); prefetch w2 ----
    stage_B(nxt, w2, 64, 64, tid);
    tile_mm<64>(hB, cur, acc, tx, ty);
    write_h(hA, acc, 0.125f, tx, ty);
    __syncthreads();
    { float* t = cur; cur = nxt; nxt = t; }

    // ---- layer 2: hB = silu(hA @ w2 / 8); prefetch w3 j=0 ----
    stage_B(nxt, w3, 320, 64, tid);
    tile_mm<64>(hA, cur, acc, tx, ty);
    write_h(hB, acc, 0.125f, tx, ty);
    __syncthreads();
    { float* t = cur; cur = nxt; nxt = t; }

    // ---- TP projection ×5 ----
    for (int j = 0; j < 5; j++) {
        if (j < 4) stage_B(nxt, w3 + (j + 1) * 64, 320, 64, tid);
        tile_mm<64>(hB, cur, acc, tx, ty);
        write_gmem(g_TP + e0 * 320 + j * 64, 320, acc, 0.125f, tx, ty);
        __syncthreads();
        { float* t = cur; cur = nxt; nxt = t; }
    }
}

// ================= register-blocked GEMM, double-buffered tiles =================
template<int RB, int KT, bool SKIP>
__device__ __forceinline__ void g_stageA(float* dst, const float* __restrict__ Arow,
                                         int acs, const float* __restrict__ ai,
                                         int k0, int K, int arow, int kseg)
{
    const int LDA = RB + 4;
    const int KPT = (RB == 128) ? KT : KT / 2;
    if (SKIP) {
#pragma unroll 8
        for (int c = 0; c < KPT; c++) {
            int k = k0 + kseg + c;             // K=640 exact -> no guard
            int u = (k * 6554) >> 16;
            int v = k - u * 10;
            dst[(kseg + c) * LDA + arow] = Arow[u] * ai[v];
        }
    } else if (acs == 1) {
#pragma unroll
        for (int c = 0; c < KPT / 4; c++) {
            int kk = kseg + c * 4;
            float4 val = make_float4(0.f, 0.f, 0.f, 0.f);
            if (k0 + kk < K) val = *(const float4*)(Arow + k0 + kk);
            dst[(kk + 0) * LDA + arow] = val.x;
            dst[(kk + 1) * LDA + arow] = val.y;
            dst[(kk + 2) * LDA + arow] = val.z;
            dst[(kk + 3) * LDA + arow] = val.w;
        }
    } else {
#pragma unroll 8
        for (int c = 0; c < KPT; c++) {
            int kk = kseg + c;
            float v = 0.f;
            if (k0 + kk < K) v = Arow[(long)(k0 + kk) * acs];
            dst[kk * LDA + arow] = v;
        }
    }
}

template<int KT>
__device__ __forceinline__ void g_stageB(float* dst, const float* __restrict__ B,
                                         int brs, int col0, int k0, int K, int tid)
{
#pragma unroll
    for (int j = 0; j < KT / 8; j++) {
        int kk = (tid >> 4) + j * 8;
        int c  = (tid & 15) * 4;
        float4 val = make_float4(0.f, 0.f, 0.f, 0.f);
        if (k0 + kk < K)
            val = *(const float4*)(B + (size_t)(k0 + kk) * brs + col0 + c);
        *(float4*)(dst + kk * 68 + c) = val;
    }
}

template<int RB, int KT, bool SKIP>
__global__ void __launch_bounds__(128) gemmk(
    const float* __restrict__ A, long ars, int acs, long azs,
    const float* __restrict__ B0, const float* __restrict__ Bz, int brs,
    float* __restrict__ C, long crs, int ccs, long czs,
    int K, float alpha, int act,
    const float* __restrict__ MSP, const float* __restrict__ MVP)
{
    const int LDA = RB + 4;
    const int ASZ = KT * LDA;
    const int BSZ = KT * 68;
    const int RPT = RB / 16;
    const int PPT = RPT / 2;
    __shared__ float As[2 * KT * (RB + 4)];
    __shared__ float Bs[2 * KT * 68];

    const int tid = threadIdx.x;
    const int tx = tid & 7;
    const int ty = tid >> 3;
    const long row0 = (long)blockIdx.x * RB;
    const int  col0 = blockIdx.y * 64;
    const int  z = blockIdx.z;
    const float* __restrict__ B = (z == 0) ? B0 : Bz;
    C += (long)z * czs;

    const int arow = tid & (RB - 1);
    const int kseg = (RB == 128) ? 0 : ((tid >> 6) * (KT / 2));

    const float* Arow;
    const float* ai = 0;
    if (SKIP) {
        Arow = (z == 0) ? (MSP + (row0 + arow) * 64)
                        : (MVP + (row0 + arow) * 192 + (z - 1) * 64);
        ai = g_AI + (row0 + arow) * 10;
    } else {
        Arow = A + (long)z * azs + (row0 + arow) * ars;
    }

    ull acc[PPT * 8];
#pragma unroll
    for (int i = 0; i < PPT * 8; i++) acc[i] = 0ull;

    const int NT = (K + KT - 1) / KT;
    g_stageA<RB,KT,SKIP>(As, Arow, acs, ai, 0, K, arow, kseg);
    g_stageB<KT>(Bs, B, brs, col0, 0, K, tid);
    __syncthreads();

    for (int t = 0; t < NT; t++) {
        const float* Ab = As + (t & 1) * ASZ;
        const float* Bb = Bs + (t & 1) * BSZ;
        if (t + 1 < NT) {
            g_stageA<RB,KT,SKIP>(As + ((t + 1) & 1) * ASZ, Arow, acs, ai,
                                 (t + 1) * KT, K, arow, kseg);
            g_stageB<KT>(Bs + ((t + 1) & 1) * BSZ, B, brs, col0, (t + 1) * KT, K, tid);
        }
#pragma unroll 4
        for (int kk = 0; kk < KT; kk++) {
            ull ar[PPT];
            {
                const ulonglong2* ap = (const ulonglong2*)(Ab + kk * LDA + ty * RPT);
                ulonglong2 t0 = ap[0];
                ar[0] = t0.x; ar[1] = t0.y;
                if (RB == 128) {
                    ulonglong2 t1 = ap[1];
                    ar[2] = t1.x; ar[3] = t1.y;
                }
            }
            const float4* bp = (const float4*)(Bb + kk * 68 + tx * 8);
            float4 b0 = bp[0], b1 = bp[1];
            ull bb[8];
            bb[0] = bcast(b0.x); bb[1] = bcast(b0.y);
            bb[2] = bcast(b0.z); bb[3] = bcast(b0.w);
            bb[4] = bcast(b1.x); bb[5] = bcast(b1.y);
            bb[6] = bcast(b1.z); bb[7] = bcast(b1.w);
#pragma unroll
            for (int c = 0; c < 8; c++)
#pragma unroll
                for (int p = 0; p < PPT; p++)
                    fma2(acc[p * 8 + c], ar[p], bb[c]);
        }
        __syncthreads();
    }

#pragma unroll
    for (int rp = 0; rp < PPT; rp++) {
        long r = row0 + ty * RPT + rp * 2;
        float lo[8], hi[8];
#pragma unroll
        for (int c = 0; c < 8; c++) {
            ull av = acc[rp * 8 + c];
            float v0 = lo2(av) * alpha;
            float v1 = hi2(av) * alpha;
            if (act) { v0 = silu(v0); v1 = silu(v1); }
            lo[c] = v0; hi[c] = v1;
        }
        if (ccs == 1) {
            float* c0 = C + r * crs + col0 + tx * 8;
            float* c1 = c0 + crs;
            *(float4*)(c0)     = make_float4(lo[0], lo[1], lo[2], lo[3]);
            *(float4*)(c0 + 4) = make_float4(lo[4], lo[5], lo[6], lo[7]);
            *(float4*)(c1)     = make_float4(hi[0], hi[1], hi[2], hi[3]);
            *(float4*)(c1 + 4) = make_float4(hi[4], hi[5], hi[6], hi[7]);
        } else {
#pragma unroll
            for (int c = 0; c < 8; c++) {
                long col = (long)(col0 + tx * 8 + c) * ccs;
                C[r * crs + col] = lo[c];
                C[(r + 1) * crs + col] = hi[c];
            }
        }
    }
}

// ---------------- sort: hist(+density) -> scan(re-zero CNT) -> scatter(+sorted copies) ----
__global__ void k_hist(const int* __restrict__ EI, const float* __restrict__ EF,
                       const float* __restrict__ DW)
{
    int e = blockIdx.x * 256 + threadIdx.x;
    atomicAdd(&g_CNT[EI[N_EDGES + e]], 1);
    float d = 0.f;
#pragma unroll
    for (int i = 0; i < 8; i++) d += EF[e * 8 + i] * DW[i];
    d *= 0.3535533905932738f;
    g_EDN[e] = tanhf(d * d);
}
__global__ void k_scan()
{
    __shared__ int part[1024];
    int t = threadIdx.x;
    int loc[8]; int s = 0;
#pragma unroll
    for (int j = 0; j < 8; j++) { loc[j] = s; s += g_CNT[t * 8 + j]; }
    part[t] = s;
    __syncthreads();
    for (int off = 1; off < 1024; off <<= 1) {
        int v = (t >= off) ? part[t - off] : 0;
        __syncthreads();
        part[t] += v;
        __syncthreads();
    }
    int excl = part[t] - s;
#pragma unroll
    for (int j = 0; j < 8; j++) {
        g_OFF[t * 8 + j] = excl + loc[j];
        g_CNT[t * 8 + j] = 0;
    }
    if (t == 1023) g_OFF[N_NODES] = part[1023];
}
__global__ void k_scatter(const int* __restrict__ EI, const float* __restrict__ EA)
{
    int e = blockIdx.x * 256 + threadIdx.x;
    int r = EI[N_EDGES + e];
    int p = g_OFF[r] + atomicAdd(&g_CUR[r], 1);
    g_SORT[p] = e;
    g_SNDS[p] = EI[e];
    g_EAS[p]  = *(const float4*)(EA + (size_t)e * 4);
    g_EDNS[p] = g_EDN[e];
}

// ---------------- per-node combine (sequential payload, pipelined node gathers) ----
__global__ void __launch_bounds__(64) k_mm(const float* __restrict__ MA,
                                           const float* __restrict__ ATTR)
{
    const int n = blockIdx.x;
    const int u = threadIdx.x;
    const int beg = g_OFF[n], end = g_OFF[n + 1];

    float as0 = 0, as1 = 0, as2 = 0, as3 = 0, as4 = 0;
    float av[8][3];
#pragma unroll
    for (int j = 0; j < 8; j++)
#pragma unroll
        for (int i = 0; i < 3; i++) av[j][i] = 0.f;
    float dens = 0.f;

    const float I3 = 0.5773502691896258f;
    const float I2 = 0.7071067811865476f;

    float4 ma_c = make_float4(0,0,0,0);
    float xs_c = 0, vx_c = 0, vy_c = 0, vz_c = 0;
    if (beg < end) {
        int sc = g_SNDS[beg];
        ma_c = *(const float4*)(MA + (size_t)sc * 4);
        xs_c = g_S[(size_t)sc * 64 + u];
        const float* vp = g_V + (size_t)sc * 192 + u;
        vx_c = vp[0]; vy_c = vp[64]; vz_c = vp[128];
    }

    for (int q = beg; q < end; q++) {
        float4 ma_n = make_float4(0,0,0,0);
        float xs_n = 0, vx_n = 0, vy_n = 0, vz_n = 0;
        if (q + 1 < end) {
            int sn = g_SNDS[q + 1];
            ma_n = *(const float4*)(MA + (size_t)sn * 4);
            xs_n = g_S[(size_t)sn * 64 + u];
            const float* vp = g_V + (size_t)sn * 192 + u;
            vx_n = vp[0]; vy_n = vp[64]; vz_n = vp[128];
        }

        const float4 eav = g_EAS[q];
        const float y0 = eav.x, yx = eav.y, yy = eav.z, yz = eav.w;
        const float* tp = g_TP + (size_t)q * 320 + u;
        const float t0 = tp[0], t1 = tp[64], t2 = tp[128], t3 = tp[192], t4 = tp[256];
        const float* wm = g_WM + (size_t)q * 832 + u;

        const float m0 = ma_c.x, mx = ma_c.y, my = ma_c.z, mz = ma_c.w;
        const float xs = xs_c, vx = vx_c, vy = vy_c, vz = vz_c;

        const float ms0 = t0 * xs * y0;
        const float A0x = t1 * xs * yx, A0y = t1 * xs * yy, A0z = t1 * xs * yz;
        const float B0x = t2 * vx * y0, B0y = t2 * vy * y0, B0z = t2 * vz * y0;
        const float ms1 = t3 * (vx * yx + vy * yy + vz * yz) * I3;
        const float cx = vy * yz - vz * yy;
        const float cy = vz * yx - vx * yz;
        const float cz = vx * yy - vy * yx;
        const float C0x = t4 * cx * I2, C0y = t4 * cy * I2, C0z = t4 * cz * I2;

        as0 += wm[0] * ms0 * m0;
        { float w_ = wm[64] * ms0;  av[0][0] += w_ * mx; av[0][1] += w_ * my; av[0][2] += w_ * mz; }
        as1 += wm[128] * ms1 * m0;
        { float w_ = wm[192] * ms1; av[1][0] += w_ * mx; av[1][1] += w_ * my; av[1][2] += w_ * mz; }

        { float w_ = wm[256] * m0;  av[2][0] += w_ * A0x; av[2][1] += w_ * A0y; av[2][2] += w_ * A0z; }
        as2 += wm[320] * (A0x * mx + A0y * my + A0z * mz) * I3;
        { float w_ = wm[384] * I2;
          av[3][0] += w_ * (A0y * mz - A0z * my);
          av[3][1] += w_ * (A0z * mx - A0x * mz);
          av[3][2] += w_ * (A0x * my - A0y * mx); }

        { float w_ = wm[448] * m0;  av[4][0] += w_ * B0x; av[4][1] += w_ * B0y; av[4][2] += w_ * B0z; }
        as3 += wm[512] * (B0x * mx + B0y * my + B0z * mz) * I3;
        { float w_ = wm[576] * I2;
          av[5][0] += w_ * (B0y * mz - B0z * my);
          av[5][1] += w_ * (B0z * mx - B0x * mz);
          av[5][2] += w_ * (B0x * my - B0y * mx); }

        { float w_ = wm[640] * m0;  av[6][0] += w_ * C0x; av[6][1] += w_ * C0y; av[6][2] += w_ * C0z; }
        as4 += wm[704] * (C0x * mx + C0y * my + C0z * mz) * I3;
        { float w_ = wm[768] * I2;
          av[7][0] += w_ * (C0y * mz - C0z * my);
          av[7][1] += w_ * (C0z * mx - C0x * mz);
          av[7][2] += w_ * (C0x * my - C0y * mx); }

        dens += g_EDNS[q];

        ma_c = ma_n; xs_c = xs_n; vx_c = vx_n; vy_c = vy_n; vz_c = vz_n;
    }

    const size_t b = (size_t)n * 320 + u;
    g_MS[b]       = as0;
    g_MS[b + 64]  = as1;
    g_MS[b + 128] = as2;
    g_MS[b + 192] = as3;
    g_MS[b + 256] = as4;
    const size_t bv = (size_t)n * 1536 + u;
#pragma unroll
    for (int i = 0; i < 3; i++)
#pragma unroll
        for (int j = 0; j < 8; j++)
            g_MV[bv + i * 512 + j * 64] = av[j][i];
    if (u < 10) g_AI[n * 10 + u] = ATTR[n * 10 + u] / (dens + 1.f);
    if (u == 0) g_CUR[n] = 0;
}

// ---------------- launcher ----------------
extern "C" void kernel_launch(void* const* d_in, const int* in_sizes, int n_in,
                              void* d_out, int out_size)
{
    (void)in_sizes; (void)n_in; (void)out_size;
    const float* node_attrs = (const float*)d_in[0];
    const float* node_feats = (const float*)d_in[1];
    const float* edge_attrs = (const float*)d_in[2];
    const float* edge_feats = (const float*)d_in[3];
    const int*   edge_index = (const int*)  d_in[4];
    const float* maginv     = (const float*)d_in[5];
    const float* magattr    = (const float*)d_in[6];
    const float* Wups       = (const float*)d_in[7];
    const float* Wupv       = (const float*)d_in[8];
    const float* w0         = (const float*)d_in[9];
    const float* w1         = (const float*)d_in[10];
    const float* w2         = (const float*)d_in[11];
    const float* w3         = (const float*)d_in[12];
    const float* magw       = (const float*)d_in[13];
    const float* densw      = (const float*)d_in[14];
    const float* lins       = (const float*)d_in[15];
    const float* linv       = (const float*)d_in[16];
    const float* skips      = (const float*)d_in[17];
    const float* skipv      = (const float*)d_in[18];
    float* out = (float*)d_out;

    float *pS, *pV, *pMS, *pMV, *pMSP, *pMVP;
    cudaGetSymbolAddress((void**)&pS,   g_S);
    cudaGetSymbolAddress((void**)&pV,   g_V);
    cudaGetSymbolAddress((void**)&pMS,  g_MS);
    cudaGetSymbolAddress((void**)&pMV,  g_MV);
    cudaGetSymbolAddress((void**)&pMSP, g_MSP);
    cudaGetSymbolAddress((void**)&pMVP, g_MVP);

    cudaFuncSetAttribute(k_mlp, cudaFuncAttributeMaxDynamicSharedMemorySize, SM_MLP);

    const float a8   = 0.125f;
    const float a320 = 1.f / sqrtf(320.f);
    const float a512 = 1.f / sqrtf(512.f);
    const float a640 = 1.f / sqrtf(640.f);

    k_hist   <<<N_EDGES/256, 256>>>(edge_index, edge_feats, densw);      // 0
    k_scan   <<<1, 1024>>>();                                            // 1
    k_scatter<<<N_EDGES/256, 256>>>(edge_index, edge_attrs);             // 2

    k_mlp<<<N_EDGES/128, 128, SM_MLP>>>(edge_feats, maginv, edge_index,
                                        w0, w1, w2, w3, magw);           // 3 (profiled)

    // node up-projection
    gemmk<64,32,false><<<dim3(N_NODES/64, 1, 1), 128>>>(node_feats, 256, 1, 0, Wups, Wups, 64,
                                                        pS, 64, 1, 0, 64, a8, 0, 0, 0);
    gemmk<64,32,false><<<dim3(N_NODES/64, 1, 3), 128>>>(node_feats + 64, 256, 3, 1, Wupv, Wupv, 64,
                                                        pV, 192, 1, 64, 64, a8, 0, 0, 0);

    // per-node tensor-product combine + segment reduction
    k_mm<<<N_NODES, 64>>>(magattr, node_attrs);

    // lin_s / lin_v
    gemmk<64,32,false><<<dim3(N_NODES/64, 1, 1), 128>>>(pMS, 320, 1, 0, lins, lins, 64,
                                                        pMSP, 64, 1, 0, 320, a320, 0, 0, 0);
    gemmk<64,32,false><<<dim3(N_NODES/64, 1, 3), 128>>>(pMV, 1536, 1, 512, linv, linv, 64,
                                                        pMVP, 192, 1, 64, 512, a512, 0, 0, 0);

    // skip einsum
    gemmk<64,32,true><<<dim3(N_NODES/64, 1, 4), 128>>>(0, 0, 0, 0, skips, skipv, 64,
                                                       out, 256, 4, 1, 640, a640, 0, pMSP, pMVP);
}

// round 11
// speedup vs baseline: 1.1866x; 1.0766x over previous
#include <cuda_runtime.h>
#include <math.h>

#define N_NODES 8192
#define N_EDGES 65536

typedef unsigned long long ull;

// ---------------- scratch (static device globals; zero-initialized) ----------------
__device__ float g_S   [N_NODES*64];
__device__ float g_V   [N_NODES*192];
__device__ float g_EDN [N_EDGES];
__device__ float g_TP  [(size_t)N_EDGES*320];   // edge-order
__device__ float g_WM  [(size_t)N_EDGES*832];   // edge-order
__device__ float g_MS  [N_NODES*320];
__device__ float g_MV  [N_NODES*1536];
__device__ float g_AI  [N_NODES*10];
__device__ float g_MSP [N_NODES*64];
__device__ float g_MVP [N_NODES*192];
__device__ int   g_CNT [N_NODES];
__device__ int   g_CUR [N_NODES];
__device__ int   g_OFF [N_NODES+1];
__device__ int   g_SORT[N_EDGES];
__device__ int   g_SNDS[N_EDGES];               // sender id, sorted order
__device__ float4 g_EAS[N_EDGES];               // edge_attrs, sorted order
__device__ float g_EDNS[N_EDGES];               // density, sorted order

__device__ __forceinline__ ull bcast(float f) {
    unsigned int u = __float_as_uint(f);
    ull r;
    asm("mov.b64 %0, {%1, %1};" : "=l"(r) : "r"(u));
    return r;
}
__device__ __forceinline__ ull pack2(float a, float b) {
    return ((ull)__float_as_uint(b) << 32) | __float_as_uint(a);
}
__device__ __forceinline__ void fma2(ull& acc, ull a, ull b) {
    asm("fma.rn.f32x2 %0, %1, %2, %0;" : "+l"(acc) : "l"(a), "l"(b));
}
__device__ __forceinline__ float lo2(ull v) { return __uint_as_float((unsigned int)v); }
__device__ __forceinline__ float hi2(ull v) { return __uint_as_float((unsigned int)(v >> 32)); }
__device__ __forceinline__ float silu(float v) { return v / (1.f + __expf(-v)); }

// ================= mega kernel: edge path (+hist +density) and node up-proj ========
#define LDH 132
#define BSZE (64*68)
#define SM_MLP ((2*64*LDH + 2*BSZE) * 4)   // hA + hB + 2x Bs = 102 KB
#define EDGE_BLOCKS (N_EDGES/128)          // 512
#define UP_BLOCKS   256                    // 4 z * 64 row-tiles of 128

__device__ __forceinline__ void stage_B(float* Bs, const float* __restrict__ src,
                                        int srcStride, int rows, int tid)
{
    for (int j = 0; j < rows / 8; j++) {
        int kk = (tid >> 4) + j * 8;
        int c  = (tid & 15) * 4;
        *(float4*)(Bs + kk * 68 + c) = *(const float4*)(src + (size_t)kk * srcStride + c);
    }
}

template<int K>
__device__ __forceinline__ void tile_mm(const float* hsrc, const float* Bs,
                                        ull* acc, int tx, int ty)
{
#pragma unroll
    for (int i = 0; i < 32; i++) acc[i] = 0ull;
#pragma unroll 4
    for (int kk = 0; kk < K; kk++) {
        const ulonglong2* ap = (const ulonglong2*)(hsrc + kk * LDH + ty * 8);
        ulonglong2 aA = ap[0];
        ulonglong2 aB = ap[1];
        const float4* bp = (const float4*)(Bs + kk * 68 + tx * 8);
        float4 b0 = bp[0], b1 = bp[1];
        ull bb[8];
        bb[0] = bcast(b0.x); bb[1] = bcast(b0.y);
        bb[2] = bcast(b0.z); bb[3] = bcast(b0.w);
        bb[4] = bcast(b1.x); bb[5] = bcast(b1.y);
        bb[6] = bcast(b1.z); bb[7] = bcast(b1.w);
#pragma unroll
        for (int c = 0; c < 8; c++) {
            fma2(acc[c],      aA.x, bb[c]);
            fma2(acc[8 + c],  aA.y, bb[c]);
            fma2(acc[16 + c], aB.x, bb[c]);
            fma2(acc[24 + c], aB.y, bb[c]);
        }
    }
}

__device__ __forceinline__ void write_gmem(float* dst, int rs, const ull* acc,
                                           float alpha, int tx, int ty)
{
#pragma unroll
    for (int rp = 0; rp < 4; rp++) {
        int r = ty * 8 + rp * 2;
        float* c0 = dst + (size_t)r * rs + tx * 8;
        float* c1 = c0 + rs;
        float4 l0, l1, h0, h1;
        l0.x = lo2(acc[rp*8+0]) * alpha; h0.x = hi2(acc[rp*8+0]) * alpha;
        l0.y = lo2(acc[rp*8+1]) * alpha; h0.y = hi2(acc[rp*8+1]) * alpha;
        l0.z = lo2(acc[rp*8+2]) * alpha; h0.z = hi2(acc[rp*8+2]) * alpha;
        l0.w = lo2(acc[rp*8+3]) * alpha; h0.w = hi2(acc[rp*8+3]) * alpha;
        l1.x = lo2(acc[rp*8+4]) * alpha; h1.x = hi2(acc[rp*8+4]) * alpha;
        l1.y = lo2(acc[rp*8+5]) * alpha; h1.y = hi2(acc[rp*8+5]) * alpha;
        l1.z = lo2(acc[rp*8+6]) * alpha; h1.z = hi2(acc[rp*8+6]) * alpha;
        l1.w = lo2(acc[rp*8+7]) * alpha; h1.w = hi2(acc[rp*8+7]) * alpha;
        *(float4*)(c0)     = l0;
        *(float4*)(c0 + 4) = l1;
        *(float4*)(c1)     = h0;
        *(float4*)(c1 + 4) = h1;
    }
}

__device__ __forceinline__ void write_h(float* hdst, const ull* acc,
                                        float alpha, int tx, int ty)
{
#pragma unroll
    for (int rp = 0; rp < 4; rp++) {
        int r = ty * 8 + rp * 2;
#pragma unroll
        for (int c = 0; c < 8; c++) {
            float v0 = silu(lo2(acc[rp*8+c]) * alpha);
            float v1 = silu(hi2(acc[rp*8+c]) * alpha);
            *(ull*)(hdst + (tx * 8 + c) * LDH + r) = pack2(v0, v1);
        }
    }
}

__global__ void __launch_bounds__(128) k_mega(
    const float* __restrict__ EF, const float* __restrict__ MI,
    const int* __restrict__ EI,
    const float* __restrict__ w0, const float* __restrict__ w1,
    const float* __restrict__ w2, const float* __restrict__ w3,
    const float* __restrict__ magw, const float* __restrict__ DW,
    const float* __restrict__ feats,
    const float* __restrict__ Wups, const float* __restrict__ Wupv)
{
    extern __shared__ float sm[];
    float* hA  = sm;
    float* hB  = sm + 64 * LDH;
    float* Bs0 = sm + 2 * 64 * LDH;
    float* Bs1 = Bs0 + BSZE;

    const int tid = threadIdx.x;
    const int tx = tid & 7, ty = tid >> 3;

    if (blockIdx.x >= EDGE_BLOCKS) {
        // =============== node up-projection block ===============
        int ub = blockIdx.x - EDGE_BLOCKS;      // 0..255
        int z  = ub >> 6;                       // 0 = scalar, 1..3 = vector comps
        long row0 = (long)(ub & 63) * 128;

        if (z == 0) {
            const float* Ar = feats + (row0 + tid) * 256;
#pragma unroll
            for (int k4 = 0; k4 < 16; k4++) {
                float4 v = *(const float4*)(Ar + k4 * 4);
                hA[(k4*4 + 0) * LDH + tid] = v.x;
                hA[(k4*4 + 1) * LDH + tid] = v.y;
                hA[(k4*4 + 2) * LDH + tid] = v.z;
                hA[(k4*4 + 3) * LDH + tid] = v.w;
            }
        } else {
            const float* Ar = feats + (row0 + tid) * 256 + 64 + (z - 1);
#pragma unroll 8
            for (int k = 0; k < 64; k++)
                hA[k * LDH + tid] = Ar[k * 3];
        }
        stage_B(Bs0, (z == 0) ? Wups : Wupv, 64, 64, tid);
        __syncthreads();

        ull acc[32];
        tile_mm<64>(hA, Bs0, acc, tx, ty);
        if (z == 0)
            write_gmem(g_S + row0 * 64, 64, acc, 0.125f, tx, ty);
        else
            write_gmem(g_V + row0 * 192 + (z - 1) * 64, 192, acc, 0.125f, tx, ty);
        return;
    }

    // =============== edge-path block ===============
    const size_t e0 = (size_t)blockIdx.x * 128;

    // stage efm (edge order) + receiver hist + density
    {
        size_t e = e0 + tid;
        float4 a = *(const float4*)(EF + e * 8);
        float4 b = *(const float4*)(EF + e * 8 + 4);
        int snd = EI[e];
        int rcv = EI[N_EDGES + e];
        atomicAdd(&g_CNT[rcv], 1);
        float4 c = *(const float4*)(MI + (size_t)snd * 8);
        float4 d = *(const float4*)(MI + (size_t)snd * 8 + 4);
        hA[ 0*LDH+tid]=a.x; hA[ 1*LDH+tid]=a.y; hA[ 2*LDH+tid]=a.z; hA[ 3*LDH+tid]=a.w;
        hA[ 4*LDH+tid]=b.x; hA[ 5*LDH+tid]=b.y; hA[ 6*LDH+tid]=b.z; hA[ 7*LDH+tid]=b.w;
        hA[ 8*LDH+tid]=c.x; hA[ 9*LDH+tid]=c.y; hA[10*LDH+tid]=c.z; hA[11*LDH+tid]=c.w;
        hA[12*LDH+tid]=d.x; hA[13*LDH+tid]=d.y; hA[14*LDH+tid]=d.z; hA[15*LDH+tid]=d.w;
        float dd = a.x*DW[0] + a.y*DW[1] + a.z*DW[2] + a.w*DW[3]
                 + b.x*DW[4] + b.y*DW[5] + b.z*DW[6] + b.w*DW[7];
        dd *= 0.3535533905932738f;
        g_EDN[e] = tanhf(dd * dd);
    }
    stage_B(Bs0, w0, 64, 16, tid);
    __syncthreads();

    ull acc[32];
    float* cur = Bs0;
    float* nxt = Bs1;

    // layer 0
    stage_B(nxt, magw, 832, 16, tid);
    tile_mm<16>(hA, cur, acc, tx, ty);
    write_h(hB, acc, 0.25f, tx, ty);
    __syncthreads();
    { float* t = cur; cur = nxt; nxt = t; }

    // magw x13
    for (int j = 0; j < 13; j++) {
        if (j < 12) stage_B(nxt, magw + (j + 1) * 64, 832, 16, tid);
        else        stage_B(nxt, w1, 64, 64, tid);
        tile_mm<16>(hA, cur, acc, tx, ty);
        write_gmem(g_WM + e0 * 832 + j * 64, 832, acc, 0.25f, tx, ty);
        __syncthreads();
        { float* t = cur; cur = nxt; nxt = t; }
    }

    // layer 1
    stage_B(nxt, w2, 64, 64, tid);
    tile_mm<64>(hB, cur, acc, tx, ty);
    write_h(hA, acc, 0.125f, tx, ty);
    __syncthreads();
    { float* t = cur; cur = nxt; nxt = t; }

    // layer 2
    stage_B(nxt, w3, 320, 64, tid);
    tile_mm<64>(hA, cur, acc, tx, ty);
    write_h(hB, acc, 0.125f, tx, ty);
    __syncthreads();
    { float* t = cur; cur = nxt; nxt = t; }

    // TP x5
    for (int j = 0; j < 5; j++) {
        if (j < 4) stage_B(nxt, w3 + (j + 1) * 64, 320, 64, tid);
        tile_mm<64>(hB, cur, acc, tx, ty);
        write_gmem(g_TP + e0 * 320 + j * 64, 320, acc, 0.125f, tx, ty);
        __syncthreads();
        { float* t = cur; cur = nxt; nxt = t; }
    }
}

// ================= register-blocked GEMM, double-buffered tiles =================
template<int RB, int KT, bool SKIP>
__device__ __forceinline__ void g_stageA(float* dst, const float* __restrict__ Arow,
                                         int acs, const float* __restrict__ ai,
                                         int k0, int K, int arow, int kseg)
{
    const int LDA = RB + 4;
    const int KPT = (RB == 128) ? KT : KT / 2;
    if (SKIP) {
#pragma unroll 8
        for (int c = 0; c < KPT; c++) {
            int k = k0 + kseg + c;
            int u = (k * 6554) >> 16;
            int v = k - u * 10;
            dst[(kseg + c) * LDA + arow] = Arow[u] * ai[v];
        }
    } else if (acs == 1) {
#pragma unroll
        for (int c = 0; c < KPT / 4; c++) {
            int kk = kseg + c * 4;
            float4 val = make_float4(0.f, 0.f, 0.f, 0.f);
            if (k0 + kk < K) val = *(const float4*)(Arow + k0 + kk);
            dst[(kk + 0) * LDA + arow] = val.x;
            dst[(kk + 1) * LDA + arow] = val.y;
            dst[(kk + 2) * LDA + arow] = val.z;
            dst[(kk + 3) * LDA + arow] = val.w;
        }
    } else {
#pragma unroll 8
        for (int c = 0; c < KPT; c++) {
            int kk = kseg + c;
            float v = 0.f;
            if (k0 + kk < K) v = Arow[(long)(k0 + kk) * acs];
            dst[kk * LDA + arow] = v;
        }
    }
}

template<int KT>
__device__ __forceinline__ void g_stageB(float* dst, const float* __restrict__ B,
                                         int brs, int col0, int k0, int K, int tid)
{
#pragma unroll
    for (int j = 0; j < KT / 8; j++) {
        int kk = (tid >> 4) + j * 8;
        int c  = (tid & 15) * 4;
        float4 val = make_float4(0.f, 0.f, 0.f, 0.f);
        if (k0 + kk < K)
            val = *(const float4*)(B + (size_t)(k0 + kk) * brs + col0 + c);
        *(float4*)(dst + kk * 68 + c) = val;
    }
}

template<int RB, int KT, bool SKIP>
__global__ void __launch_bounds__(128) gemmk(
    const float* __restrict__ A, long ars, int acs, long azs,
    const float* __restrict__ B0, const float* __restrict__ Bz, int brs,
    float* __restrict__ C, long crs, int ccs, long czs,
    int K, float alpha, int act,
    const float* __restrict__ MSP, const float* __restrict__ MVP)
{
    const int LDA = RB + 4;
    const int ASZ = KT * LDA;
    const int BSZ = KT * 68;
    const int RPT = RB / 16;
    const int PPT = RPT / 2;
    __shared__ float As[2 * KT * (RB + 4)];
    __shared__ float Bs[2 * KT * 68];

    const int tid = threadIdx.x;
    const int tx = tid & 7;
    const int ty = tid >> 3;
    const long row0 = (long)blockIdx.x * RB;
    const int  col0 = blockIdx.y * 64;
    const int  z = blockIdx.z;
    const float* __restrict__ B = (z == 0) ? B0 : Bz;
    C += (long)z * czs;

    const int arow = tid & (RB - 1);
    const int kseg = (RB == 128) ? 0 : ((tid >> 6) * (KT / 2));

    const float* Arow;
    const float* ai = 0;
    if (SKIP) {
        Arow = (z == 0) ? (MSP + (row0 + arow) * 64)
                        : (MVP + (row0 + arow) * 192 + (z - 1) * 64);
        ai = g_AI + (row0 + arow) * 10;
    } else {
        Arow = A + (long)z * azs + (row0 + arow) * ars;
    }

    ull acc[PPT * 8];
#pragma unroll
    for (int i = 0; i < PPT * 8; i++) acc[i] = 0ull;

    const int NT = (K + KT - 1) / KT;
    g_stageA<RB,KT,SKIP>(As, Arow, acs, ai, 0, K, arow, kseg);
    g_stageB<KT>(Bs, B, brs, col0, 0, K, tid);
    __syncthreads();

    for (int t = 0; t < NT; t++) {
        const float* Ab = As + (t & 1) * ASZ;
        const float* Bb = Bs + (t & 1) * BSZ;
        if (t + 1 < NT) {
            g_stageA<RB,KT,SKIP>(As + ((t + 1) & 1) * ASZ, Arow, acs, ai,
                                 (t + 1) * KT, K, arow, kseg);
            g_stageB<KT>(Bs + ((t + 1) & 1) * BSZ, B, brs, col0, (t + 1) * KT, K, tid);
        }
#pragma unroll 4
        for (int kk = 0; kk < KT; kk++) {
            ull ar[PPT];
            {
                const ulonglong2* ap = (const ulonglong2*)(Ab + kk * LDA + ty * RPT);
                ulonglong2 t0 = ap[0];
                ar[0] = t0.x; ar[1] = t0.y;
                if (RB == 128) {
                    ulonglong2 t1 = ap[1];
                    ar[2] = t1.x; ar[3] = t1.y;
                }
            }
            const float4* bp = (const float4*)(Bb + kk * 68 + tx * 8);
            float4 b0 = bp[0], b1 = bp[1];
            ull bb[8];
            bb[0] = bcast(b0.x); bb[1] = bcast(b0.y);
            bb[2] = bcast(b0.z); bb[3] = bcast(b0.w);
            bb[4] = bcast(b1.x); bb[5] = bcast(b1.y);
            bb[6] = bcast(b1.z); bb[7] = bcast(b1.w);
#pragma unroll
            for (int c = 0; c < 8; c++)
#pragma unroll
                for (int p = 0; p < PPT; p++)
                    fma2(acc[p * 8 + c], ar[p], bb[c]);
        }
        __syncthreads();
    }

#pragma unroll
    for (int rp = 0; rp < PPT; rp++) {
        long r = row0 + ty * RPT + rp * 2;
        float lo[8], hi[8];
#pragma unroll
        for (int c = 0; c < 8; c++) {
            ull av = acc[rp * 8 + c];
            float v0 = lo2(av) * alpha;
            float v1 = hi2(av) * alpha;
            if (act) { v0 = silu(v0); v1 = silu(v1); }
            lo[c] = v0; hi[c] = v1;
        }
        if (ccs == 1) {
            float* c0 = C + r * crs + col0 + tx * 8;
            float* c1 = c0 + crs;
            *(float4*)(c0)     = make_float4(lo[0], lo[1], lo[2], lo[3]);
            *(float4*)(c0 + 4) = make_float4(lo[4], lo[5], lo[6], lo[7]);
            *(float4*)(c1)     = make_float4(hi[0], hi[1], hi[2], hi[3]);
            *(float4*)(c1 + 4) = make_float4(hi[4], hi[5], hi[6], hi[7]);
        } else {
#pragma unroll
            for (int c = 0; c < 8; c++) {
                long col = (long)(col0 + tx * 8 + c) * ccs;
                C[r * crs + col] = lo[c];
                C[(r + 1) * crs + col] = hi[c];
            }
        }
    }
}

// ---------------- scan (re-zero CNT) + scatter (sorted copies) ----------------
__global__ void k_scan()
{
    __shared__ int part[1024];
    int t = threadIdx.x;
    int loc[8]; int s = 0;
#pragma unroll
    for (int j = 0; j < 8; j++) { loc[j] = s; s += g_CNT[t * 8 + j]; }
    part[t] = s;
    __syncthreads();
    for (int off = 1; off < 1024; off <<= 1) {
        int v = (t >= off) ? part[t - off] : 0;
        __syncthreads();
        part[t] += v;
        __syncthreads();
    }
    int excl = part[t] - s;
#pragma unroll
    for (int j = 0; j < 8; j++) {
        g_OFF[t * 8 + j] = excl + loc[j];
        g_CNT[t * 8 + j] = 0;
    }
    if (t == 1023) g_OFF[N_NODES] = part[1023];
}
__global__ void k_scatter(const int* __restrict__ EI, const float* __restrict__ EA)
{
    int e = blockIdx.x * 256 + threadIdx.x;
    int r = EI[N_EDGES + e];
    int p = g_OFF[r] + atomicAdd(&g_CUR[r], 1);
    g_SORT[p] = e;
    g_SNDS[p] = EI[e];
    g_EAS[p]  = *(const float4*)(EA + (size_t)e * 4);
    g_EDNS[p] = g_EDN[e];
}

// ---------------- per-node combine (deep pipeline, g_SORT-indexed payload) ----------
__global__ void __launch_bounds__(64) k_mm(const float* __restrict__ MA,
                                           const float* __restrict__ ATTR)
{
    const int n = blockIdx.x;
    const int u = threadIdx.x;
    const int beg = g_OFF[n], end = g_OFF[n + 1];

    float as0 = 0, as1 = 0, as2 = 0, as3 = 0, as4 = 0;
    float av[8][3];
#pragma unroll
    for (int j = 0; j < 8; j++)
#pragma unroll
        for (int i = 0; i < 3; i++) av[j][i] = 0.f;
    float dens = 0.f;

    const float I3 = 0.5773502691896258f;
    const float I2 = 0.7071067811865476f;

    // pipeline: edge id known 2 ahead, payload 1 ahead
    int e_n = 0;
    float4 ea_c = make_float4(0,0,0,0), ma_c = make_float4(0,0,0,0);
    float xs_c = 0, vx_c = 0, vy_c = 0, vz_c = 0, ed_c = 0;
    float t_c[5], w_c[13];
#pragma unroll
    for (int i = 0; i < 5; i++) t_c[i] = 0.f;
#pragma unroll
    for (int i = 0; i < 13; i++) w_c[i] = 0.f;

    if (beg < end) {
        int ec = g_SORT[beg];
        if (beg + 1 < end) e_n = g_SORT[beg + 1];
        int sc = g_SNDS[beg];
        ea_c = g_EAS[beg];
        ed_c = g_EDNS[beg];
        ma_c = *(const float4*)(MA + (size_t)sc * 4);
        xs_c = g_S[(size_t)sc * 64 + u];
        const float* vp = g_V + (size_t)sc * 192 + u;
        vx_c = vp[0]; vy_c = vp[64]; vz_c = vp[128];
        const float* tp = g_TP + (size_t)ec * 320 + u;
#pragma unroll
        for (int i = 0; i < 5; i++) t_c[i] = tp[i * 64];
        const float* wm = g_WM + (size_t)ec * 832 + u;
#pragma unroll
        for (int i = 0; i < 13; i++) w_c[i] = wm[i * 64];
    }

    for (int q = beg; q < end; q++) {
        // ---- prefetch q+1 payload (e_n known), fetch e for q+2 ----
        float4 ea_nn = make_float4(0,0,0,0), ma_nn = make_float4(0,0,0,0);
        float xs_nn = 0, vx_nn = 0, vy_nn = 0, vz_nn = 0, ed_nn = 0;
        float t_nn[5], w_nn[13];
#pragma unroll
        for (int i = 0; i < 5; i++) t_nn[i] = 0.f;
#pragma unroll
        for (int i = 0; i < 13; i++) w_nn[i] = 0.f;
        int e_2 = 0;
        if (q + 1 < end) {
            if (q + 2 < end) e_2 = g_SORT[q + 2];
            int sn = g_SNDS[q + 1];
            ea_nn = g_EAS[q + 1];
            ed_nn = g_EDNS[q + 1];
            ma_nn = *(const float4*)(MA + (size_t)sn * 4);
            xs_nn = g_S[(size_t)sn * 64 + u];
            const float* vp = g_V + (size_t)sn * 192 + u;
            vx_nn = vp[0]; vy_nn = vp[64]; vz_nn = vp[128];
            const float* tp = g_TP + (size_t)e_n * 320 + u;
#pragma unroll
            for (int i = 0; i < 5; i++) t_nn[i] = tp[i * 64];
            const float* wm = g_WM + (size_t)e_n * 832 + u;
#pragma unroll
            for (int i = 0; i < 13; i++) w_nn[i] = wm[i * 64];
        }

        // ---- compute with current payload ----
        const float y0 = ea_c.x, yx = ea_c.y, yy = ea_c.z, yz = ea_c.w;
        const float m0 = ma_c.x, mx = ma_c.y, my = ma_c.z, mz = ma_c.w;
        const float xs = xs_c, vx = vx_c, vy = vy_c, vz = vz_c;

        const float ms0 = t_c[0] * xs * y0;
        const float A0x = t_c[1] * xs * yx, A0y = t_c[1] * xs * yy, A0z = t_c[1] * xs * yz;
        const float B0x = t_c[2] * vx * y0, B0y = t_c[2] * vy * y0, B0z = t_c[2] * vz * y0;
        const float ms1 = t_c[3] * (vx * yx + vy * yy + vz * yz) * I3;
        const float cx = vy * yz - vz * yy;
        const float cy = vz * yx - vx * yz;
        const float cz = vx * yy - vy * yx;
        const float C0x = t_c[4] * cx * I2, C0y = t_c[4] * cy * I2, C0z = t_c[4] * cz * I2;

        as0 += w_c[0] * ms0 * m0;
        { float w_ = w_c[1] * ms0;  av[0][0] += w_ * mx; av[0][1] += w_ * my; av[0][2] += w_ * mz; }
        as1 += w_c[2] * ms1 * m0;
        { float w_ = w_c[3] * ms1;  av[1][0] += w_ * mx; av[1][1] += w_ * my; av[1][2] += w_ * mz; }

        { float w_ = w_c[4] * m0;   av[2][0] += w_ * A0x; av[2][1] += w_ * A0y; av[2][2] += w_ * A0z; }
        as2 += w_c[5] * (A0x * mx + A0y * my + A0z * mz) * I3;
        { float w_ = w_c[6] * I2;
          av[3][0] += w_ * (A0y * mz - A0z * my);
          av[3][1] += w_ * (A0z * mx - A0x * mz);
          av[3][2] += w_ * (A0x * my - A0y * mx); }

        { float w_ = w_c[7] * m0;   av[4][0] += w_ * B0x; av[4][1] += w_ * B0y; av[4][2] += w_ * B0z; }
        as3 += w_c[8] * (B0x * mx + B0y * my + B0z * mz) * I3;
        { float w_ = w_c[9] * I2;
          av[5][0] += w_ * (B0y * mz - B0z * my);
          av[5][1] += w_ * (B0z * mx - B0x * mz);
          av[5][2] += w_ * (B0x * my - B0y * mx); }

        { float w_ = w_c[10] * m0;  av[6][0] += w_ * C0x; av[6][1] += w_ * C0y; av[6][2] += w_ * C0z; }
        as4 += w_c[11] * (C0x * mx + C0y * my + C0z * mz) * I3;
        { float w_ = w_c[12] * I2;
          av[7][0] += w_ * (C0y * mz - C0z * my);
          av[7][1] += w_ * (C0z * mx - C0x * mz);
          av[7][2] += w_ * (C0x * my - C0y * mx); }

        dens += ed_c;

        // ---- rotate pipeline ----
        ea_c = ea_nn; ma_c = ma_nn;
        xs_c = xs_nn; vx_c = vx_nn; vy_c = vy_nn; vz_c = vz_nn; ed_c = ed_nn;
#pragma unroll
        for (int i = 0; i < 5; i++) t_c[i] = t_nn[i];
#pragma unroll
        for (int i = 0; i < 13; i++) w_c[i] = w_nn[i];
        e_n = e_2;
    }

    const size_t b = (size_t)n * 320 + u;
    g_MS[b]       = as0;
    g_MS[b + 64]  = as1;
    g_MS[b + 128] = as2;
    g_MS[b + 192] = as3;
    g_MS[b + 256] = as4;
    const size_t bv = (size_t)n * 1536 + u;
#pragma unroll
    for (int i = 0; i < 3; i++)
#pragma unroll
        for (int j = 0; j < 8; j++)
            g_MV[bv + i * 512 + j * 64] = av[j][i];
    if (u < 10) g_AI[n * 10 + u] = ATTR[n * 10 + u] / (dens + 1.f);
    if (u == 0) g_CUR[n] = 0;
}

// ---------------- launcher ----------------
extern "C" void kernel_launch(void* const* d_in, const int* in_sizes, int n_in,
                              void* d_out, int out_size)
{
    (void)in_sizes; (void)n_in; (void)out_size;
    const float* node_attrs = (const float*)d_in[0];
    const float* node_feats = (const float*)d_in[1];
    const float* edge_attrs = (const float*)d_in[2];
    const float* edge_feats = (const float*)d_in[3];
    const int*   edge_index = (const int*)  d_in[4];
    const float* maginv     = (const float*)d_in[5];
    const float* magattr    = (const float*)d_in[6];
    const float* Wups       = (const float*)d_in[7];
    const float* Wupv       = (const float*)d_in[8];
    const float* w0         = (const float*)d_in[9];
    const float* w1         = (const float*)d_in[10];
    const float* w2         = (const float*)d_in[11];
    const float* w3         = (const float*)d_in[12];
    const float* magw       = (const float*)d_in[13];
    const float* densw      = (const float*)d_in[14];
    const float* lins       = (const float*)d_in[15];
    const float* linv       = (const float*)d_in[16];
    const float* skips      = (const float*)d_in[17];
    const float* skipv      = (const float*)d_in[18];
    float* out = (float*)d_out;

    float *pMS, *pMV, *pMSP, *pMVP;
    cudaGetSymbolAddress((void**)&pMS,  g_MS);
    cudaGetSymbolAddress((void**)&pMV,  g_MV);
    cudaGetSymbolAddress((void**)&pMSP, g_MSP);
    cudaGetSymbolAddress((void**)&pMVP, g_MVP);

    cudaFuncSetAttribute(k_mega, cudaFuncAttributeMaxDynamicSharedMemorySize, SM_MLP);

    const float a320 = 1.f / sqrtf(320.f);
    const float a512 = 1.f / sqrtf(512.f);
    const float a640 = 1.f / sqrtf(640.f);

    // 0: mega (edge path + hist + density + node up-proj)
    k_mega<<<EDGE_BLOCKS + UP_BLOCKS, 128, SM_MLP>>>(
        edge_feats, maginv, edge_index, w0, w1, w2, w3, magw, densw,
        node_feats, Wups, Wupv);
    // 1, 2: sort
    k_scan   <<<1, 1024>>>();
    k_scatter<<<N_EDGES/256, 256>>>(edge_index, edge_attrs);
    // 3: per-node combine  (PROFILED SLOT)
    k_mm<<<N_NODES, 64>>>(magattr, node_attrs);

    // lin_s / lin_v
    gemmk<64,32,false><<<dim3(N_NODES/64, 1, 1), 128>>>(pMS, 320, 1, 0, lins, lins, 64,
                                                        pMSP, 64, 1, 0, 320, a320, 0, 0, 0);
    gemmk<64,32,false><<<dim3(N_NODES/64, 1, 3), 128>>>(pMV, 1536, 1, 512, linv, linv, 64,
                                                        pMVP, 192, 1, 64, 512, a512, 0, 0, 0);
    // skip einsum
    gemmk<64,32,true><<<dim3(N_NODES/64, 1, 4), 128>>>(0, 0, 0, 0, skips, skipv, 64,
                                                       out, 256, 4, 1, 640, a640, 0, pMSP, pMVP);
}

// round 12
// speedup vs baseline: 1.1947x; 1.0068x over previous
#include <cuda_runtime.h>
#include <math.h>

#define N_NODES 8192
#define N_EDGES 65536

typedef unsigned long long ull;

// ---------------- scratch (static device globals; zero-initialized) ----------------
__device__ float g_S   [N_NODES*64];
__device__ float g_V   [N_NODES*192];
__device__ float g_EDN [N_EDGES];
__device__ float g_TP  [(size_t)N_EDGES*320];   // edge-order
__device__ float g_WM  [(size_t)N_EDGES*832];   // edge-order
__device__ float g_MS  [N_NODES*320];
__device__ float g_MV  [N_NODES*1536];
__device__ float g_AI  [N_NODES*10];
__device__ float g_MSP [N_NODES*64];
__device__ float g_MVP [N_NODES*192];
__device__ int   g_CNT [N_NODES];
__device__ int   g_CUR [N_NODES];
__device__ int   g_OFF [N_NODES+1];
__device__ int   g_SORT[N_EDGES];
__device__ int   g_SNDS[N_EDGES];
__device__ float4 g_EAS[N_EDGES];
__device__ float g_EDNS[N_EDGES];

__device__ __forceinline__ ull bcast(float f) {
    unsigned int u = __float_as_uint(f);
    ull r;
    asm("mov.b64 %0, {%1, %1};" : "=l"(r) : "r"(u));
    return r;
}
__device__ __forceinline__ ull pack2(float a, float b) {
    return ((ull)__float_as_uint(b) << 32) | __float_as_uint(a);
}
__device__ __forceinline__ void fma2(ull& acc, ull a, ull b) {
    asm("fma.rn.f32x2 %0, %1, %2, %0;" : "+l"(acc) : "l"(a), "l"(b));
}
__device__ __forceinline__ float lo2(ull v) { return __uint_as_float((unsigned int)v); }
__device__ __forceinline__ float hi2(ull v) { return __uint_as_float((unsigned int)(v >> 32)); }
__device__ __forceinline__ float silu(float v) { return v / (1.f + __expf(-v)); }

// ================= mega kernel: edge path and node up-proj ========
#define LDH 132
#define BSZE (64*68)
#define SM_MLP ((2*64*LDH + 2*BSZE) * 4)   // 102 KB
#define EDGE_BLOCKS (N_EDGES/128)          // 512
#define UP_BLOCKS   256

__device__ __forceinline__ void stage_B(float* Bs, const float* __restrict__ src,
                                        int srcStride, int rows, int tid)
{
    for (int j = 0; j < rows / 8; j++) {
        int kk = (tid >> 4) + j * 8;
        int c  = (tid & 15) * 4;
        *(float4*)(Bs + kk * 68 + c) = *(const float4*)(src + (size_t)kk * srcStride + c);
    }
}

template<int K>
__device__ __forceinline__ void tile_mm(const float* hsrc, const float* Bs,
                                        ull* acc, int tx, int ty)
{
#pragma unroll
    for (int i = 0; i < 32; i++) acc[i] = 0ull;
#pragma unroll 4
    for (int kk = 0; kk < K; kk++) {
        const ulonglong2* ap = (const ulonglong2*)(hsrc + kk * LDH + ty * 8);
        ulonglong2 aA = ap[0];
        ulonglong2 aB = ap[1];
        const float4* bp = (const float4*)(Bs + kk * 68 + tx * 8);
        float4 b0 = bp[0], b1 = bp[1];
        ull bb[8];
        bb[0] = bcast(b0.x); bb[1] = bcast(b0.y);
        bb[2] = bcast(b0.z); bb[3] = bcast(b0.w);
        bb[4] = bcast(b1.x); bb[5] = bcast(b1.y);
        bb[6] = bcast(b1.z); bb[7] = bcast(b1.w);
#pragma unroll
        for (int c = 0; c < 8; c++) {
            fma2(acc[c],      aA.x, bb[c]);
            fma2(acc[8 + c],  aA.y, bb[c]);
            fma2(acc[16 + c], aB.x, bb[c]);
            fma2(acc[24 + c], aB.y, bb[c]);
        }
    }
}

__device__ __forceinline__ void write_gmem(float* dst, int rs, const ull* acc,
                                           float alpha, int tx, int ty)
{
#pragma unroll
    for (int rp = 0; rp < 4; rp++) {
        int r = ty * 8 + rp * 2;
        float* c0 = dst + (size_t)r * rs + tx * 8;
        float* c1 = c0 + rs;
        float4 l0, l1, h0, h1;
        l0.x = lo2(acc[rp*8+0]) * alpha; h0.x = hi2(acc[rp*8+0]) * alpha;
        l0.y = lo2(acc[rp*8+1]) * alpha; h0.y = hi2(acc[rp*8+1]) * alpha;
        l0.z = lo2(acc[rp*8+2]) * alpha; h0.z = hi2(acc[rp*8+2]) * alpha;
        l0.w = lo2(acc[rp*8+3]) * alpha; h0.w = hi2(acc[rp*8+3]) * alpha;
        l1.x = lo2(acc[rp*8+4]) * alpha; h1.x = hi2(acc[rp*8+4]) * alpha;
        l1.y = lo2(acc[rp*8+5]) * alpha; h1.y = hi2(acc[rp*8+5]) * alpha;
        l1.z = lo2(acc[rp*8+6]) * alpha; h1.z = hi2(acc[rp*8+6]) * alpha;
        l1.w = lo2(acc[rp*8+7]) * alpha; h1.w = hi2(acc[rp*8+7]) * alpha;
        *(float4*)(c0)     = l0;
        *(float4*)(c0 + 4) = l1;
        *(float4*)(c1)     = h0;
        *(float4*)(c1 + 4) = h1;
    }
}

__device__ __forceinline__ void write_h(float* hdst, const ull* acc,
                                        float alpha, int tx, int ty)
{
#pragma unroll
    for (int rp = 0; rp < 4; rp++) {
        int r = ty * 8 + rp * 2;
#pragma unroll
        for (int c = 0; c < 8; c++) {
            float v0 = silu(lo2(acc[rp*8+c]) * alpha);
            float v1 = silu(hi2(acc[rp*8+c]) * alpha);
            *(ull*)(hdst + (tx * 8 + c) * LDH + r) = pack2(v0, v1);
        }
    }
}

__global__ void __launch_bounds__(128) k_mega(
    const float* __restrict__ EF, const float* __restrict__ MI,
    const int* __restrict__ EI,
    const float* __restrict__ w0, const float* __restrict__ w1,
    const float* __restrict__ w2, const float* __restrict__ w3,
    const float* __restrict__ magw,
    const float* __restrict__ feats,
    const float* __restrict__ Wups, const float* __restrict__ Wupv)
{
    extern __shared__ float sm[];
    float* hA  = sm;
    float* hB  = sm + 64 * LDH;
    float* Bs0 = sm + 2 * 64 * LDH;
    float* Bs1 = Bs0 + BSZE;

    const int tid = threadIdx.x;
    const int tx = tid & 7, ty = tid >> 3;

    if (blockIdx.x >= EDGE_BLOCKS) {
        // =============== node up-projection block ===============
        int ub = blockIdx.x - EDGE_BLOCKS;
        int z  = ub >> 6;
        long row0 = (long)(ub & 63) * 128;

        if (z == 0) {
            const float* Ar = feats + (row0 + tid) * 256;
#pragma unroll
            for (int k4 = 0; k4 < 16; k4++) {
                float4 v = *(const float4*)(Ar + k4 * 4);
                hA[(k4*4 + 0) * LDH + tid] = v.x;
                hA[(k4*4 + 1) * LDH + tid] = v.y;
                hA[(k4*4 + 2) * LDH + tid] = v.z;
                hA[(k4*4 + 3) * LDH + tid] = v.w;
            }
        } else {
            const float* Ar = feats + (row0 + tid) * 256 + 64 + (z - 1);
#pragma unroll 8
            for (int k = 0; k < 64; k++)
                hA[k * LDH + tid] = Ar[k * 3];
        }
        stage_B(Bs0, (z == 0) ? Wups : Wupv, 64, 64, tid);
        __syncthreads();

        ull acc[32];
        tile_mm<64>(hA, Bs0, acc, tx, ty);
        if (z == 0)
            write_gmem(g_S + row0 * 64, 64, acc, 0.125f, tx, ty);
        else
            write_gmem(g_V + row0 * 192 + (z - 1) * 64, 192, acc, 0.125f, tx, ty);
        return;
    }

    // =============== edge-path block ===============
    const size_t e0 = (size_t)blockIdx.x * 128;
    {
        size_t e = e0 + tid;
        float4 a = *(const float4*)(EF + e * 8);
        float4 b = *(const float4*)(EF + e * 8 + 4);
        int snd = EI[e];
        float4 c = *(const float4*)(MI + (size_t)snd * 8);
        float4 d = *(const float4*)(MI + (size_t)snd * 8 + 4);
        hA[ 0*LDH+tid]=a.x; hA[ 1*LDH+tid]=a.y; hA[ 2*LDH+tid]=a.z; hA[ 3*LDH+tid]=a.w;
        hA[ 4*LDH+tid]=b.x; hA[ 5*LDH+tid]=b.y; hA[ 6*LDH+tid]=b.z; hA[ 7*LDH+tid]=b.w;
        hA[ 8*LDH+tid]=c.x; hA[ 9*LDH+tid]=c.y; hA[10*LDH+tid]=c.z; hA[11*LDH+tid]=c.w;
        hA[12*LDH+tid]=d.x; hA[13*LDH+tid]=d.y; hA[14*LDH+tid]=d.z; hA[15*LDH+tid]=d.w;
    }
    stage_B(Bs0, w0, 64, 16, tid);
    __syncthreads();

    ull acc[32];
    float* cur = Bs0;
    float* nxt = Bs1;

    // layer 0
    stage_B(nxt, magw, 832, 16, tid);
    tile_mm<16>(hA, cur, acc, tx, ty);
    write_h(hB, acc, 0.25f, tx, ty);
    __syncthreads();
    { float* t = cur; cur = nxt; nxt = t; }

    // magw x13
    for (int j = 0; j < 13; j++) {
        if (j < 12) stage_B(nxt, magw + (j + 1) * 64, 832, 16, tid);
        else        stage_B(nxt, w1, 64, 64, tid);
        tile_mm<16>(hA, cur, acc, tx, ty);
        write_gmem(g_WM + e0 * 832 + j * 64, 832, acc, 0.25f, tx, ty);
        __syncthreads();
        { float* t = cur; cur = nxt; nxt = t; }
    }

    // layer 1
    stage_B(nxt, w2, 64, 64, tid);
    tile_mm<64>(hB, cur, acc, tx, ty);
    write_h(hA, acc, 0.125f, tx, ty);
    __syncthreads();
    { float* t = cur; cur = nxt; nxt = t; }

    // layer 2
    stage_B(nxt, w3, 320, 64, tid);
    tile_mm<64>(hA, cur, acc, tx, ty);
    write_h(hB, acc, 0.125f, tx, ty);
    __syncthreads();
    { float* t = cur; cur = nxt; nxt = t; }

    // TP x5
    for (int j = 0; j < 5; j++) {
        if (j < 4) stage_B(nxt, w3 + (j + 1) * 64, 320, 64, tid);
        tile_mm<64>(hB, cur, acc, tx, ty);
        write_gmem(g_TP + e0 * 320 + j * 64, 320, acc, 0.125f, tx, ty);
        __syncthreads();
        { float* t = cur; cur = nxt; nxt = t; }
    }
}

// ================= register-blocked GEMM (MODE: 0=normal, 1=skip, 2=lin) =========
template<int RB, int KT, int MODE>
__device__ __forceinline__ void g_stageA(float* dst, const float* __restrict__ Arow,
                                         const float* __restrict__ ai,
                                         int k0, int K, int arow, int kseg)
{
    const int LDA = RB + 4;
    const int KPT = (RB == 128) ? KT : KT / 2;
    if (MODE == 1) {
#pragma unroll 8
        for (int c = 0; c < KPT; c++) {
            int k = k0 + kseg + c;
            int u = (k * 6554) >> 16;
            int v = k - u * 10;
            dst[(kseg + c) * LDA + arow] = Arow[u] * ai[v];
        }
    } else {
#pragma unroll
        for (int c = 0; c < KPT / 4; c++) {
            int kk = kseg + c * 4;
            float4 val = make_float4(0.f, 0.f, 0.f, 0.f);
            if (k0 + kk < K) val = *(const float4*)(Arow + k0 + kk);
            dst[(kk + 0) * LDA + arow] = val.x;
            dst[(kk + 1) * LDA + arow] = val.y;
            dst[(kk + 2) * LDA + arow] = val.z;
            dst[(kk + 3) * LDA + arow] = val.w;
        }
    }
}

template<int KT>
__device__ __forceinline__ void g_stageB(float* dst, const float* __restrict__ B,
                                         int brs, int col0, int k0, int K, int tid)
{
#pragma unroll
    for (int j = 0; j < KT / 8; j++) {
        int kk = (tid >> 4) + j * 8;
        int c  = (tid & 15) * 4;
        float4 val = make_float4(0.f, 0.f, 0.f, 0.f);
        if (k0 + kk < K)
            val = *(const float4*)(B + (size_t)(k0 + kk) * brs + col0 + c);
        *(float4*)(dst + kk * 68 + c) = val;
    }
}

template<int RB, int KT, int MODE>
__global__ void __launch_bounds__(128) gemmk(
    const float* __restrict__ A, long ars, long azs,
    const float* __restrict__ B0, const float* __restrict__ Bz, int brs,
    float* __restrict__ C, long crs, int ccs, long czs,
    int Kin, float alphain,
    const float* __restrict__ MSP, const float* __restrict__ MVP)
{
    const int LDA = RB + 4;
    const int ASZ = KT * LDA;
    const int BSZ = KT * 68;
    const int RPT = RB / 16;
    const int PPT = RPT / 2;
    __shared__ float As[2 * KT * (RB + 4)];
    __shared__ float Bs[2 * KT * 68];

    const int tid = threadIdx.x;
    const int tx = tid & 7;
    const int ty = tid >> 3;
    const long row0 = (long)blockIdx.x * RB;
    const int  col0 = blockIdx.y * 64;
    const int  z = blockIdx.z;
    const float* __restrict__ B = (z == 0) ? B0 : Bz;

    const int arow = tid & (RB - 1);
    const int kseg = (RB == 128) ? 0 : ((tid >> 6) * (KT / 2));

    int K = Kin;
    float alpha = alphain;
    const float* Arow;
    const float* ai = 0;
    float* Crow;
    long crsE = crs;
    if (MODE == 1) {
        Arow = (z == 0) ? (MSP + (row0 + arow) * 64)
                        : (MVP + (row0 + arow) * 192 + (z - 1) * 64);
        ai = g_AI + (row0 + arow) * 10;
        Crow = C + z * czs;
    } else if (MODE == 2) {
        if (z == 0) {
            Arow = g_MS + (row0 + arow) * 320;
            K = 320; alpha = 0.05590169943749474f;         // 1/sqrt(320)
            Crow = g_MSP; crsE = 64;
        } else {
            Arow = g_MV + (row0 + arow) * 1536 + (z - 1) * 512;
            K = 512; alpha = 0.044194173824159216f;        // 1/sqrt(512)
            Crow = g_MVP + (z - 1) * 64; crsE = 192;
        }
    } else {
        Arow = A + (long)z * azs + (row0 + arow) * ars;
        Crow = C + z * czs;
    }

    ull acc[PPT * 8];
#pragma unroll
    for (int i = 0; i < PPT * 8; i++) acc[i] = 0ull;

    const int NT = (K + KT - 1) / KT;
    g_stageA<RB,KT,MODE>(As, Arow, ai, 0, K, arow, kseg);
    g_stageB<KT>(Bs, B, brs, col0, 0, K, tid);
    __syncthreads();

    for (int t = 0; t < NT; t++) {
        const float* Ab = As + (t & 1) * ASZ;
        const float* Bb = Bs + (t & 1) * BSZ;
        if (t + 1 < NT) {
            g_stageA<RB,KT,MODE>(As + ((t + 1) & 1) * ASZ, Arow, ai,
                                 (t + 1) * KT, K, arow, kseg);
            g_stageB<KT>(Bs + ((t + 1) & 1) * BSZ, B, brs, col0, (t + 1) * KT, K, tid);
        }
#pragma unroll 4
        for (int kk = 0; kk < KT; kk++) {
            ull ar[PPT];
            {
                const ulonglong2* ap = (const ulonglong2*)(Ab + kk * LDA + ty * RPT);
                ulonglong2 t0 = ap[0];
                ar[0] = t0.x; ar[1] = t0.y;
                if (RB == 128) {
                    ulonglong2 t1 = ap[1];
                    ar[2] = t1.x; ar[3] = t1.y;
                }
            }
            const float4* bp = (const float4*)(Bb + kk * 68 + tx * 8);
            float4 b0 = bp[0], b1 = bp[1];
            ull bb[8];
            bb[0] = bcast(b0.x); bb[1] = bcast(b0.y);
            bb[2] = bcast(b0.z); bb[3] = bcast(b0.w);
            bb[4] = bcast(b1.x); bb[5] = bcast(b1.y);
            bb[6] = bcast(b1.z); bb[7] = bcast(b1.w);
#pragma unroll
            for (int c = 0; c < 8; c++)
#pragma unroll
                for (int p = 0; p < PPT; p++)
                    fma2(acc[p * 8 + c], ar[p], bb[c]);
        }
        __syncthreads();
    }

#pragma unroll
    for (int rp = 0; rp < PPT; rp++) {
        long r = row0 + ty * RPT + rp * 2;
        float lo[8], hi[8];
#pragma unroll
        for (int c = 0; c < 8; c++) {
            ull av = acc[rp * 8 + c];
            lo[c] = lo2(av) * alpha;
            hi[c] = hi2(av) * alpha;
        }
        if (ccs == 1) {
            float* c0 = Crow + r * crsE + col0 + tx * 8;
            float* c1 = c0 + crsE;
            *(float4*)(c0)     = make_float4(lo[0], lo[1], lo[2], lo[3]);
            *(float4*)(c0 + 4) = make_float4(lo[4], lo[5], lo[6], lo[7]);
            *(float4*)(c1)     = make_float4(hi[0], hi[1], hi[2], hi[3]);
            *(float4*)(c1 + 4) = make_float4(hi[4], hi[5], hi[6], hi[7]);
        } else {
#pragma unroll
            for (int c = 0; c < 8; c++) {
                long col = (long)(col0 + tx * 8 + c) * ccs;
                Crow[r * crsE + col] = lo[c];
                Crow[(r + 1) * crsE + col] = hi[c];
            }
        }
    }
}

// ---------------- hist(+density), scan, scatter ----------------
__global__ void k_hist(const int* __restrict__ EI, const float* __restrict__ EF,
                       const float* __restrict__ DW)
{
    int e = blockIdx.x * 256 + threadIdx.x;
    atomicAdd(&g_CNT[EI[N_EDGES + e]], 1);
    float d = 0.f;
#pragma unroll
    for (int i = 0; i < 8; i++) d += EF[e * 8 + i] * DW[i];
    d *= 0.3535533905932738f;
    g_EDN[e] = tanhf(d * d);
}
__global__ void k_scan()
{
    __shared__ int part[1024];
    int t = threadIdx.x;
    int loc[8]; int s = 0;
#pragma unroll
    for (int j = 0; j < 8; j++) { loc[j] = s; s += g_CNT[t * 8 + j]; }
    part[t] = s;
    __syncthreads();
    for (int off = 1; off < 1024; off <<= 1) {
        int v = (t >= off) ? part[t - off] : 0;
        __syncthreads();
        part[t] += v;
        __syncthreads();
    }
    int excl = part[t] - s;
#pragma unroll
    for (int j = 0; j < 8; j++) {
        g_OFF[t * 8 + j] = excl + loc[j];
        g_CNT[t * 8 + j] = 0;
    }
    if (t == 1023) g_OFF[N_NODES] = part[1023];
}
__global__ void k_scatter(const int* __restrict__ EI, const float* __restrict__ EA)
{
    int e = blockIdx.x * 256 + threadIdx.x;
    int r = EI[N_EDGES + e];
    int p = g_OFF[r] + atomicAdd(&g_CUR[r], 1);
    g_SORT[p] = e;
    g_SNDS[p] = EI[e];
    g_EAS[p]  = *(const float4*)(EA + (size_t)e * 4);
    g_EDNS[p] = g_EDN[e];
}

// ---------------- per-node combine (unchanged from R11) ----------
__global__ void __launch_bounds__(64) k_mm(const float* __restrict__ MA,
                                           const float* __restrict__ ATTR)
{
    const int n = blockIdx.x;
    const int u = threadIdx.x;
    const int beg = g_OFF[n], end = g_OFF[n + 1];

    float as0 = 0, as1 = 0, as2 = 0, as3 = 0, as4 = 0;
    float av[8][3];
#pragma unroll
    for (int j = 0; j < 8; j++)
#pragma unroll
        for (int i = 0; i < 3; i++) av[j][i] = 0.f;
    float dens = 0.f;

    const float I3 = 0.5773502691896258f;
    const float I2 = 0.7071067811865476f;

    int e_n = 0;
    float4 ea_c = make_float4(0,0,0,0), ma_c = make_float4(0,0,0,0);
    float xs_c = 0, vx_c = 0, vy_c = 0, vz_c = 0, ed_c = 0;
    float t_c[5], w_c[13];
#pragma unroll
    for (int i = 0; i < 5; i++) t_c[i] = 0.f;
#pragma unroll
    for (int i = 0; i < 13; i++) w_c[i] = 0.f;

    if (beg < end) {
        int ec = g_SORT[beg];
        if (beg + 1 < end) e_n = g_SORT[beg + 1];
        int sc = g_SNDS[beg];
        ea_c = g_EAS[beg];
        ed_c = g_EDNS[beg];
        ma_c = *(const float4*)(MA + (size_t)sc * 4);
        xs_c = g_S[(size_t)sc * 64 + u];
        const float* vp = g_V + (size_t)sc * 192 + u;
        vx_c = vp[0]; vy_c = vp[64]; vz_c = vp[128];
        const float* tp = g_TP + (size_t)ec * 320 + u;
#pragma unroll
        for (int i = 0; i < 5; i++) t_c[i] = tp[i * 64];
        const float* wm = g_WM + (size_t)ec * 832 + u;
#pragma unroll
        for (int i = 0; i < 13; i++) w_c[i] = wm[i * 64];
    }

    for (int q = beg; q < end; q++) {
        float4 ea_nn = make_float4(0,0,0,0), ma_nn = make_float4(0,0,0,0);
        float xs_nn = 0, vx_nn = 0, vy_nn = 0, vz_nn = 0, ed_nn = 0;
        float t_nn[5], w_nn[13];
#pragma unroll
        for (int i = 0; i < 5; i++) t_nn[i] = 0.f;
#pragma unroll
        for (int i = 0; i < 13; i++) w_nn[i] = 0.f;
        int e_2 = 0;
        if (q + 1 < end) {
            if (q + 2 < end) e_2 = g_SORT[q + 2];
            int sn = g_SNDS[q + 1];
            ea_nn = g_EAS[q + 1];
            ed_nn = g_EDNS[q + 1];
            ma_nn = *(const float4*)(MA + (size_t)sn * 4);
            xs_nn = g_S[(size_t)sn * 64 + u];
            const float* vp = g_V + (size_t)sn * 192 + u;
            vx_nn = vp[0]; vy_nn = vp[64]; vz_nn = vp[128];
            const float* tp = g_TP + (size_t)e_n * 320 + u;
#pragma unroll
            for (int i = 0; i < 5; i++) t_nn[i] = tp[i * 64];
            const float* wm = g_WM + (size_t)e_n * 832 + u;
#pragma unroll
            for (int i = 0; i < 13; i++) w_nn[i] = wm[i * 64];
        }

        const float y0 = ea_c.x, yx = ea_c.y, yy = ea_c.z, yz = ea_c.w;
        const float m0 = ma_c.x, mx = ma_c.y, my = ma_c.z, mz = ma_c.w;
        const float xs = xs_c, vx = vx_c, vy = vy_c, vz = vz_c;

        const float ms0 = t_c[0] * xs * y0;
        const float A0x = t_c[1] * xs * yx, A0y = t_c[1] * xs * yy, A0z = t_c[1] * xs * yz;
        const float B0x = t_c[2] * vx * y0, B0y = t_c[2] * vy * y0, B0z = t_c[2] * vz * y0;
        const float ms1 = t_c[3] * (vx * yx + vy * yy + vz * yz) * I3;
        const float cx = vy * yz - vz * yy;
        const float cy = vz * yx - vx * yz;
        const float cz = vx * yy - vy * yx;
        const float C0x = t_c[4] * cx * I2, C0y = t_c[4] * cy * I2, C0z = t_c[4] * cz * I2;

        as0 += w_c[0] * ms0 * m0;
        { float w_ = w_c[1] * ms0;  av[0][0] += w_ * mx; av[0][1] += w_ * my; av[0][2] += w_ * mz; }
        as1 += w_c[2] * ms1 * m0;
        { float w_ = w_c[3] * ms1;  av[1][0] += w_ * mx; av[1][1] += w_ * my; av[1][2] += w_ * mz; }

        { float w_ = w_c[4] * m0;   av[2][0] += w_ * A0x; av[2][1] += w_ * A0y; av[2][2] += w_ * A0z; }
        as2 += w_c[5] * (A0x * mx + A0y * my + A0z * mz) * I3;
        { float w_ = w_c[6] * I2;
          av[3][0] += w_ * (A0y * mz - A0z * my);
          av[3][1] += w_ * (A0z * mx - A0x * mz);
          av[3][2] += w_ * (A0x * my - A0y * mx); }

        { float w_ = w_c[7] * m0;   av[4][0] += w_ * B0x; av[4][1] += w_ * B0y; av[4][2] += w_ * B0z; }
        as3 += w_c[8] * (B0x * mx + B0y * my + B0z * mz) * I3;
        { float w_ = w_c[9] * I2;
          av[5][0] += w_ * (B0y * mz - B0z * my);
          av[5][1] += w_ * (B0z * mx - B0x * mz);
          av[5][2] += w_ * (B0x * my - B0y * mx); }

        { float w_ = w_c[10] * m0;  av[6][0] += w_ * C0x; av[6][1] += w_ * C0y; av[6][2] += w_ * C0z; }
        as4 += w_c[11] * (C0x * mx + C0y * my + C0z * mz) * I3;
        { float w_ = w_c[12] * I2;
          av[7][0] += w_ * (C0y * mz - C0z * my);
          av[7][1] += w_ * (C0z * mx - C0x * mz);
          av[7][2] += w_ * (C0x * my - C0y * mx); }

        dens += ed_c;

        ea_c = ea_nn; ma_c = ma_nn;
        xs_c = xs_nn; vx_c = vx_nn; vy_c = vy_nn; vz_c = vz_nn; ed_c = ed_nn;
#pragma unroll
        for (int i = 0; i < 5; i++) t_c[i] = t_nn[i];
#pragma unroll
        for (int i = 0; i < 13; i++) w_c[i] = w_nn[i];
        e_n = e_2;
    }

    const size_t b = (size_t)n * 320 + u;
    g_MS[b]       = as0;
    g_MS[b + 64]  = as1;
    g_MS[b + 128] = as2;
    g_MS[b + 192] = as3;
    g_MS[b + 256] = as4;
    const size_t bv = (size_t)n * 1536 + u;
#pragma unroll
    for (int i = 0; i < 3; i++)
#pragma unroll
        for (int j = 0; j < 8; j++)
            g_MV[bv + i * 512 + j * 64] = av[j][i];
    if (u < 10) g_AI[n * 10 + u] = ATTR[n * 10 + u] / (dens + 1.f);
    if (u == 0) g_CUR[n] = 0;
}

// ---------------- launcher ----------------
extern "C" void kernel_launch(void* const* d_in, const int* in_sizes, int n_in,
                              void* d_out, int out_size)
{
    (void)in_sizes; (void)n_in; (void)out_size;
    const float* node_attrs = (const float*)d_in[0];
    const float* node_feats = (const float*)d_in[1];
    const float* edge_attrs = (const float*)d_in[2];
    const float* edge_feats = (const float*)d_in[3];
    const int*   edge_index = (const int*)  d_in[4];
    const float* maginv     = (const float*)d_in[5];
    const float* magattr    = (const float*)d_in[6];
    const float* Wups       = (const float*)d_in[7];
    const float* Wupv       = (const float*)d_in[8];
    const float* w0         = (const float*)d_in[9];
    const float* w1         = (const float*)d_in[10];
    const float* w2         = (const float*)d_in[11];
    const float* w3         = (const float*)d_in[12];
    const float* magw       = (const float*)d_in[13];
    const float* densw      = (const float*)d_in[14];
    const float* lins       = (const float*)d_in[15];
    const float* linv       = (const float*)d_in[16];
    const float* skips      = (const float*)d_in[17];
    const float* skipv      = (const float*)d_in[18];
    float* out = (float*)d_out;

    float *pMSP, *pMVP;
    cudaGetSymbolAddress((void**)&pMSP, g_MSP);
    cudaGetSymbolAddress((void**)&pMVP, g_MVP);

    cudaFuncSetAttribute(k_mega, cudaFuncAttributeMaxDynamicSharedMemorySize, SM_MLP);

    const float a640 = 1.f / sqrtf(640.f);

    // 0-2: hist(+density), scan, scatter
    k_hist   <<<N_EDGES/256, 256>>>(edge_index, edge_feats, densw);
    k_scan   <<<1, 1024>>>();
    k_scatter<<<N_EDGES/256, 256>>>(edge_index, edge_attrs);

    // 3: mega (edge path + node up-proj)  (PROFILED SLOT)
    k_mega<<<EDGE_BLOCKS + UP_BLOCKS, 128, SM_MLP>>>(
        edge_feats, maginv, edge_index, w0, w1, w2, w3, magw,
        node_feats, Wups, Wupv);

    // 4: per-node combine
    k_mm<<<N_NODES, 64>>>(magattr, node_attrs);

    // 5: lin_s + lin_v batched (MODE=2)
    gemmk<64,32,2><<<dim3(N_NODES/64, 1, 4), 128>>>(0, 0, 0, lins, linv, 64,
                                                    0, 0, 1, 0, 0, 0.f, 0, 0);
    // 6: skip einsum (MODE=1)
    gemmk<64,32,1><<<dim3(N_NODES/64, 1, 4), 128>>>(0, 0, 0, skips, skipv, 64,
                                                    out, 256, 4, 1, 640, a640, pMSP, pMVP);
}

// round 13
// speedup vs baseline: 1.2093x; 1.0123x over previous
#include <cuda_runtime.h>
#include <math.h>

#define N_NODES 8192
#define N_EDGES 65536

typedef unsigned long long ull;

// ---------------- scratch (static device globals; zero-initialized) ----------------
__device__ float g_S   [N_NODES*64];
__device__ float g_V   [N_NODES*192];
__device__ float g_EDN [N_EDGES];
__device__ float g_TP  [(size_t)N_EDGES*320];   // edge-order
__device__ float g_WM  [(size_t)N_EDGES*832];   // edge-order
__device__ float g_MS  [N_NODES*320];
__device__ float g_MV  [N_NODES*1536];
__device__ float g_AI  [N_NODES*10];
__device__ float g_MSP [N_NODES*64];
__device__ float g_MVP [N_NODES*192];
__device__ int   g_CNT [N_NODES];
__device__ int   g_CUR [N_NODES];
__device__ int   g_OFF [N_NODES+1];
__device__ int   g_SORT[N_EDGES];
__device__ int   g_SNDS[N_EDGES];
__device__ float4 g_EAS[N_EDGES];
__device__ float g_EDNS[N_EDGES];

__device__ __forceinline__ ull bcast(float f) {
    unsigned int u = __float_as_uint(f);
    ull r;
    asm("mov.b64 %0, {%1, %1};" : "=l"(r) : "r"(u));
    return r;
}
__device__ __forceinline__ ull pack2(float a, float b) {
    return ((ull)__float_as_uint(b) << 32) | __float_as_uint(a);
}
__device__ __forceinline__ void fma2(ull& acc, ull a, ull b) {
    asm("fma.rn.f32x2 %0, %1, %2, %0;" : "+l"(acc) : "l"(a), "l"(b));
}
__device__ __forceinline__ float lo2(ull v) { return __uint_as_float((unsigned int)v); }
__device__ __forceinline__ float hi2(ull v) { return __uint_as_float((unsigned int)(v >> 32)); }
__device__ __forceinline__ float silu(float v) { return v / (1.f + __expf(-v)); }

// ================= mega kernel: edge path and node up-proj ========
// Single h buffer (in-place layer updates) + single Bs -> 51.2 KB -> 4 blocks/SM.
#define LDH 132
#define BSZE (64*68)
#define SM_MLP ((64*LDH + BSZE) * 4)       // h + Bs = 51.2 KB
#define EDGE_BLOCKS (N_EDGES/128)          // 512
#define UP_BLOCKS   256

__device__ __forceinline__ void stage_B(float* Bs, const float* __restrict__ src,
                                        int srcStride, int rows, int tid)
{
    for (int j = 0; j < rows / 8; j++) {
        int kk = (tid >> 4) + j * 8;
        int c  = (tid & 15) * 4;
        *(float4*)(Bs + kk * 68 + c) = *(const float4*)(src + (size_t)kk * srcStride + c);
    }
}

template<int K>
__device__ __forceinline__ void tile_mm(const float* hsrc, const float* Bs,
                                        ull* acc, int tx, int ty)
{
#pragma unroll
    for (int i = 0; i < 32; i++) acc[i] = 0ull;
#pragma unroll 4
    for (int kk = 0; kk < K; kk++) {
        const ulonglong2* ap = (const ulonglong2*)(hsrc + kk * LDH + ty * 8);
        ulonglong2 aA = ap[0];
        ulonglong2 aB = ap[1];
        const float4* bp = (const float4*)(Bs + kk * 68 + tx * 8);
        float4 b0 = bp[0], b1 = bp[1];
        ull bb[8];
        bb[0] = bcast(b0.x); bb[1] = bcast(b0.y);
        bb[2] = bcast(b0.z); bb[3] = bcast(b0.w);
        bb[4] = bcast(b1.x); bb[5] = bcast(b1.y);
        bb[6] = bcast(b1.z); bb[7] = bcast(b1.w);
#pragma unroll
        for (int c = 0; c < 8; c++) {
            fma2(acc[c],      aA.x, bb[c]);
            fma2(acc[8 + c],  aA.y, bb[c]);
            fma2(acc[16 + c], aB.x, bb[c]);
            fma2(acc[24 + c], aB.y, bb[c]);
        }
    }
}

__device__ __forceinline__ void write_gmem(float* dst, int rs, const ull* acc,
                                           float alpha, int tx, int ty)
{
#pragma unroll
    for (int rp = 0; rp < 4; rp++) {
        int r = ty * 8 + rp * 2;
        float* c0 = dst + (size_t)r * rs + tx * 8;
        float* c1 = c0 + rs;
        float4 l0, l1, h0, h1;
        l0.x = lo2(acc[rp*8+0]) * alpha; h0.x = hi2(acc[rp*8+0]) * alpha;
        l0.y = lo2(acc[rp*8+1]) * alpha; h0.y = hi2(acc[rp*8+1]) * alpha;
        l0.z = lo2(acc[rp*8+2]) * alpha; h0.z = hi2(acc[rp*8+2]) * alpha;
        l0.w = lo2(acc[rp*8+3]) * alpha; h0.w = hi2(acc[rp*8+3]) * alpha;
        l1.x = lo2(acc[rp*8+4]) * alpha; h1.x = hi2(acc[rp*8+4]) * alpha;
        l1.y = lo2(acc[rp*8+5]) * alpha; h1.y = hi2(acc[rp*8+5]) * alpha;
        l1.z = lo2(acc[rp*8+6]) * alpha; h1.z = hi2(acc[rp*8+6]) * alpha;
        l1.w = lo2(acc[rp*8+7]) * alpha; h1.w = hi2(acc[rp*8+7]) * alpha;
        *(float4*)(c0)     = l0;
        *(float4*)(c0 + 4) = l1;
        *(float4*)(c1)     = h0;
        *(float4*)(c1 + 4) = h1;
    }
}

__device__ __forceinline__ void write_h(float* hdst, const ull* acc,
                                        float alpha, int tx, int ty)
{
#pragma unroll
    for (int rp = 0; rp < 4; rp++) {
        int r = ty * 8 + rp * 2;
#pragma unroll
        for (int c = 0; c < 8; c++) {
            float v0 = silu(lo2(acc[rp*8+c]) * alpha);
            float v1 = silu(hi2(acc[rp*8+c]) * alpha);
            *(ull*)(hdst + (tx * 8 + c) * LDH + r) = pack2(v0, v1);
        }
    }
}

__global__ void __launch_bounds__(128, 4) k_mega(
    const float* __restrict__ EF, const float* __restrict__ MI,
    const int* __restrict__ EI,
    const float* __restrict__ w0, const float* __restrict__ w1,
    const float* __restrict__ w2, const float* __restrict__ w3,
    const float* __restrict__ magw,
    const float* __restrict__ feats,
    const float* __restrict__ Wups, const float* __restrict__ Wupv)
{
    extern __shared__ float sm[];
    float* hA = sm;                 // 64 x LDH (in-place across layers)
    float* Bs = sm + 64 * LDH;      // 64 x 68  (single buffer)

    const int tid = threadIdx.x;
    const int tx = tid & 7, ty = tid >> 3;

    if (blockIdx.x >= EDGE_BLOCKS) {
        // =============== node up-projection block ===============
        int ub = blockIdx.x - EDGE_BLOCKS;
        int z  = ub >> 6;
        long row0 = (long)(ub & 63) * 128;

        if (z == 0) {
            const float* Ar = feats + (row0 + tid) * 256;
#pragma unroll
            for (int k4 = 0; k4 < 16; k4++) {
                float4 v = *(const float4*)(Ar + k4 * 4);
                hA[(k4*4 + 0) * LDH + tid] = v.x;
                hA[(k4*4 + 1) * LDH + tid] = v.y;
                hA[(k4*4 + 2) * LDH + tid] = v.z;
                hA[(k4*4 + 3) * LDH + tid] = v.w;
            }
        } else {
            const float* Ar = feats + (row0 + tid) * 256 + 64 + (z - 1);
#pragma unroll 8
            for (int k = 0; k < 64; k++)
                hA[k * LDH + tid] = Ar[k * 3];
        }
        stage_B(Bs, (z == 0) ? Wups : Wupv, 64, 64, tid);
        __syncthreads();

        ull acc[32];
        tile_mm<64>(hA, Bs, acc, tx, ty);
        if (z == 0)
            write_gmem(g_S + row0 * 64, 64, acc, 0.125f, tx, ty);
        else
            write_gmem(g_V + row0 * 192 + (z - 1) * 64, 192, acc, 0.125f, tx, ty);
        return;
    }

    // =============== edge-path block ===============
    const size_t e0 = (size_t)blockIdx.x * 128;
    {
        size_t e = e0 + tid;
        float4 a = *(const float4*)(EF + e * 8);
        float4 b = *(const float4*)(EF + e * 8 + 4);
        int snd = EI[e];
        float4 c = *(const float4*)(MI + (size_t)snd * 8);
        float4 d = *(const float4*)(MI + (size_t)snd * 8 + 4);
        hA[ 0*LDH+tid]=a.x; hA[ 1*LDH+tid]=a.y; hA[ 2*LDH+tid]=a.z; hA[ 3*LDH+tid]=a.w;
        hA[ 4*LDH+tid]=b.x; hA[ 5*LDH+tid]=b.y; hA[ 6*LDH+tid]=b.z; hA[ 7*LDH+tid]=b.w;
        hA[ 8*LDH+tid]=c.x; hA[ 9*LDH+tid]=c.y; hA[10*LDH+tid]=c.z; hA[11*LDH+tid]=c.w;
        hA[12*LDH+tid]=d.x; hA[13*LDH+tid]=d.y; hA[14*LDH+tid]=d.z; hA[15*LDH+tid]=d.w;
    }
    stage_B(Bs, magw, 832, 16, tid);
    __syncthreads();

    ull acc[32];

    // ---- magw x13 (efm still in hA) ----
    for (int j = 0; j < 13; j++) {
        tile_mm<16>(hA, Bs, acc, tx, ty);
        __syncthreads();                               // Bs reads done
        write_gmem(g_WM + e0 * 832 + j * 64, 832, acc, 0.25f, tx, ty);
        if (j < 12) stage_B(Bs, magw + (j + 1) * 64, 832, 16, tid);
        else        stage_B(Bs, w0, 64, 16, tid);
        __syncthreads();                               // Bs staged
    }

    // ---- layer 0 (in-place): hA <- silu(efm @ w0 / 4) ----
    tile_mm<16>(hA, Bs, acc, tx, ty);
    __syncthreads();                                   // hA+Bs reads done
    write_h(hA, acc, 0.25f, tx, ty);
    stage_B(Bs, w1, 64, 64, tid);
    __syncthreads();

    // ---- layer 1 ----
    tile_mm<64>(hA, Bs, acc, tx, ty);
    __syncthreads();
    write_h(hA, acc, 0.125f, tx, ty);
    stage_B(Bs, w2, 64, 64, tid);
    __syncthreads();

    // ---- layer 2 ----
    tile_mm<64>(hA, Bs, acc, tx, ty);
    __syncthreads();
    write_h(hA, acc, 0.125f, tx, ty);
    stage_B(Bs, w3, 320, 64, tid);
    __syncthreads();

    // ---- TP x5 ----
    for (int j = 0; j < 5; j++) {
        tile_mm<64>(hA, Bs, acc, tx, ty);
        __syncthreads();
        write_gmem(g_TP + e0 * 320 + j * 64, 320, acc, 0.125f, tx, ty);
        if (j < 4) stage_B(Bs, w3 + (j + 1) * 64, 320, 64, tid);
        __syncthreads();
    }
}

// ================= register-blocked GEMM (MODE: 0=normal, 1=skip, 2=lin) =========
template<int RB, int KT, int MODE>
__device__ __forceinline__ void g_stageA(float* dst, const float* __restrict__ Arow,
                                         const float* __restrict__ ai,
                                         int k0, int K, int arow, int kseg)
{
    const int LDA = RB + 4;
    const int KPT = (RB == 128) ? KT : KT / 2;
    if (MODE == 1) {
#pragma unroll 8
        for (int c = 0; c < KPT; c++) {
            int k = k0 + kseg + c;
            int u = (k * 6554) >> 16;
            int v = k - u * 10;
            dst[(kseg + c) * LDA + arow] = Arow[u] * ai[v];
        }
    } else {
#pragma unroll
        for (int c = 0; c < KPT / 4; c++) {
            int kk = kseg + c * 4;
            float4 val = make_float4(0.f, 0.f, 0.f, 0.f);
            if (k0 + kk < K) val = *(const float4*)(Arow + k0 + kk);
            dst[(kk + 0) * LDA + arow] = val.x;
            dst[(kk + 1) * LDA + arow] = val.y;
            dst[(kk + 2) * LDA + arow] = val.z;
            dst[(kk + 3) * LDA + arow] = val.w;
        }
    }
}

template<int KT>
__device__ __forceinline__ void g_stageB(float* dst, const float* __restrict__ B,
                                         int brs, int col0, int k0, int K, int tid)
{
#pragma unroll
    for (int j = 0; j < KT / 8; j++) {
        int kk = (tid >> 4) + j * 8;
        int c  = (tid & 15) * 4;
        float4 val = make_float4(0.f, 0.f, 0.f, 0.f);
        if (k0 + kk < K)
            val = *(const float4*)(B + (size_t)(k0 + kk) * brs + col0 + c);
        *(float4*)(dst + kk * 68 + c) = val;
    }
}

template<int RB, int KT, int MODE>
__global__ void __launch_bounds__(128) gemmk(
    const float* __restrict__ A, long ars, long azs,
    const float* __restrict__ B0, const float* __restrict__ Bz, int brs,
    float* __restrict__ C, long crs, int ccs, long czs,
    int Kin, float alphain,
    const float* __restrict__ MSP, const float* __restrict__ MVP)
{
    const int LDA = RB + 4;
    const int ASZ = KT * LDA;
    const int BSZ = KT * 68;
    const int RPT = RB / 16;
    const int PPT = RPT / 2;
    __shared__ float As[2 * KT * (RB + 4)];
    __shared__ float Bs[2 * KT * 68];

    const int tid = threadIdx.x;
    const int tx = tid & 7;
    const int ty = tid >> 3;
    const long row0 = (long)blockIdx.x * RB;
    const int  col0 = blockIdx.y * 64;
    const int  z = blockIdx.z;
    const float* __restrict__ B = (z == 0) ? B0 : Bz;

    const int arow = tid & (RB - 1);
    const int kseg = (RB == 128) ? 0 : ((tid >> 6) * (KT / 2));

    int K = Kin;
    float alpha = alphain;
    const float* Arow;
    const float* ai = 0;
    float* Crow;
    long crsE = crs;
    if (MODE == 1) {
        Arow = (z == 0) ? (MSP + (row0 + arow) * 64)
                        : (MVP + (row0 + arow) * 192 + (z - 1) * 64);
        ai = g_AI + (row0 + arow) * 10;
        Crow = C + z * czs;
    } else if (MODE == 2) {
        if (z == 0) {
            Arow = g_MS + (row0 + arow) * 320;
            K = 320; alpha = 0.05590169943749474f;
            Crow = g_MSP; crsE = 64;
        } else {
            Arow = g_MV + (row0 + arow) * 1536 + (z - 1) * 512;
            K = 512; alpha = 0.044194173824159216f;
            Crow = g_MVP + (z - 1) * 64; crsE = 192;
        }
    } else {
        Arow = A + (long)z * azs + (row0 + arow) * ars;
        Crow = C + z * czs;
    }

    ull acc[PPT * 8];
#pragma unroll
    for (int i = 0; i < PPT * 8; i++) acc[i] = 0ull;

    const int NT = (K + KT - 1) / KT;
    g_stageA<RB,KT,MODE>(As, Arow, ai, 0, K, arow, kseg);
    g_stageB<KT>(Bs, B, brs, col0, 0, K, tid);
    __syncthreads();

    for (int t = 0; t < NT; t++) {
        const float* Ab = As + (t & 1) * ASZ;
        const float* Bb = Bs + (t & 1) * BSZ;
        if (t + 1 < NT) {
            g_stageA<RB,KT,MODE>(As + ((t + 1) & 1) * ASZ, Arow, ai,
                                 (t + 1) * KT, K, arow, kseg);
            g_stageB<KT>(Bs + ((t + 1) & 1) * BSZ, B, brs, col0, (t + 1) * KT, K, tid);
        }
#pragma unroll 4
        for (int kk = 0; kk < KT; kk++) {
            ull ar[PPT];
            {
                const ulonglong2* ap = (const ulonglong2*)(Ab + kk * LDA + ty * RPT);
                ulonglong2 t0 = ap[0];
                ar[0] = t0.x; ar[1] = t0.y;
                if (RB == 128) {
                    ulonglong2 t1 = ap[1];
                    ar[2] = t1.x; ar[3] = t1.y;
                }
            }
            const float4* bp = (const float4*)(Bb + kk * 68 + tx * 8);
            float4 b0 = bp[0], b1 = bp[1];
            ull bb[8];
            bb[0] = bcast(b0.x); bb[1] = bcast(b0.y);
            bb[2] = bcast(b0.z); bb[3] = bcast(b0.w);
            bb[4] = bcast(b1.x); bb[5] = bcast(b1.y);
            bb[6] = bcast(b1.z); bb[7] = bcast(b1.w);
#pragma unroll
            for (int c = 0; c < 8; c++)
#pragma unroll
                for (int p = 0; p < PPT; p++)
                    fma2(acc[p * 8 + c], ar[p], bb[c]);
        }
        __syncthreads();
    }

#pragma unroll
    for (int rp = 0; rp < PPT; rp++) {
        long r = row0 + ty * RPT + rp * 2;
        float lo[8], hi[8];
#pragma unroll
        for (int c = 0; c < 8; c++) {
            ull av = acc[rp * 8 + c];
            lo[c] = lo2(av) * alpha;
            hi[c] = hi2(av) * alpha;
        }
        if (ccs == 1) {
            float* c0 = Crow + r * crsE + col0 + tx * 8;
            float* c1 = c0 + crsE;
            *(float4*)(c0)     = make_float4(lo[0], lo[1], lo[2], lo[3]);
            *(float4*)(c0 + 4) = make_float4(lo[4], lo[5], lo[6], lo[7]);
            *(float4*)(c1)     = make_float4(hi[0], hi[1], hi[2], hi[3]);
            *(float4*)(c1 + 4) = make_float4(hi[4], hi[5], hi[6], hi[7]);
        } else {
#pragma unroll
            for (int c = 0; c < 8; c++) {
                long col = (long)(col0 + tx * 8 + c) * ccs;
                Crow[r * crsE + col] = lo[c];
                Crow[(r + 1) * crsE + col] = hi[c];
            }
        }
    }
}

// ---------------- hist(+density), scan, scatter ----------------
__global__ void k_hist(const int* __restrict__ EI, const float* __restrict__ EF,
                       const float* __restrict__ DW)
{
    int e = blockIdx.x * 256 + threadIdx.x;
    atomicAdd(&g_CNT[EI[N_EDGES + e]], 1);
    float d = 0.f;
#pragma unroll
    for (int i = 0; i < 8; i++) d += EF[e * 8 + i] * DW[i];
    d *= 0.3535533905932738f;
    g_EDN[e] = tanhf(d * d);
}
__global__ void k_scan()
{
    __shared__ int part[1024];
    int t = threadIdx.x;
    int loc[8]; int s = 0;
#pragma unroll
    for (int j = 0; j < 8; j++) { loc[j] = s; s += g_CNT[t * 8 + j]; }
    part[t] = s;
    __syncthreads();
    for (int off = 1; off < 1024; off <<= 1) {
        int v = (t >= off) ? part[t - off] : 0;
        __syncthreads();
        part[t] += v;
        __syncthreads();
    }
    int excl = part[t] - s;
#pragma unroll
    for (int j = 0; j < 8; j++) {
        g_OFF[t * 8 + j] = excl + loc[j];
        g_CNT[t * 8 + j] = 0;
    }
    if (t == 1023) g_OFF[N_NODES] = part[1023];
}
__global__ void k_scatter(const int* __restrict__ EI, const float* __restrict__ EA)
{
    int e = blockIdx.x * 256 + threadIdx.x;
    int r = EI[N_EDGES + e];
    int p = g_OFF[r] + atomicAdd(&g_CUR[r], 1);
    g_SORT[p] = e;
    g_SNDS[p] = EI[e];
    g_EAS[p]  = *(const float4*)(EA + (size_t)e * 4);
    g_EDNS[p] = g_EDN[e];
}

// ---------------- per-node combine ----------
__global__ void __launch_bounds__(64) k_mm(const float* __restrict__ MA,
                                           const float* __restrict__ ATTR)
{
    const int n = blockIdx.x;
    const int u = threadIdx.x;
    const int beg = g_OFF[n], end = g_OFF[n + 1];

    float as0 = 0, as1 = 0, as2 = 0, as3 = 0, as4 = 0;
    float av[8][3];
#pragma unroll
    for (int j = 0; j < 8; j++)
#pragma unroll
        for (int i = 0; i < 3; i++) av[j][i] = 0.f;
    float dens = 0.f;

    const float I3 = 0.5773502691896258f;
    const float I2 = 0.7071067811865476f;

    int e_n = 0;
    float4 ea_c = make_float4(0,0,0,0), ma_c = make_float4(0,0,0,0);
    float xs_c = 0, vx_c = 0, vy_c = 0, vz_c = 0, ed_c = 0;
    float t_c[5], w_c[13];
#pragma unroll
    for (int i = 0; i < 5; i++) t_c[i] = 0.f;
#pragma unroll
    for (int i = 0; i < 13; i++) w_c[i] = 0.f;

    if (beg < end) {
        int ec = g_SORT[beg];
        if (beg + 1 < end) e_n = g_SORT[beg + 1];
        int sc = g_SNDS[beg];
        ea_c = g_EAS[beg];
        ed_c = g_EDNS[beg];
        ma_c = *(const float4*)(MA + (size_t)sc * 4);
        xs_c = g_S[(size_t)sc * 64 + u];
        const float* vp = g_V + (size_t)sc * 192 + u;
        vx_c = vp[0]; vy_c = vp[64]; vz_c = vp[128];
        const float* tp = g_TP + (size_t)ec * 320 + u;
#pragma unroll
        for (int i = 0; i < 5; i++) t_c[i] = tp[i * 64];
        const float* wm = g_WM + (size_t)ec * 832 + u;
#pragma unroll
        for (int i = 0; i < 13; i++) w_c[i] = wm[i * 64];
    }

    for (int q = beg; q < end; q++) {
        float4 ea_nn = make_float4(0,0,0,0), ma_nn = make_float4(0,0,0,0);
        float xs_nn = 0, vx_nn = 0, vy_nn = 0, vz_nn = 0, ed_nn = 0;
        float t_nn[5], w_nn[13];
#pragma unroll
        for (int i = 0; i < 5; i++) t_nn[i] = 0.f;
#pragma unroll
        for (int i = 0; i < 13; i++) w_nn[i] = 0.f;
        int e_2 = 0;
        if (q + 1 < end) {
            if (q + 2 < end) e_2 = g_SORT[q + 2];
            int sn = g_SNDS[q + 1];
            ea_nn = g_EAS[q + 1];
            ed_nn = g_EDNS[q + 1];
            ma_nn = *(const float4*)(MA + (size_t)sn * 4);
            xs_nn = g_S[(size_t)sn * 64 + u];
            const float* vp = g_V + (size_t)sn * 192 + u;
            vx_nn = vp[0]; vy_nn = vp[64]; vz_nn = vp[128];
            const float* tp = g_TP + (size_t)e_n * 320 + u;
#pragma unroll
            for (int i = 0; i < 5; i++) t_nn[i] = tp[i * 64];
            const float* wm = g_WM + (size_t)e_n * 832 + u;
#pragma unroll
            for (int i = 0; i < 13; i++) w_nn[i] = wm[i * 64];
        }

        const float y0 = ea_c.x, yx = ea_c.y, yy = ea_c.z, yz = ea_c.w;
        const float m0 = ma_c.x, mx = ma_c.y, my = ma_c.z, mz = ma_c.w;
        const float xs = xs_c, vx = vx_c, vy = vy_c, vz = vz_c;

        const float ms0 = t_c[0] * xs * y0;
        const float A0x = t_c[1] * xs * yx, A0y = t_c[1] * xs * yy, A0z = t_c[1] * xs * yz;
        const float B0x = t_c[2] * vx * y0, B0y = t_c[2] * vy * y0, B0z = t_c[2] * vz * y0;
        const float ms1 = t_c[3] * (vx * yx + vy * yy + vz * yz) * I3;
        const float cx = vy * yz - vz * yy;
        const float cy = vz * yx - vx * yz;
        const float cz = vx * yy - vy * yx;
        const float C0x = t_c[4] * cx * I2, C0y = t_c[4] * cy * I2, C0z = t_c[4] * cz * I2;

        as0 += w_c[0] * ms0 * m0;
        { float w_ = w_c[1] * ms0;  av[0][0] += w_ * mx; av[0][1] += w_ * my; av[0][2] += w_ * mz; }
        as1 += w_c[2] * ms1 * m0;
        { float w_ = w_c[3] * ms1;  av[1][0] += w_ * mx; av[1][1] += w_ * my; av[1][2] += w_ * mz; }

        { float w_ = w_c[4] * m0;   av[2][0] += w_ * A0x; av[2][1] += w_ * A0y; av[2][2] += w_ * A0z; }
        as2 += w_c[5] * (A0x * mx + A0y * my + A0z * mz) * I3;
        { float w_ = w_c[6] * I2;
          av[3][0] += w_ * (A0y * mz - A0z * my);
          av[3][1] += w_ * (A0z * mx - A0x * mz);
          av[3][2] += w_ * (A0x * my - A0y * mx); }

        { float w_ = w_c[7] * m0;   av[4][0] += w_ * B0x; av[4][1] += w_ * B0y; av[4][2] += w_ * B0z; }
        as3 += w_c[8] * (B0x * mx + B0y * my + B0z * mz) * I3;
        { float w_ = w_c[9] * I2;
          av[5][0] += w_ * (B0y * mz - B0z * my);
          av[5][1] += w_ * (B0z * mx - B0x * mz);
          av[5][2] += w_ * (B0x * my - B0y * mx); }

        { float w_ = w_c[10] * m0;  av[6][0] += w_ * C0x; av[6][1] += w_ * C0y; av[6][2] += w_ * C0z; }
        as4 += w_c[11] * (C0x * mx + C0y * my + C0z * mz) * I3;
        { float w_ = w_c[12] * I2;
          av[7][0] += w_ * (C0y * mz - C0z * my);
          av[7][1] += w_ * (C0z * mx - C0x * mz);
          av[7][2] += w_ * (C0x * my - C0y * mx); }

        dens += ed_c;

        ea_c = ea_nn; ma_c = ma_nn;
        xs_c = xs_nn; vx_c = vx_nn; vy_c = vy_nn; vz_c = vz_nn; ed_c = ed_nn;
#pragma unroll
        for (int i = 0; i < 5; i++) t_c[i] = t_nn[i];
#pragma unroll
        for (int i = 0; i < 13; i++) w_c[i] = w_nn[i];
        e_n = e_2;
    }

    const size_t b = (size_t)n * 320 + u;
    g_MS[b]       = as0;
    g_MS[b + 64]  = as1;
    g_MS[b + 128] = as2;
    g_MS[b + 192] = as3;
    g_MS[b + 256] = as4;
    const size_t bv = (size_t)n * 1536 + u;
#pragma unroll
    for (int i = 0; i < 3; i++)
#pragma unroll
        for (int j = 0; j < 8; j++)
            g_MV[bv + i * 512 + j * 64] = av[j][i];
    if (u < 10) g_AI[n * 10 + u] = ATTR[n * 10 + u] / (dens + 1.f);
    if (u == 0) g_CUR[n] = 0;
}

// ---------------- launcher ----------------
extern "C" void kernel_launch(void* const* d_in, const int* in_sizes, int n_in,
                              void* d_out, int out_size)
{
    (void)in_sizes; (void)n_in; (void)out_size;
    const float* node_attrs = (const float*)d_in[0];
    const float* node_feats = (const float*)d_in[1];
    const float* edge_attrs = (const float*)d_in[2];
    const float* edge_feats = (const float*)d_in[3];
    const int*   edge_index = (const int*)  d_in[4];
    const float* maginv     = (const float*)d_in[5];
    const float* magattr    = (const float*)d_in[6];
    const float* Wups       = (const float*)d_in[7];
    const float* Wupv       = (const float*)d_in[8];
    const float* w0         = (const float*)d_in[9];
    const float* w1         = (const float*)d_in[10];
    const float* w2         = (const float*)d_in[11];
    const float* w3         = (const float*)d_in[12];
    const float* magw       = (const float*)d_in[13];
    const float* densw      = (const float*)d_in[14];
    const float* lins       = (const float*)d_in[15];
    const float* linv       = (const float*)d_in[16];
    const float* skips      = (const float*)d_in[17];
    const float* skipv      = (const float*)d_in[18];
    float* out = (float*)d_out;

    float *pMSP, *pMVP;
    cudaGetSymbolAddress((void**)&pMSP, g_MSP);
    cudaGetSymbolAddress((void**)&pMVP, g_MVP);

    cudaFuncSetAttribute(k_mega, cudaFuncAttributeMaxDynamicSharedMemorySize, SM_MLP);

    const float a640 = 1.f / sqrtf(640.f);

    // 0-2: hist(+density), scan, scatter
    k_hist   <<<N_EDGES/256, 256>>>(edge_index, edge_feats, densw);
    k_scan   <<<1, 1024>>>();
    k_scatter<<<N_EDGES/256, 256>>>(edge_index, edge_attrs);

    // 3: mega (edge path + node up-proj)  (PROFILED SLOT)
    k_mega<<<EDGE_BLOCKS + UP_BLOCKS, 128, SM_MLP>>>(
        edge_feats, maginv, edge_index, w0, w1, w2, w3, magw,
        node_feats, Wups, Wupv);

    // 4: per-node combine
    k_mm<<<N_NODES, 64>>>(magattr, node_attrs);

    // 5: lin_s + lin_v batched
    gemmk<64,32,2><<<dim3(N_NODES/64, 1, 4), 128>>>(0, 0, 0, lins, linv, 64,
                                                    0, 0, 1, 0, 0, 0.f, 0, 0);
    // 6: skip einsum
    gemmk<64,32,1><<<dim3(N_NODES/64, 1, 4), 128>>>(0, 0, 0, skips, skipv, 64,
                                                    out, 256, 4, 1, 640, a640, pMSP, pMVP);
}

// round 14
// speedup vs baseline: 1.4320x; 1.1842x over previous
#include <cuda_runtime.h>
#include <math.h>

#define N_NODES 8192
#define N_EDGES 65536

typedef unsigned long long ull;

// ---------------- scratch (static device globals; zero-initialized) ----------------
__device__ float g_S   [N_NODES*64];
__device__ float g_V   [N_NODES*192];
__device__ float g_EDN [N_EDGES];
__device__ float g_TP  [(size_t)N_EDGES*320];
__device__ float g_WM  [(size_t)N_EDGES*832];
__device__ float g_MS  [N_NODES*320];
__device__ float g_MV  [N_NODES*1536];
__device__ float g_AI  [N_NODES*10];
__device__ int   g_CNT [N_NODES];
__device__ int   g_CUR [N_NODES];
__device__ int   g_OFF [N_NODES+1];
__device__ int   g_SORT[N_EDGES];
__device__ int   g_SNDS[N_EDGES];
__device__ float4 g_EAS[N_EDGES];
__device__ float g_EDNS[N_EDGES];

__device__ __forceinline__ ull bcast(float f) {
    unsigned int u = __float_as_uint(f);
    ull r;
    asm("mov.b64 %0, {%1, %1};" : "=l"(r) : "r"(u));
    return r;
}
__device__ __forceinline__ ull pack2(float a, float b) {
    return ((ull)__float_as_uint(b) << 32) | __float_as_uint(a);
}
__device__ __forceinline__ void fma2(ull& acc, ull a, ull b) {
    asm("fma.rn.f32x2 %0, %1, %2, %0;" : "+l"(acc) : "l"(a), "l"(b));
}
__device__ __forceinline__ float lo2(ull v) { return __uint_as_float((unsigned int)v); }
__device__ __forceinline__ float hi2(ull v) { return __uint_as_float((unsigned int)(v >> 32)); }
__device__ __forceinline__ float silu(float v) { return v / (1.f + __expf(-v)); }

// ================= mega kernel: edge path (+hist +density) and node up-proj ========
// Single h buffer + single Bs -> 51.2 KB -> 4 blocks/SM.
// Grid 576 = 512 edge blocks + 64 up blocks (each loops 4 z items) -> ONE wave.
#define LDH 132
#define BSZE (64*68)
#define SM_MLP ((64*LDH + BSZE) * 4)       // 51.2 KB
#define EDGE_BLOCKS (N_EDGES/128)          // 512
#define UPB 64

__device__ __forceinline__ void stage_B(float* Bs, const float* __restrict__ src,
                                        int srcStride, int rows, int tid)
{
    for (int j = 0; j < rows / 8; j++) {
        int kk = (tid >> 4) + j * 8;
        int c  = (tid & 15) * 4;
        *(float4*)(Bs + kk * 68 + c) = *(const float4*)(src + (size_t)kk * srcStride + c);
    }
}

template<int K>
__device__ __forceinline__ void tile_mm(const float* hsrc, const float* Bs,
                                        ull* acc, int tx, int ty)
{
#pragma unroll
    for (int i = 0; i < 32; i++) acc[i] = 0ull;
#pragma unroll 4
    for (int kk = 0; kk < K; kk++) {
        const ulonglong2* ap = (const ulonglong2*)(hsrc + kk * LDH + ty * 8);
        ulonglong2 aA = ap[0];
        ulonglong2 aB = ap[1];
        const float4* bp = (const float4*)(Bs + kk * 68 + tx * 8);
        float4 b0 = bp[0], b1 = bp[1];
        ull bb[8];
        bb[0] = bcast(b0.x); bb[1] = bcast(b0.y);
        bb[2] = bcast(b0.z); bb[3] = bcast(b0.w);
        bb[4] = bcast(b1.x); bb[5] = bcast(b1.y);
        bb[6] = bcast(b1.z); bb[7] = bcast(b1.w);
#pragma unroll
        for (int c = 0; c < 8; c++) {
            fma2(acc[c],      aA.x, bb[c]);
            fma2(acc[8 + c],  aA.y, bb[c]);
            fma2(acc[16 + c], aB.x, bb[c]);
            fma2(acc[24 + c], aB.y, bb[c]);
        }
    }
}

__device__ __forceinline__ void write_gmem(float* dst, int rs, const ull* acc,
                                           float alpha, int tx, int ty)
{
#pragma unroll
    for (int rp = 0; rp < 4; rp++) {
        int r = ty * 8 + rp * 2;
        float* c0 = dst + (size_t)r * rs + tx * 8;
        float* c1 = c0 + rs;
        float4 l0, l1, h0, h1;
        l0.x = lo2(acc[rp*8+0]) * alpha; h0.x = hi2(acc[rp*8+0]) * alpha;
        l0.y = lo2(acc[rp*8+1]) * alpha; h0.y = hi2(acc[rp*8+1]) * alpha;
        l0.z = lo2(acc[rp*8+2]) * alpha; h0.z = hi2(acc[rp*8+2]) * alpha;
        l0.w = lo2(acc[rp*8+3]) * alpha; h0.w = hi2(acc[rp*8+3]) * alpha;
        l1.x = lo2(acc[rp*8+4]) * alpha; h1.x = hi2(acc[rp*8+4]) * alpha;
        l1.y = lo2(acc[rp*8+5]) * alpha; h1.y = hi2(acc[rp*8+5]) * alpha;
        l1.z = lo2(acc[rp*8+6]) * alpha; h1.z = hi2(acc[rp*8+6]) * alpha;
        l1.w = lo2(acc[rp*8+7]) * alpha; h1.w = hi2(acc[rp*8+7]) * alpha;
        *(float4*)(c0)     = l0;
        *(float4*)(c0 + 4) = l1;
        *(float4*)(c1)     = h0;
        *(float4*)(c1 + 4) = h1;
    }
}

__device__ __forceinline__ void write_h(float* hdst, const ull* acc,
                                        float alpha, int tx, int ty)
{
#pragma unroll
    for (int rp = 0; rp < 4; rp++) {
        int r = ty * 8 + rp * 2;
#pragma unroll
        for (int c = 0; c < 8; c++) {
            float v0 = silu(lo2(acc[rp*8+c]) * alpha);
            float v1 = silu(hi2(acc[rp*8+c]) * alpha);
            *(ull*)(hdst + (tx * 8 + c) * LDH + r) = pack2(v0, v1);
        }
    }
}

__global__ void __launch_bounds__(128, 4) k_mega(
    const float* __restrict__ EF, const float* __restrict__ MI,
    const int* __restrict__ EI,
    const float* __restrict__ w0, const float* __restrict__ w1,
    const float* __restrict__ w2, const float* __restrict__ w3,
    const float* __restrict__ magw, const float* __restrict__ DW,
    const float* __restrict__ feats,
    const float* __restrict__ Wups, const float* __restrict__ Wupv)
{
    extern __shared__ float sm[];
    float* hA = sm;                 // 64 x LDH
    float* Bs = sm + 64 * LDH;      // 64 x 68

    const int tid = threadIdx.x;
    const int tx = tid & 7, ty = tid >> 3;

    if (blockIdx.x >= EDGE_BLOCKS) {
        // ====== node up-projection: one row-tile, loop over 4 z items ======
        const long row0 = (long)(blockIdx.x - EDGE_BLOCKS) * 128;
        ull acc[32];
#pragma unroll 1
        for (int z = 0; z < 4; z++) {
            if (z > 0) __syncthreads();       // prior tile_mm reads done
            if (z == 0) {
                const float* Ar = feats + (row0 + tid) * 256;
#pragma unroll
                for (int k4 = 0; k4 < 16; k4++) {
                    float4 v = *(const float4*)(Ar + k4 * 4);
                    hA[(k4*4 + 0) * LDH + tid] = v.x;
                    hA[(k4*4 + 1) * LDH + tid] = v.y;
                    hA[(k4*4 + 2) * LDH + tid] = v.z;
                    hA[(k4*4 + 3) * LDH + tid] = v.w;
                }
            } else {
                const float* Ar = feats + (row0 + tid) * 256 + 64 + (z - 1);
#pragma unroll 8
                for (int k = 0; k < 64; k++)
                    hA[k * LDH + tid] = Ar[k * 3];
            }
            stage_B(Bs, (z == 0) ? Wups : Wupv, 64, 64, tid);
            __syncthreads();
            tile_mm<64>(hA, Bs, acc, tx, ty);
            if (z == 0)
                write_gmem(g_S + row0 * 64, 64, acc, 0.125f, tx, ty);
            else
                write_gmem(g_V + row0 * 192 + (z - 1) * 64, 192, acc, 0.125f, tx, ty);
        }
        return;
    }

    // ====== edge-path block ======
    const size_t e0 = (size_t)blockIdx.x * 128;
    {
        size_t e = e0 + tid;
        float4 a = *(const float4*)(EF + e * 8);
        float4 b = *(const float4*)(EF + e * 8 + 4);
        int snd = EI[e];
        int rcv = EI[N_EDGES + e];
        atomicAdd(&g_CNT[rcv], 1);
        float4 c = *(const float4*)(MI + (size_t)snd * 8);
        float4 d = *(const float4*)(MI + (size_t)snd * 8 + 4);
        hA[ 0*LDH+tid]=a.x; hA[ 1*LDH+tid]=a.y; hA[ 2*LDH+tid]=a.z; hA[ 3*LDH+tid]=a.w;
        hA[ 4*LDH+tid]=b.x; hA[ 5*LDH+tid]=b.y; hA[ 6*LDH+tid]=b.z; hA[ 7*LDH+tid]=b.w;
        hA[ 8*LDH+tid]=c.x; hA[ 9*LDH+tid]=c.y; hA[10*LDH+tid]=c.z; hA[11*LDH+tid]=c.w;
        hA[12*LDH+tid]=d.x; hA[13*LDH+tid]=d.y; hA[14*LDH+tid]=d.z; hA[15*LDH+tid]=d.w;
        float dd = a.x*DW[0] + a.y*DW[1] + a.z*DW[2] + a.w*DW[3]
                 + b.x*DW[4] + b.y*DW[5] + b.z*DW[6] + b.w*DW[7];
        dd *= 0.3535533905932738f;
        g_EDN[e] = tanhf(dd * dd);
    }
    stage_B(Bs, magw, 832, 16, tid);
    __syncthreads();

    ull acc[32];

    // magw x13 (efm still in hA)
    for (int j = 0; j < 13; j++) {
        tile_mm<16>(hA, Bs, acc, tx, ty);
        __syncthreads();
        write_gmem(g_WM + e0 * 832 + j * 64, 832, acc, 0.25f, tx, ty);
        if (j < 12) stage_B(Bs, magw + (j + 1) * 64, 832, 16, tid);
        else        stage_B(Bs, w0, 64, 16, tid);
        __syncthreads();
    }

    // layer 0 (in-place)
    tile_mm<16>(hA, Bs, acc, tx, ty);
    __syncthreads();
    write_h(hA, acc, 0.25f, tx, ty);
    stage_B(Bs, w1, 64, 64, tid);
    __syncthreads();

    // layer 1
    tile_mm<64>(hA, Bs, acc, tx, ty);
    __syncthreads();
    write_h(hA, acc, 0.125f, tx, ty);
    stage_B(Bs, w2, 64, 64, tid);
    __syncthreads();

    // layer 2
    tile_mm<64>(hA, Bs, acc, tx, ty);
    __syncthreads();
    write_h(hA, acc, 0.125f, tx, ty);
    stage_B(Bs, w3, 320, 64, tid);
    __syncthreads();

    // TP x5
    for (int j = 0; j < 5; j++) {
        tile_mm<64>(hA, Bs, acc, tx, ty);
        __syncthreads();
        write_gmem(g_TP + e0 * 320 + j * 64, 320, acc, 0.125f, tx, ty);
        if (j < 4) stage_B(Bs, w3 + (j + 1) * 64, 320, 64, tid);
        __syncthreads();
    }
}

// ================= fused tail: lin (phase 1, into smem) + skip (phase 2) ==========
// Block = (64-row tile, z). z=0: msel=MS@lins (K=320); z>0: msel=MV_z@linv (K=512).
// Phase 2: out_z = (msel*ai) @ skip  (K=640).
#define TLD 65
#define SM_TAIL ((4*32*68 + 64*TLD) * 4)   // As(2) + Bs(2) + Msel = 51.4 KB

__global__ void __launch_bounds__(128) k_tail(
    const float* __restrict__ lins, const float* __restrict__ linv,
    const float* __restrict__ skips, const float* __restrict__ skipv,
    float* __restrict__ out)
{
    extern __shared__ float smt[];
    float* As   = smt;                 // 2 x 32 x 68
    float* Bs   = smt + 2 * 32 * 68;   // 2 x 32 x 68
    float* Msel = smt + 4 * 32 * 68;   // 64 x TLD

    const int tid = threadIdx.x;
    const int tx = tid & 7;
    const int ty = tid >> 3;
    const long row0 = (long)blockIdx.x * 64;
    const int z = blockIdx.z;
    const int arow = tid & 63;
    const int kseg = (tid >> 6) * 16;

    // ---------- phase 1: msel tile ----------
    const float* Arow;
    const float* B1;
    int K1; float a1;
    if (z == 0) {
        Arow = g_MS + (row0 + arow) * 320;
        B1 = lins; K1 = 320; a1 = 0.05590169943749474f;       // 1/sqrt(320)
    } else {
        Arow = g_MV + (row0 + arow) * 1536 + (z - 1) * 512;
        B1 = linv; K1 = 512; a1 = 0.044194173824159216f;      // 1/sqrt(512)
    }

    ull acc[16];
#pragma unroll
    for (int i = 0; i < 16; i++) acc[i] = 0ull;

    // stage tile 0
#pragma unroll
    for (int c = 0; c < 4; c++) {
        int kk = kseg + c * 4;
        float4 v = *(const float4*)(Arow + kk);
        As[(kk+0)*68 + arow] = v.x; As[(kk+1)*68 + arow] = v.y;
        As[(kk+2)*68 + arow] = v.z; As[(kk+3)*68 + arow] = v.w;
    }
#pragma unroll
    for (int j = 0; j < 4; j++) {
        int kk = (tid >> 4) + j * 8;
        int c  = (tid & 15) * 4;
        *(float4*)(Bs + kk * 68 + c) = *(const float4*)(B1 + (size_t)kk * 64 + c);
    }
    __syncthreads();

    const int NT1 = K1 / 32;
    for (int t = 0; t < NT1; t++) {
        const float* Ab = As + (t & 1) * (32 * 68);
        const float* Bb = Bs + (t & 1) * (32 * 68);
        if (t + 1 < NT1) {
            float* Ad = As + ((t + 1) & 1) * (32 * 68);
            float* Bd = Bs + ((t + 1) & 1) * (32 * 68);
            int k0 = (t + 1) * 32;
#pragma unroll
            for (int c = 0; c < 4; c++) {
                int kk = kseg + c * 4;
                float4 v = *(const float4*)(Arow + k0 + kk);
                Ad[(kk+0)*68 + arow] = v.x; Ad[(kk+1)*68 + arow] = v.y;
                Ad[(kk+2)*68 + arow] = v.z; Ad[(kk+3)*68 + arow] = v.w;
            }
#pragma unroll
            for (int j = 0; j < 4; j++) {
                int kk = (tid >> 4) + j * 8;
                int c  = (tid & 15) * 4;
                *(float4*)(Bd + kk * 68 + c) =
                    *(const float4*)(B1 + (size_t)(k0 + kk) * 64 + c);
            }
        }
#pragma unroll 4
        for (int kk = 0; kk < 32; kk++) {
            ulonglong2 aA = *(const ulonglong2*)(Ab + kk * 68 + ty * 4);
            const float4* bp = (const float4*)(Bb + kk * 68 + tx * 8);
            float4 b0 = bp[0], b1 = bp[1];
            ull bb[8];
            bb[0] = bcast(b0.x); bb[1] = bcast(b0.y);
            bb[2] = bcast(b0.z); bb[3] = bcast(b0.w);
            bb[4] = bcast(b1.x); bb[5] = bcast(b1.y);
            bb[6] = bcast(b1.z); bb[7] = bcast(b1.w);
#pragma unroll
            for (int c = 0; c < 8; c++) {
                fma2(acc[c],     aA.x, bb[c]);
                fma2(acc[8 + c], aA.y, bb[c]);
            }
        }
        __syncthreads();
    }
    // epilogue phase 1 -> Msel
#pragma unroll
    for (int rp = 0; rp < 2; rp++) {
        int r = ty * 4 + rp * 2;
#pragma unroll
        for (int c = 0; c < 8; c++) {
            ull av = acc[rp * 8 + c];
            Msel[r * TLD + tx * 8 + c]       = lo2(av) * a1;
            Msel[(r + 1) * TLD + tx * 8 + c] = hi2(av) * a1;
        }
    }
    __syncthreads();

    // ---------- phase 2: skip GEMM (K=640) ----------
    float ai[10];
#pragma unroll
    for (int v = 0; v < 10; v++) ai[v] = g_AI[(row0 + arow) * 10 + v];
    const float* B2 = (z == 0) ? skips : skipv;
    const float* mrow = Msel + arow * TLD;

#pragma unroll
    for (int i = 0; i < 16; i++) acc[i] = 0ull;

    // stage tile 0
#pragma unroll 8
    for (int c = 0; c < 16; c++) {
        int k = kseg + c;
        int u = (k * 6554) >> 16;
        int v = k - u * 10;
        As[(kseg + c) * 68 + arow] = mrow[u] * ai[v];
    }
#pragma unroll
    for (int j = 0; j < 4; j++) {
        int kk = (tid >> 4) + j * 8;
        int c  = (tid & 15) * 4;
        *(float4*)(Bs + kk * 68 + c) = *(const float4*)(B2 + (size_t)kk * 64 + c);
    }
    __syncthreads();

    for (int t = 0; t < 20; t++) {
        const float* Ab = As + (t & 1) * (32 * 68);
        const float* Bb = Bs + (t & 1) * (32 * 68);
        if (t + 1 < 20) {
            float* Ad = As + ((t + 1) & 1) * (32 * 68);
            float* Bd = Bs + ((t + 1) & 1) * (32 * 68);
            int k0 = (t + 1) * 32;
#pragma unroll 8
            for (int c = 0; c < 16; c++) {
                int k = k0 + kseg + c;
                int u = (k * 6554) >> 16;
                int v = k - u * 10;
                Ad[(kseg + c) * 68 + arow] = mrow[u] * ai[v];
            }
#pragma unroll
            for (int j = 0; j < 4; j++) {
                int kk = (tid >> 4) + j * 8;
                int c  = (tid & 15) * 4;
                *(float4*)(Bd + kk * 68 + c) =
                    *(const float4*)(B2 + (size_t)(k0 + kk) * 64 + c);
            }
        }
#pragma unroll 4
        for (int kk = 0; kk < 32; kk++) {
            ulonglong2 aA = *(const ulonglong2*)(Ab + kk * 68 + ty * 4);
            const float4* bp = (const float4*)(Bb + kk * 68 + tx * 8);
            float4 b0 = bp[0], b1 = bp[1];
            ull bb[8];
            bb[0] = bcast(b0.x); bb[1] = bcast(b0.y);
            bb[2] = bcast(b0.z); bb[3] = bcast(b0.w);
            bb[4] = bcast(b1.x); bb[5] = bcast(b1.y);
            bb[6] = bcast(b1.z); bb[7] = bcast(b1.w);
#pragma unroll
            for (int c = 0; c < 8; c++) {
                fma2(acc[c],     aA.x, bb[c]);
                fma2(acc[8 + c], aA.y, bb[c]);
            }
        }
        __syncthreads();
    }

    // epilogue phase 2 -> out (crs=256, ccs=4, +z)
    const float a640 = 0.03952847075210474f;  // 1/sqrt(640)
#pragma unroll
    for (int rp = 0; rp < 2; rp++) {
        long r = row0 + ty * 4 + rp * 2;
#pragma unroll
        for (int c = 0; c < 8; c++) {
            ull av = acc[rp * 8 + c];
            long col = (long)(tx * 8 + c) * 4 + z;
            out[r * 256 + col]       = lo2(av) * a640;
            out[(r + 1) * 256 + col] = hi2(av) * a640;
        }
    }
}

// ---------------- scan (re-zero CNT) + scatter (sorted copies) ----------------
__global__ void k_scan()
{
    __shared__ int part[1024];
    int t = threadIdx.x;
    int loc[8]; int s = 0;
#pragma unroll
    for (int j = 0; j < 8; j++) { loc[j] = s; s += g_CNT[t * 8 + j]; }
    part[t] = s;
    __syncthreads();
    for (int off = 1; off < 1024; off <<= 1) {
        int v = (t >= off) ? part[t - off] : 0;
        __syncthreads();
        part[t] += v;
        __syncthreads();
    }
    int excl = part[t] - s;
#pragma unroll
    for (int j = 0; j < 8; j++) {
        g_OFF[t * 8 + j] = excl + loc[j];
        g_CNT[t * 8 + j] = 0;
    }
    if (t == 1023) g_OFF[N_NODES] = part[1023];
}
__global__ void k_scatter(const int* __restrict__ EI, const float* __restrict__ EA)
{
    int e = blockIdx.x * 256 + threadIdx.x;
    int r = EI[N_EDGES + e];
    int p = g_OFF[r] + atomicAdd(&g_CUR[r], 1);
    g_SORT[p] = e;
    g_SNDS[p] = EI[e];
    g_EAS[p]  = *(const float4*)(EA + (size_t)e * 4);
    g_EDNS[p] = g_EDN[e];
}

// ---------------- per-node combine ----------
__global__ void __launch_bounds__(64) k_mm(const float* __restrict__ MA,
                                           const float* __restrict__ ATTR)
{
    const int n = blockIdx.x;
    const int u = threadIdx.x;
    const int beg = g_OFF[n], end = g_OFF[n + 1];

    float as0 = 0, as1 = 0, as2 = 0, as3 = 0, as4 = 0;
    float av[8][3];
#pragma unroll
    for (int j = 0; j < 8; j++)
#pragma unroll
        for (int i = 0; i < 3; i++) av[j][i] = 0.f;
    float dens = 0.f;

    const float I3 = 0.5773502691896258f;
    const float I2 = 0.7071067811865476f;

    int e_n = 0;
    float4 ea_c = make_float4(0,0,0,0), ma_c = make_float4(0,0,0,0);
    float xs_c = 0, vx_c = 0, vy_c = 0, vz_c = 0, ed_c = 0;
    float t_c[5], w_c[13];
#pragma unroll
    for (int i = 0; i < 5; i++) t_c[i] = 0.f;
#pragma unroll
    for (int i = 0; i < 13; i++) w_c[i] = 0.f;

    if (beg < end) {
        int ec = g_SORT[beg];
        if (beg + 1 < end) e_n = g_SORT[beg + 1];
        int sc = g_SNDS[beg];
        ea_c = g_EAS[beg];
        ed_c = g_EDNS[beg];
        ma_c = *(const float4*)(MA + (size_t)sc * 4);
        xs_c = g_S[(size_t)sc * 64 + u];
        const float* vp = g_V + (size_t)sc * 192 + u;
        vx_c = vp[0]; vy_c = vp[64]; vz_c = vp[128];
        const float* tp = g_TP + (size_t)ec * 320 + u;
#pragma unroll
        for (int i = 0; i < 5; i++) t_c[i] = tp[i * 64];
        const float* wm = g_WM + (size_t)ec * 832 + u;
#pragma unroll
        for (int i = 0; i < 13; i++) w_c[i] = wm[i * 64];
    }

    for (int q = beg; q < end; q++) {
        float4 ea_nn = make_float4(0,0,0,0), ma_nn = make_float4(0,0,0,0);
        float xs_nn = 0, vx_nn = 0, vy_nn = 0, vz_nn = 0, ed_nn = 0;
        float t_nn[5], w_nn[13];
#pragma unroll
        for (int i = 0; i < 5; i++) t_nn[i] = 0.f;
#pragma unroll
        for (int i = 0; i < 13; i++) w_nn[i] = 0.f;
        int e_2 = 0;
        if (q + 1 < end) {
            if (q + 2 < end) e_2 = g_SORT[q + 2];
            int sn = g_SNDS[q + 1];
            ea_nn = g_EAS[q + 1];
            ed_nn = g_EDNS[q + 1];
            ma_nn = *(const float4*)(MA + (size_t)sn * 4);
            xs_nn = g_S[(size_t)sn * 64 + u];
            const float* vp = g_V + (size_t)sn * 192 + u;
            vx_nn = vp[0]; vy_nn = vp[64]; vz_nn = vp[128];
            const float* tp = g_TP + (size_t)e_n * 320 + u;
#pragma unroll
            for (int i = 0; i < 5; i++) t_nn[i] = tp[i * 64];
            const float* wm = g_WM + (size_t)e_n * 832 + u;
#pragma unroll
            for (int i = 0; i < 13; i++) w_nn[i] = wm[i * 64];
        }

        const float y0 = ea_c.x, yx = ea_c.y, yy = ea_c.z, yz = ea_c.w;
        const float m0 = ma_c.x, mx = ma_c.y, my = ma_c.z, mz = ma_c.w;
        const float xs = xs_c, vx = vx_c, vy = vy_c, vz = vz_c;

        const float ms0 = t_c[0] * xs * y0;
        const float A0x = t_c[1] * xs * yx, A0y = t_c[1] * xs * yy, A0z = t_c[1] * xs * yz;
        const float B0x = t_c[2] * vx * y0, B0y = t_c[2] * vy * y0, B0z = t_c[2] * vz * y0;
        const float ms1 = t_c[3] * (vx * yx + vy * yy + vz * yz) * I3;
        const float cx = vy * yz - vz * yy;
        const float cy = vz * yx - vx * yz;
        const float cz = vx * yy - vy * yx;
        const float C0x = t_c[4] * cx * I2, C0y = t_c[4] * cy * I2, C0z = t_c[4] * cz * I2;

        as0 += w_c[0] * ms0 * m0;
        { float w_ = w_c[1] * ms0;  av[0][0] += w_ * mx; av[0][1] += w_ * my; av[0][2] += w_ * mz; }
        as1 += w_c[2] * ms1 * m0;
        { float w_ = w_c[3] * ms1;  av[1][0] += w_ * mx; av[1][1] += w_ * my; av[1][2] += w_ * mz; }

        { float w_ = w_c[4] * m0;   av[2][0] += w_ * A0x; av[2][1] += w_ * A0y; av[2][2] += w_ * A0z; }
        as2 += w_c[5] * (A0x * mx + A0y * my + A0z * mz) * I3;
        { float w_ = w_c[6] * I2;
          av[3][0] += w_ * (A0y * mz - A0z * my);
          av[3][1] += w_ * (A0z * mx - A0x * mz);
          av[3][2] += w_ * (A0x * my - A0y * mx); }

        { float w_ = w_c[7] * m0;   av[4][0] += w_ * B0x; av[4][1] += w_ * B0y; av[4][2] += w_ * B0z; }
        as3 += w_c[8] * (B0x * mx + B0y * my + B0z * mz) * I3;
        { float w_ = w_c[9] * I2;
          av[5][0] += w_ * (B0y * mz - B0z * my);
          av[5][1] += w_ * (B0z * mx - B0x * mz);
          av[5][2] += w_ * (B0x * my - B0y * mx); }

        { float w_ = w_c[10] * m0;  av[6][0] += w_ * C0x; av[6][1] += w_ * C0y; av[6][2] += w_ * C0z; }
        as4 += w_c[11] * (C0x * mx + C0y * my + C0z * mz) * I3;
        { float w_ = w_c[12] * I2;
          av[7][0] += w_ * (C0y * mz - C0z * my);
          av[7][1] += w_ * (C0z * mx - C0x * mz);
          av[7][2] += w_ * (C0x * my - C0y * mx); }

        dens += ed_c;

        ea_c = ea_nn; ma_c = ma_nn;
        xs_c = xs_nn; vx_c = vx_nn; vy_c = vy_nn; vz_c = vz_nn; ed_c = ed_nn;
#pragma unroll
        for (int i = 0; i < 5; i++) t_c[i] = t_nn[i];
#pragma unroll
        for (int i = 0; i < 13; i++) w_c[i] = w_nn[i];
        e_n = e_2;
    }

    const size_t b = (size_t)n * 320 + u;
    g_MS[b]       = as0;
    g_MS[b + 64]  = as1;
    g_MS[b + 128] = as2;
    g_MS[b + 192] = as3;
    g_MS[b + 256] = as4;
    const size_t bv = (size_t)n * 1536 + u;
#pragma unroll
    for (int i = 0; i < 3; i++)
#pragma unroll
        for (int j = 0; j < 8; j++)
            g_MV[bv + i * 512 + j * 64] = av[j][i];
    if (u < 10) g_AI[n * 10 + u] = ATTR[n * 10 + u] / (dens + 1.f);
    if (u == 0) g_CUR[n] = 0;
}

// ---------------- launcher ----------------
extern "C" void kernel_launch(void* const* d_in, const int* in_sizes, int n_in,
                              void* d_out, int out_size)
{
    (void)in_sizes; (void)n_in; (void)out_size;
    const float* node_attrs = (const float*)d_in[0];
    const float* node_feats = (const float*)d_in[1];
    const float* edge_attrs = (const float*)d_in[2];
    const float* edge_feats = (const float*)d_in[3];
    const int*   edge_index = (const int*)  d_in[4];
    const float* maginv     = (const float*)d_in[5];
    const float* magattr    = (const float*)d_in[6];
    const float* Wups       = (const float*)d_in[7];
    const float* Wupv       = (const float*)d_in[8];
    const float* w0         = (const float*)d_in[9];
    const float* w1         = (const float*)d_in[10];
    const float* w2         = (const float*)d_in[11];
    const float* w3         = (const float*)d_in[12];
    const float* magw       = (const float*)d_in[13];
    const float* densw      = (const float*)d_in[14];
    const float* lins       = (const float*)d_in[15];
    const float* linv       = (const float*)d_in[16];
    const float* skips      = (const float*)d_in[17];
    const float* skipv      = (const float*)d_in[18];
    float* out = (float*)d_out;

    cudaFuncSetAttribute(k_mega, cudaFuncAttributeMaxDynamicSharedMemorySize, SM_MLP);
    cudaFuncSetAttribute(k_tail, cudaFuncAttributeMaxDynamicSharedMemorySize, SM_TAIL);

    // 0: mega (edge path + hist + density + node up-proj), single wave
    k_mega<<<EDGE_BLOCKS + UPB, 128, SM_MLP>>>(
        edge_feats, maginv, edge_index, w0, w1, w2, w3, magw, densw,
        node_feats, Wups, Wupv);
    // 1, 2: sort
    k_scan   <<<1, 1024>>>();
    k_scatter<<<N_EDGES/256, 256>>>(edge_index, edge_attrs);
    // 3: per-node combine (PROFILED SLOT)
    k_mm<<<N_NODES, 64>>>(magattr, node_attrs);
    // 4: fused lin + skip tail
    k_tail<<<dim3(N_NODES/64, 1, 4), 128, SM_TAIL>>>(lins, linv, skips, skipv, out);
}

// round 16
// speedup vs baseline: 1.5436x; 1.0779x over previous
#include <cuda_runtime.h>
#include <cuda_fp16.h>
#include <math.h>

#define N_NODES 8192
#define N_EDGES 65536

typedef unsigned long long ull;

// ---------------- scratch (static device globals; zero-initialized) ----------------
__device__ float g_S   [N_NODES*64];
__device__ float g_V   [N_NODES*192];
__device__ float g_EDN [N_EDGES];
__device__ __half g_TP [(size_t)N_EDGES*320];   // fp16
__device__ __half g_WM [(size_t)N_EDGES*832];   // fp16
__device__ float g_MS  [N_NODES*320];
__device__ float g_MV  [N_NODES*1536];
__device__ float g_AI  [N_NODES*10];
__device__ int   g_CNT [N_NODES];
__device__ int   g_CUR [N_NODES];
__device__ int   g_OFF [N_NODES+1];
__device__ int   g_SORT[N_EDGES];
__device__ int   g_SNDS[N_EDGES];
__device__ float4 g_EAS[N_EDGES];
__device__ float g_EDNS[N_EDGES];

__device__ __forceinline__ ull bcast(float f) {
    unsigned int u = __float_as_uint(f);
    ull r;
    asm("mov.b64 %0, {%1, %1};" : "=l"(r) : "r"(u));
    return r;
}
__device__ __forceinline__ ull pack2(float a, float b) {
    return ((ull)__float_as_uint(b) << 32) | __float_as_uint(a);
}
__device__ __forceinline__ void fma2(ull& acc, ull a, ull b) {
    asm("fma.rn.f32x2 %0, %1, %2, %0;" : "+l"(acc) : "l"(a), "l"(b));
}
__device__ __forceinline__ float lo2(ull v) { return __uint_as_float((unsigned int)v); }
__device__ __forceinline__ float hi2(ull v) { return __uint_as_float((unsigned int)(v >> 32)); }
__device__ __forceinline__ float silu(float v) { return v / (1.f + __expf(-v)); }

// ================= mega kernel =================
#define LDH 132
#define BSZE (64*68)
#define SM_MLP ((64*LDH + BSZE) * 4)       // 51.2 KB, 4 blocks/SM
#define EDGE_BLOCKS (N_EDGES/128)          // 512
#define UPB 64

__device__ __forceinline__ void stage_B(float* Bs, const float* __restrict__ src,
                                        int srcStride, int rows, int tid)
{
    for (int j = 0; j < rows / 8; j++) {
        int kk = (tid >> 4) + j * 8;
        int c  = (tid & 15) * 4;
        *(float4*)(Bs + kk * 68 + c) = *(const float4*)(src + (size_t)kk * srcStride + c);
    }
}

template<int K>
__device__ __forceinline__ void tile_mm(const float* hsrc, const float* Bs,
                                        ull* acc, int tx, int ty)
{
#pragma unroll
    for (int i = 0; i < 32; i++) acc[i] = 0ull;
#pragma unroll 4
    for (int kk = 0; kk < K; kk++) {
        const ulonglong2* ap = (const ulonglong2*)(hsrc + kk * LDH + ty * 8);
        ulonglong2 aA = ap[0];
        ulonglong2 aB = ap[1];
        const float4* bp = (const float4*)(Bs + kk * 68 + tx * 8);
        float4 b0 = bp[0], b1 = bp[1];
        ull bb[8];
        bb[0] = bcast(b0.x); bb[1] = bcast(b0.y);
        bb[2] = bcast(b0.z); bb[3] = bcast(b0.w);
        bb[4] = bcast(b1.x); bb[5] = bcast(b1.y);
        bb[6] = bcast(b1.z); bb[7] = bcast(b1.w);
#pragma unroll
        for (int c = 0; c < 8; c++) {
            fma2(acc[c],      aA.x, bb[c]);
            fma2(acc[8 + c],  aA.y, bb[c]);
            fma2(acc[16 + c], aB.x, bb[c]);
            fma2(acc[24 + c], aB.y, bb[c]);
        }
    }
}

__device__ __forceinline__ void write_gmem(float* dst, int rs, const ull* acc,
                                           float alpha, int tx, int ty)
{
#pragma unroll
    for (int rp = 0; rp < 4; rp++) {
        int r = ty * 8 + rp * 2;
        float* c0 = dst + (size_t)r * rs + tx * 8;
        float* c1 = c0 + rs;
        float4 l0, l1, h0, h1;
        l0.x = lo2(acc[rp*8+0]) * alpha; h0.x = hi2(acc[rp*8+0]) * alpha;
        l0.y = lo2(acc[rp*8+1]) * alpha; h0.y = hi2(acc[rp*8+1]) * alpha;
        l0.z = lo2(acc[rp*8+2]) * alpha; h0.z = hi2(acc[rp*8+2]) * alpha;
        l0.w = lo2(acc[rp*8+3]) * alpha; h0.w = hi2(acc[rp*8+3]) * alpha;
        l1.x = lo2(acc[rp*8+4]) * alpha; h1.x = hi2(acc[rp*8+4]) * alpha;
        l1.y = lo2(acc[rp*8+5]) * alpha; h1.y = hi2(acc[rp*8+5]) * alpha;
        l1.z = lo2(acc[rp*8+6]) * alpha; h1.z = hi2(acc[rp*8+6]) * alpha;
        l1.w = lo2(acc[rp*8+7]) * alpha; h1.w = hi2(acc[rp*8+7]) * alpha;
        *(float4*)(c0)     = l0;
        *(float4*)(c0 + 4) = l1;
        *(float4*)(c1)     = h0;
        *(float4*)(c1 + 4) = h1;
    }
}

// fp16 tile store: 8 cols per row -> 4 __half2 = 16 bytes per row
struct h2x4 { __half2 a, b, c, d; };
__device__ __forceinline__ void write_gmem_h(__half* dst, int rs, const ull* acc,
                                             float alpha, int tx, int ty)
{
#pragma unroll
    for (int rp = 0; rp < 4; rp++) {
        int r = ty * 8 + rp * 2;
        __half* c0 = dst + (size_t)r * rs + tx * 8;
        __half* c1 = c0 + rs;
        float lo[8], hi[8];
#pragma unroll
        for (int c = 0; c < 8; c++) {
            lo[c] = lo2(acc[rp*8+c]) * alpha;
            hi[c] = hi2(acc[rp*8+c]) * alpha;
        }
        h2x4 pl, ph;
        pl.a = __floats2half2_rn(lo[0], lo[1]);
        pl.b = __floats2half2_rn(lo[2], lo[3]);
        pl.c = __floats2half2_rn(lo[4], lo[5]);
        pl.d = __floats2half2_rn(lo[6], lo[7]);
        ph.a = __floats2half2_rn(hi[0], hi[1]);
        ph.b = __floats2half2_rn(hi[2], hi[3]);
        ph.c = __floats2half2_rn(hi[4], hi[5]);
        ph.d = __floats2half2_rn(hi[6], hi[7]);
        *(h2x4*)(c0) = pl;
        *(h2x4*)(c1) = ph;
    }
}

__device__ __forceinline__ void write_h(float* hdst, const ull* acc,
                                        float alpha, int tx, int ty)
{
#pragma unroll
    for (int rp = 0; rp < 4; rp++) {
        int r = ty * 8 + rp * 2;
#pragma unroll
        for (int c = 0; c < 8; c++) {
            float v0 = silu(lo2(acc[rp*8+c]) * alpha);
            float v1 = silu(hi2(acc[rp*8+c]) * alpha);
            *(ull*)(hdst + (tx * 8 + c) * LDH + r) = pack2(v0, v1);
        }
    }
}

__global__ void __launch_bounds__(128, 4) k_mega(
    const float* __restrict__ EF, const float* __restrict__ MI,
    const int* __restrict__ EI,
    const float* __restrict__ w0, const float* __restrict__ w1,
    const float* __restrict__ w2, const float* __restrict__ w3,
    const float* __restrict__ magw, const float* __restrict__ DW,
    const float* __restrict__ feats,
    const float* __restrict__ Wups, const float* __restrict__ Wupv)
{
    extern __shared__ float sm[];
    float* hA = sm;                 // 64 x LDH
    float* Bs = sm + 64 * LDH;      // 64 x 68 (magw phase: two 16x68 halves)

    const int tid = threadIdx.x;
    const int tx = tid & 7, ty = tid >> 3;

    if (blockIdx.x >= EDGE_BLOCKS) {
        // ====== node up-projection: one row-tile, loop over 4 z items ======
        const long row0 = (long)(blockIdx.x - EDGE_BLOCKS) * 128;
        ull acc[32];
#pragma unroll 1
        for (int z = 0; z < 4; z++) {
            if (z > 0) __syncthreads();
            if (z == 0) {
                const float* Ar = feats + (row0 + tid) * 256;
#pragma unroll
                for (int k4 = 0; k4 < 16; k4++) {
                    float4 v = *(const float4*)(Ar + k4 * 4);
                    hA[(k4*4 + 0) * LDH + tid] = v.x;
                    hA[(k4*4 + 1) * LDH + tid] = v.y;
                    hA[(k4*4 + 2) * LDH + tid] = v.z;
                    hA[(k4*4 + 3) * LDH + tid] = v.w;
                }
            } else {
                const float* Ar = feats + (row0 + tid) * 256 + 64 + (z - 1);
#pragma unroll 8
                for (int k = 0; k < 64; k++)
                    hA[k * LDH + tid] = Ar[k * 3];
            }
            stage_B(Bs, (z == 0) ? Wups : Wupv, 64, 64, tid);
            __syncthreads();
            tile_mm<64>(hA, Bs, acc, tx, ty);
            if (z == 0)
                write_gmem(g_S + row0 * 64, 64, acc, 0.125f, tx, ty);
            else
                write_gmem(g_V + row0 * 192 + (z - 1) * 64, 192, acc, 0.125f, tx, ty);
        }
        return;
    }

    // ====== edge-path block ======
    const size_t e0 = (size_t)blockIdx.x * 128;
    {
        size_t e = e0 + tid;
        float4 a = *(const float4*)(EF + e * 8);
        float4 b = *(const float4*)(EF + e * 8 + 4);
        int snd = EI[e];
        int rcv = EI[N_EDGES + e];
        atomicAdd(&g_CNT[rcv], 1);
        float4 c = *(const float4*)(MI + (size_t)snd * 8);
        float4 d = *(const float4*)(MI + (size_t)snd * 8 + 4);
        hA[ 0*LDH+tid]=a.x; hA[ 1*LDH+tid]=a.y; hA[ 2*LDH+tid]=a.z; hA[ 3*LDH+tid]=a.w;
        hA[ 4*LDH+tid]=b.x; hA[ 5*LDH+tid]=b.y; hA[ 6*LDH+tid]=b.z; hA[ 7*LDH+tid]=b.w;
        hA[ 8*LDH+tid]=c.x; hA[ 9*LDH+tid]=c.y; hA[10*LDH+tid]=c.z; hA[11*LDH+tid]=c.w;
        hA[12*LDH+tid]=d.x; hA[13*LDH+tid]=d.y; hA[14*LDH+tid]=d.z; hA[15*LDH+tid]=d.w;
        float dd = a.x*DW[0] + a.y*DW[1] + a.z*DW[2] + a.w*DW[3]
                 + b.x*DW[4] + b.y*DW[5] + b.z*DW[6] + b.w*DW[7];
        dd *= 0.3535533905932738f;
        g_EDN[e] = tanhf(dd * dd);
    }
    stage_B(Bs, magw, 832, 16, tid);       // magw j=0 -> half 0
    __syncthreads();

    ull acc[32];

    // magw x13, double-buffered in the two 16x68 halves of Bs: ONE sync/tile
    for (int j = 0; j < 13; j++) {
        float* cur = Bs + (j & 1) * (16 * 68);
        float* nxt = Bs + ((j + 1) & 1) * (16 * 68);
        if (j < 12) stage_B(nxt, magw + (j + 1) * 64, 832, 16, tid);
        else        stage_B(nxt, w0, 64, 16, tid);
        tile_mm<16>(hA, cur, acc, tx, ty);
        write_gmem_h(g_WM + e0 * 832 + j * 64, 832, acc, 0.25f, tx, ty);
        __syncthreads();
    }

    // layer 0 (w0 staged in half 1)
    tile_mm<16>(hA, Bs + 16 * 68, acc, tx, ty);
    __syncthreads();
    write_h(hA, acc, 0.25f, tx, ty);
    stage_B(Bs, w1, 64, 64, tid);
    __syncthreads();

    // layer 1
    tile_mm<64>(hA, Bs, acc, tx, ty);
    __syncthreads();
    write_h(hA, acc, 0.125f, tx, ty);
    stage_B(Bs, w2, 64, 64, tid);
    __syncthreads();

    // layer 2
    tile_mm<64>(hA, Bs, acc, tx, ty);
    __syncthreads();
    write_h(hA, acc, 0.125f, tx, ty);
    stage_B(Bs, w3, 320, 64, tid);
    __syncthreads();

    // TP x5 (fp16 store)
    for (int j = 0; j < 5; j++) {
        tile_mm<64>(hA, Bs, acc, tx, ty);
        __syncthreads();
        write_gmem_h(g_TP + e0 * 320 + j * 64, 320, acc, 0.125f, tx, ty);
        if (j < 4) stage_B(Bs, w3 + (j + 1) * 64, 320, 64, tid);
        __syncthreads();
    }
}

// ================= fused tail: lin (phase 1, smem) + skip (phase 2) ==========
#define TLD 65
#define SM_TAIL ((4*32*68 + 64*TLD) * 4)

__global__ void __launch_bounds__(128) k_tail(
    const float* __restrict__ lins, const float* __restrict__ linv,
    const float* __restrict__ skips, const float* __restrict__ skipv,
    float* __restrict__ out)
{
    extern __shared__ float smt[];
    float* As   = smt;
    float* Bs   = smt + 2 * 32 * 68;
    float* Msel = smt + 4 * 32 * 68;

    const int tid = threadIdx.x;
    const int tx = tid & 7;
    const int ty = tid >> 3;
    const long row0 = (long)blockIdx.x * 64;
    const int z = blockIdx.z;
    const int arow = tid & 63;
    const int kseg = (tid >> 6) * 16;

    // ---------- phase 1: msel tile ----------
    const float* Arow;
    const float* B1;
    int K1; float a1;
    if (z == 0) {
        Arow = g_MS + (row0 + arow) * 320;
        B1 = lins; K1 = 320; a1 = 0.05590169943749474f;
    } else {
        Arow = g_MV + (row0 + arow) * 1536 + (z - 1) * 512;
        B1 = linv; K1 = 512; a1 = 0.044194173824159216f;
    }

    ull acc[16];
#pragma unroll
    for (int i = 0; i < 16; i++) acc[i] = 0ull;

#pragma unroll
    for (int c = 0; c < 4; c++) {
        int kk = kseg + c * 4;
        float4 v = *(const float4*)(Arow + kk);
        As[(kk+0)*68 + arow] = v.x; As[(kk+1)*68 + arow] = v.y;
        As[(kk+2)*68 + arow] = v.z; As[(kk+3)*68 + arow] = v.w;
    }
#pragma unroll
    for (int j = 0; j < 4; j++) {
        int kk = (tid >> 4) + j * 8;
        int c  = (tid & 15) * 4;
        *(float4*)(Bs + kk * 68 + c) = *(const float4*)(B1 + (size_t)kk * 64 + c);
    }
    __syncthreads();

    const int NT1 = K1 / 32;
    for (int t = 0; t < NT1; t++) {
        const float* Ab = As + (t & 1) * (32 * 68);
        const float* Bb = Bs + (t & 1) * (32 * 68);
        if (t + 1 < NT1) {
            float* Ad = As + ((t + 1) & 1) * (32 * 68);
            float* Bd = Bs + ((t + 1) & 1) * (32 * 68);
            int k0 = (t + 1) * 32;
#pragma unroll
            for (int c = 0; c < 4; c++) {
                int kk = kseg + c * 4;
                float4 v = *(const float4*)(Arow + k0 + kk);
                Ad[(kk+0)*68 + arow] = v.x; Ad[(kk+1)*68 + arow] = v.y;
                Ad[(kk+2)*68 + arow] = v.z; Ad[(kk+3)*68 + arow] = v.w;
            }
#pragma unroll
            for (int j = 0; j < 4; j++) {
                int kk = (tid >> 4) + j * 8;
                int c  = (tid & 15) * 4;
                *(float4*)(Bd + kk * 68 + c) =
                    *(const float4*)(B1 + (size_t)(k0 + kk) * 64 + c);
            }
        }
#pragma unroll 4
        for (int kk = 0; kk < 32; kk++) {
            ulonglong2 aA = *(const ulonglong2*)(Ab + kk * 68 + ty * 4);
            const float4* bp = (const float4*)(Bb + kk * 68 + tx * 8);
            float4 b0 = bp[0], b1 = bp[1];
            ull bb[8];
            bb[0] = bcast(b0.x); bb[1] = bcast(b0.y);
            bb[2] = bcast(b0.z); bb[3] = bcast(b0.w);
            bb[4] = bcast(b1.x); bb[5] = bcast(b1.y);
            bb[6] = bcast(b1.z); bb[7] = bcast(b1.w);
#pragma unroll
            for (int c = 0; c < 8; c++) {
                fma2(acc[c],     aA.x, bb[c]);
                fma2(acc[8 + c], aA.y, bb[c]);
            }
        }
        __syncthreads();
    }
#pragma unroll
    for (int rp = 0; rp < 2; rp++) {
        int r = ty * 4 + rp * 2;
#pragma unroll
        for (int c = 0; c < 8; c++) {
            ull av = acc[rp * 8 + c];
            Msel[r * TLD + tx * 8 + c]       = lo2(av) * a1;
            Msel[(r + 1) * TLD + tx * 8 + c] = hi2(av) * a1;
        }
    }
    __syncthreads();

    // ---------- phase 2: skip GEMM (K=640) ----------
    float ai[10];
#pragma unroll
    for (int v = 0; v < 10; v++) ai[v] = g_AI[(row0 + arow) * 10 + v];
    const float* B2 = (z == 0) ? skips : skipv;
    const float* mrow = Msel + arow * TLD;

#pragma unroll
    for (int i = 0; i < 16; i++) acc[i] = 0ull;

#pragma unroll 8
    for (int c = 0; c < 16; c++) {
        int k = kseg + c;
        int u = (k * 6554) >> 16;
        int v = k - u * 10;
        As[(kseg + c) * 68 + arow] = mrow[u] * ai[v];
    }
#pragma unroll
    for (int j = 0; j < 4; j++) {
        int kk = (tid >> 4) + j * 8;
        int c  = (tid & 15) * 4;
        *(float4*)(Bs + kk * 68 + c) = *(const float4*)(B2 + (size_t)kk * 64 + c);
    }
    __syncthreads();

    for (int t = 0; t < 20; t++) {
        const float* Ab = As + (t & 1) * (32 * 68);
        const float* Bb = Bs + (t & 1) * (32 * 68);
        if (t + 1 < 20) {
            float* Ad = As + ((t + 1) & 1) * (32 * 68);
            float* Bd = Bs + ((t + 1) & 1) * (32 * 68);
            int k0 = (t + 1) * 32;
#pragma unroll 8
            for (int c = 0; c < 16; c++) {
                int k = k0 + kseg + c;
                int u = (k * 6554) >> 16;
                int v = k - u * 10;
                Ad[(kseg + c) * 68 + arow] = mrow[u] * ai[v];
            }
#pragma unroll
            for (int j = 0; j < 4; j++) {
                int kk = (tid >> 4) + j * 8;
                int c  = (tid & 15) * 4;
                *(float4*)(Bd + kk * 68 + c) =
                    *(const float4*)(B2 + (size_t)(k0 + kk) * 64 + c);
            }
        }
#pragma unroll 4
        for (int kk = 0; kk < 32; kk++) {
            ulonglong2 aA = *(const ulonglong2*)(Ab + kk * 68 + ty * 4);
            const float4* bp = (const float4*)(Bb + kk * 68 + tx * 8);
            float4 b0 = bp[0], b1 = bp[1];
            ull bb[8];
            bb[0] = bcast(b0.x); bb[1] = bcast(b0.y);
            bb[2] = bcast(b0.z); bb[3] = bcast(b0.w);
            bb[4] = bcast(b1.x); bb[5] = bcast(b1.y);
            bb[6] = bcast(b1.z); bb[7] = bcast(b1.w);
#pragma unroll
            for (int c = 0; c < 8; c++) {
                fma2(acc[c],     aA.x, bb[c]);
                fma2(acc[8 + c], aA.y, bb[c]);
            }
        }
        __syncthreads();
    }

    const float a640 = 0.03952847075210474f;
#pragma unroll
    for (int rp = 0; rp < 2; rp++) {
        long r = row0 + ty * 4 + rp * 2;
#pragma unroll
        for (int c = 0; c < 8; c++) {
            ull av = acc[rp * 8 + c];
            long col = (long)(tx * 8 + c) * 4 + z;
            out[r * 256 + col]       = lo2(av) * a640;
            out[(r + 1) * 256 + col] = hi2(av) * a640;
        }
    }
}

// ---------------- scan (re-zero CNT) + scatter (sorted copies) ----------------
__global__ void k_scan()
{
    __shared__ int part[1024];
    int t = threadIdx.x;
    int loc[8]; int s = 0;
#pragma unroll
    for (int j = 0; j < 8; j++) { loc[j] = s; s += g_CNT[t * 8 + j]; }
    part[t] = s;
    __syncthreads();
    for (int off = 1; off < 1024; off <<= 1) {
        int v = (t >= off) ? part[t - off] : 0;
        __syncthreads();
        part[t] += v;
        __syncthreads();
    }
    int excl = part[t] - s;
#pragma unroll
    for (int j = 0; j < 8; j++) {
        g_OFF[t * 8 + j] = excl + loc[j];
        g_CNT[t * 8 + j] = 0;
    }
    if (t == 1023) g_OFF[N_NODES] = part[1023];
}
__global__ void k_scatter(const int* __restrict__ EI, const float* __restrict__ EA)
{
    int e = blockIdx.x * 256 + threadIdx.x;
    int r = EI[N_EDGES + e];
    int p = g_OFF[r] + atomicAdd(&g_CUR[r], 1);
    g_SORT[p] = e;
    g_SNDS[p] = EI[e];
    g_EAS[p]  = *(const float4*)(EA + (size_t)e * 4);
    g_EDNS[p] = g_EDN[e];
}

// ---------------- per-node combine (fp16 TP/WM loads) ----------
__global__ void __launch_bounds__(64) k_mm(const float* __restrict__ MA,
                                           const float* __restrict__ ATTR)
{
    const int n = blockIdx.x;
    const int u = threadIdx.x;
    const int beg = g_OFF[n], end = g_OFF[n + 1];

    float as0 = 0, as1 = 0, as2 = 0, as3 = 0, as4 = 0;
    float av[8][3];
#pragma unroll
    for (int j = 0; j < 8; j++)
#pragma unroll
        for (int i = 0; i < 3; i++) av[j][i] = 0.f;
    float dens = 0.f;

    const float I3 = 0.5773502691896258f;
    const float I2 = 0.7071067811865476f;

    int e_n = 0;
    float4 ea_c = make_float4(0,0,0,0), ma_c = make_float4(0,0,0,0);
    float xs_c = 0, vx_c = 0, vy_c = 0, vz_c = 0, ed_c = 0;
    float t_c[5], w_c[13];
#pragma unroll
    for (int i = 0; i < 5; i++) t_c[i] = 0.f;
#pragma unroll
    for (int i = 0; i < 13; i++) w_c[i] = 0.f;

    if (beg < end) {
        int ec = g_SORT[beg];
        if (beg + 1 < end) e_n = g_SORT[beg + 1];
        int sc = g_SNDS[beg];
        ea_c = g_EAS[beg];
        ed_c = g_EDNS[beg];
        ma_c = *(const float4*)(MA + (size_t)sc * 4);
        xs_c = g_S[(size_t)sc * 64 + u];
        const float* vp = g_V + (size_t)sc * 192 + u;
        vx_c = vp[0]; vy_c = vp[64]; vz_c = vp[128];
        const __half* tp = g_TP + (size_t)ec * 320 + u;
#pragma unroll
        for (int i = 0; i < 5; i++) t_c[i] = __half2float(tp[i * 64]);
        const __half* wm = g_WM + (size_t)ec * 832 + u;
#pragma unroll
        for (int i = 0; i < 13; i++) w_c[i] = __half2float(wm[i * 64]);
    }

    for (int q = beg; q < end; q++) {
        float4 ea_nn = make_float4(0,0,0,0), ma_nn = make_float4(0,0,0,0);
        float xs_nn = 0, vx_nn = 0, vy_nn = 0, vz_nn = 0, ed_nn = 0;
        float t_nn[5], w_nn[13];
#pragma unroll
        for (int i = 0; i < 5; i++) t_nn[i] = 0.f;
#pragma unroll
        for (int i = 0; i < 13; i++) w_nn[i] = 0.f;
        int e_2 = 0;
        if (q + 1 < end) {
            if (q + 2 < end) e_2 = g_SORT[q + 2];
            int sn = g_SNDS[q + 1];
            ea_nn = g_EAS[q + 1];
            ed_nn = g_EDNS[q + 1];
            ma_nn = *(const float4*)(MA + (size_t)sn * 4);
            xs_nn = g_S[(size_t)sn * 64 + u];
            const float* vp = g_V + (size_t)sn * 192 + u;
            vx_nn = vp[0]; vy_nn = vp[64]; vz_nn = vp[128];
            const __half* tp = g_TP + (size_t)e_n * 320 + u;
#pragma unroll
            for (int i = 0; i < 5; i++) t_nn[i] = __half2float(tp[i * 64]);
            const __half* wm = g_WM + (size_t)e_n * 832 + u;
#pragma unroll
            for (int i = 0; i < 13; i++) w_nn[i] = __half2float(wm[i * 64]);
        }

        const float y0 = ea_c.x, yx = ea_c.y, yy = ea_c.z, yz = ea_c.w;
        const float m0 = ma_c.x, mx = ma_c.y, my = ma_c.z, mz = ma_c.w;
        const float xs = xs_c, vx = vx_c, vy = vy_c, vz = vz_c;

        const float ms0 = t_c[0] * xs * y0;
        const float A0x = t_c[1] * xs * yx, A0y = t_c[1] * xs * yy, A0z = t_c[1] * xs * yz;
        const float B0x = t_c[2] * vx * y0, B0y = t_c[2] * vy * y0, B0z = t_c[2] * vz * y0;
        const float ms1 = t_c[3] * (vx * yx + vy * yy + vz * yz) * I3;
        const float cx = vy * yz - vz * yy;
        const float cy = vz * yx - vx * yz;
        const float cz = vx * yy - vy * yx;
        const float C0x = t_c[4] * cx * I2, C0y = t_c[4] * cy * I2, C0z = t_c[4] * cz * I2;

        as0 += w_c[0] * ms0 * m0;
        { float w_ = w_c[1] * ms0;  av[0][0] += w_ * mx; av[0][1] += w_ * my; av[0][2] += w_ * mz; }
        as1 += w_c[2] * ms1 * m0;
        { float w_ = w_c[3] * ms1;  av[1][0] += w_ * mx; av[1][1] += w_ * my; av[1][2] += w_ * mz; }

        { float w_ = w_c[4] * m0;   av[2][0] += w_ * A0x; av[2][1] += w_ * A0y; av[2][2] += w_ * A0z; }
        as2 += w_c[5] * (A0x * mx + A0y * my + A0z * mz) * I3;
        { float w_ = w_c[6] * I2;
          av[3][0] += w_ * (A0y * mz - A0z * my);
          av[3][1] += w_ * (A0z * mx - A0x * mz);
          av[3][2] += w_ * (A0x * my - A0y * mx); }

        { float w_ = w_c[7] * m0;   av[4][0] += w_ * B0x; av[4][1] += w_ * B0y; av[4][2] += w_ * B0z; }
        as3 += w_c[8] * (B0x * mx + B0y * my + B0z * mz) * I3;
        { float w_ = w_c[9] * I2;
          av[5][0] += w_ * (B0y * mz - B0z * my);
          av[5][1] += w_ * (B0z * mx - B0x * mz);
          av[5][2] += w_ * (B0x * my - B0y * mx); }

        { float w_ = w_c[10] * m0;  av[6][0] += w_ * C0x; av[6][1] += w_ * C0y; av[6][2] += w_ * C0z; }
        as4 += w_c[11] * (C0x * mx + C0y * my + C0z * mz) * I3;
        { float w_ = w_c[12] * I2;
          av[7][0] += w_ * (C0y * mz - C0z * my);
          av[7][1] += w_ * (C0z * mx - C0x * mz);
          av[7][2] += w_ * (C0x * my - C0y * mx); }

        dens += ed_c;

        ea_c = ea_nn; ma_c = ma_nn;
        xs_c = xs_nn; vx_c = vx_nn; vy_c = vy_nn; vz_c = vz_nn; ed_c = ed_nn;
#pragma unroll
        for (int i = 0; i < 5; i++) t_c[i] = t_nn[i];
#pragma unroll
        for (int i = 0; i < 13; i++) w_c[i] = w_nn[i];
        e_n = e_2;
    }

    const size_t b = (size_t)n * 320 + u;
    g_MS[b]       = as0;
    g_MS[b + 64]  = as1;
    g_MS[b + 128] = as2;
    g_MS[b + 192] = as3;
    g_MS[b + 256] = as4;
    const size_t bv = (size_t)n * 1536 + u;
#pragma unroll
    for (int i = 0; i < 3; i++)
#pragma unroll
        for (int j = 0; j < 8; j++)
            g_MV[bv + i * 512 + j * 64] = av[j][i];
    if (u < 10) g_AI[n * 10 + u] = ATTR[n * 10 + u] / (dens + 1.f);
    if (u == 0) g_CUR[n] = 0;
}

// ---------------- launcher ----------------
extern "C" void kernel_launch(void* const* d_in, const int* in_sizes, int n_in,
                              void* d_out, int out_size)
{
    (void)in_sizes; (void)n_in; (void)out_size;
    const float* node_attrs = (const float*)d_in[0];
    const float* node_feats = (const float*)d_in[1];
    const float* edge_attrs = (const float*)d_in[2];
    const float* edge_feats = (const float*)d_in[3];
    const int*   edge_index = (const int*)  d_in[4];
    const float* maginv     = (const float*)d_in[5];
    const float* magattr    = (const float*)d_in[6];
    const float* Wups       = (const float*)d_in[7];
    const float* Wupv       = (const float*)d_in[8];
    const float* w0         = (const float*)d_in[9];
    const float* w1         = (const float*)d_in[10];
    const float* w2         = (const float*)d_in[11];
    const float* w3         = (const float*)d_in[12];
    const float* magw       = (const float*)d_in[13];
    const float* densw      = (const float*)d_in[14];
    const float* lins       = (const float*)d_in[15];
    const float* linv       = (const float*)d_in[16];
    const float* skips      = (const float*)d_in[17];
    const float* skipv      = (const float*)d_in[18];
    float* out = (float*)d_out;

    cudaFuncSetAttribute(k_mega, cudaFuncAttributeMaxDynamicSharedMemorySize, SM_MLP);
    cudaFuncSetAttribute(k_tail, cudaFuncAttributeMaxDynamicSharedMemorySize, SM_TAIL);

    // 0: mega (edge path + hist + density + node up-proj), single wave
    k_mega<<<EDGE_BLOCKS + UPB, 128, SM_MLP>>>(
        edge_feats, maginv, edge_index, w0, w1, w2, w3, magw, densw,
        node_feats, Wups, Wupv);
    // 1, 2: sort
    k_scan   <<<1, 1024>>>();
    k_scatter<<<N_EDGES/256, 256>>>(edge_index, edge_attrs);
    // 3: per-node combine (PROFILED SLOT)
    k_mm<<<N_NODES, 64>>>(magattr, node_attrs);
    // 4: fused lin + skip tail
    k_tail<<<dim3(N_NODES/64, 1, 4), 128, SM_TAIL>>>(lins, linv, skips, skipv, out);
}

// round 17
// speedup vs baseline: 1.7684x; 1.1456x over previous
#include <cuda_runtime.h>
#include <cuda_fp16.h>
#include <math.h>

#define N_NODES 8192
#define N_EDGES 65536

typedef unsigned long long ull;

// ---------------- scratch (static device globals; zero-initialized) ----------------
__device__ float g_S   [N_NODES*64];
__device__ float g_V   [N_NODES*192];
__device__ float g_EDN [N_EDGES];
__device__ __half g_TP [(size_t)N_EDGES*320];   // fp16
__device__ __half g_WM [(size_t)N_EDGES*832];   // fp16
__device__ float g_MS  [N_NODES*320];
__device__ float g_MV  [N_NODES*1536];
__device__ float g_AI  [N_NODES*10];
__device__ int   g_CNT [N_NODES];
__device__ int   g_CUR [N_NODES];
__device__ int   g_OFF [N_NODES+1];
__device__ int   g_SORT[N_EDGES];
__device__ int   g_SNDS[N_EDGES];
__device__ float4 g_EAS[N_EDGES];
__device__ float g_EDNS[N_EDGES];

__device__ __forceinline__ ull bcast(float f) {
    unsigned int u = __float_as_uint(f);
    ull r;
    asm("mov.b64 %0, {%1, %1};" : "=l"(r) : "r"(u));
    return r;
}
__device__ __forceinline__ ull pack2(float a, float b) {
    return ((ull)__float_as_uint(b) << 32) | __float_as_uint(a);
}
__device__ __forceinline__ void fma2(ull& acc, ull a, ull b) {
    asm("fma.rn.f32x2 %0, %1, %2, %0;" : "+l"(acc) : "l"(a), "l"(b));
}
__device__ __forceinline__ float lo2(ull v) { return __uint_as_float((unsigned int)v); }
__device__ __forceinline__ float hi2(ull v) { return __uint_as_float((unsigned int)(v >> 32)); }
__device__ __forceinline__ float silu(float v) { return v / (1.f + __expf(-v)); }

// ================= shared microkernel pieces =================
#define LDH 132
#define BSZE (64*68)
#define SM_MLP ((64*LDH + BSZE) * 4)       // 51.2 KB, 4 blocks/SM
#define EDGE_BLOCKS (N_EDGES/128)          // 512
#define UPB 64

__device__ __forceinline__ void stage_B(float* Bs, const float* __restrict__ src,
                                        int srcStride, int rows, int tid)
{
    for (int j = 0; j < rows / 8; j++) {
        int kk = (tid >> 4) + j * 8;
        int c  = (tid & 15) * 4;
        *(float4*)(Bs + kk * 68 + c) = *(const float4*)(src + (size_t)kk * srcStride + c);
    }
}

// accumulate (no zero-init): 8 rows x 8 cols per thread, A stride LDH
template<int K>
__device__ __forceinline__ void tile_acc(const float* hsrc, const float* Bs,
                                         ull* acc, int tx, int ty)
{
#pragma unroll 4
    for (int kk = 0; kk < K; kk++) {
        const ulonglong2* ap = (const ulonglong2*)(hsrc + kk * LDH + ty * 8);
        ulonglong2 aA = ap[0];
        ulonglong2 aB = ap[1];
        const float4* bp = (const float4*)(Bs + kk * 68 + tx * 8);
        float4 b0 = bp[0], b1 = bp[1];
        ull bb[8];
        bb[0] = bcast(b0.x); bb[1] = bcast(b0.y);
        bb[2] = bcast(b0.z); bb[3] = bcast(b0.w);
        bb[4] = bcast(b1.x); bb[5] = bcast(b1.y);
        bb[6] = bcast(b1.z); bb[7] = bcast(b1.w);
#pragma unroll
        for (int c = 0; c < 8; c++) {
            fma2(acc[c],      aA.x, bb[c]);
            fma2(acc[8 + c],  aA.y, bb[c]);
            fma2(acc[16 + c], aB.x, bb[c]);
            fma2(acc[24 + c], aB.y, bb[c]);
        }
    }
}

template<int K>
__device__ __forceinline__ void tile_mm(const float* hsrc, const float* Bs,
                                        ull* acc, int tx, int ty)
{
#pragma unroll
    for (int i = 0; i < 32; i++) acc[i] = 0ull;
    tile_acc<K>(hsrc, Bs, acc, tx, ty);
}

__device__ __forceinline__ void write_gmem(float* dst, int rs, const ull* acc,
                                           float alpha, int tx, int ty)
{
#pragma unroll
    for (int rp = 0; rp < 4; rp++) {
        int r = ty * 8 + rp * 2;
        float* c0 = dst + (size_t)r * rs + tx * 8;
        float* c1 = c0 + rs;
        float4 l0, l1, h0, h1;
        l0.x = lo2(acc[rp*8+0]) * alpha; h0.x = hi2(acc[rp*8+0]) * alpha;
        l0.y = lo2(acc[rp*8+1]) * alpha; h0.y = hi2(acc[rp*8+1]) * alpha;
        l0.z = lo2(acc[rp*8+2]) * alpha; h0.z = hi2(acc[rp*8+2]) * alpha;
        l0.w = lo2(acc[rp*8+3]) * alpha; h0.w = hi2(acc[rp*8+3]) * alpha;
        l1.x = lo2(acc[rp*8+4]) * alpha; h1.x = hi2(acc[rp*8+4]) * alpha;
        l1.y = lo2(acc[rp*8+5]) * alpha; h1.y = hi2(acc[rp*8+5]) * alpha;
        l1.z = lo2(acc[rp*8+6]) * alpha; h1.z = hi2(acc[rp*8+6]) * alpha;
        l1.w = lo2(acc[rp*8+7]) * alpha; h1.w = hi2(acc[rp*8+7]) * alpha;
        *(float4*)(c0)     = l0;
        *(float4*)(c0 + 4) = l1;
        *(float4*)(c1)     = h0;
        *(float4*)(c1 + 4) = h1;
    }
}

// fp16 tile store
struct h2x4 { __half2 a, b, c, d; };
__device__ __forceinline__ void write_gmem_h(__half* dst, int rs, const ull* acc,
                                             float alpha, int tx, int ty)
{
#pragma unroll
    for (int rp = 0; rp < 4; rp++) {
        int r = ty * 8 + rp * 2;
        __half* c0 = dst + (size_t)r * rs + tx * 8;
        __half* c1 = c0 + rs;
        float lo[8], hi[8];
#pragma unroll
        for (int c = 0; c < 8; c++) {
            lo[c] = lo2(acc[rp*8+c]) * alpha;
            hi[c] = hi2(acc[rp*8+c]) * alpha;
        }
        h2x4 pl, ph;
        pl.a = __floats2half2_rn(lo[0], lo[1]);
        pl.b = __floats2half2_rn(lo[2], lo[3]);
        pl.c = __floats2half2_rn(lo[4], lo[5]);
        pl.d = __floats2half2_rn(lo[6], lo[7]);
        ph.a = __floats2half2_rn(hi[0], hi[1]);
        ph.b = __floats2half2_rn(hi[2], hi[3]);
        ph.c = __floats2half2_rn(hi[4], hi[5]);
        ph.d = __floats2half2_rn(hi[6], hi[7]);
        *(h2x4*)(c0) = pl;
        *(h2x4*)(c1) = ph;
    }
}

__device__ __forceinline__ void write_h(float* hdst, const ull* acc,
                                        float alpha, int tx, int ty)
{
#pragma unroll
    for (int rp = 0; rp < 4; rp++) {
        int r = ty * 8 + rp * 2;
#pragma unroll
        for (int c = 0; c < 8; c++) {
            float v0 = silu(lo2(acc[rp*8+c]) * alpha);
            float v1 = silu(hi2(acc[rp*8+c]) * alpha);
            *(ull*)(hdst + (tx * 8 + c) * LDH + r) = pack2(v0, v1);
        }
    }
}

// ================= mega kernel =================
__global__ void __launch_bounds__(128, 4) k_mega(
    const float* __restrict__ EF, const float* __restrict__ MI,
    const int* __restrict__ EI,
    const float* __restrict__ w0, const float* __restrict__ w1,
    const float* __restrict__ w2, const float* __restrict__ w3,
    const float* __restrict__ magw, const float* __restrict__ DW,
    const float* __restrict__ feats,
    const float* __restrict__ Wups, const float* __restrict__ Wupv)
{
    extern __shared__ float sm[];
    float* hA = sm;                 // 64 x LDH
    float* Bs = sm + 64 * LDH;      // 64 x 68 (magw phase: two 16x68 halves)

    const int tid = threadIdx.x;
    const int tx = tid & 7, ty = tid >> 3;

    if (blockIdx.x >= EDGE_BLOCKS) {
        const long row0 = (long)(blockIdx.x - EDGE_BLOCKS) * 128;
        ull acc[32];
#pragma unroll 1
        for (int z = 0; z < 4; z++) {
            if (z > 0) __syncthreads();
            if (z == 0) {
                const float* Ar = feats + (row0 + tid) * 256;
#pragma unroll
                for (int k4 = 0; k4 < 16; k4++) {
                    float4 v = *(const float4*)(Ar + k4 * 4);
                    hA[(k4*4 + 0) * LDH + tid] = v.x;
                    hA[(k4*4 + 1) * LDH + tid] = v.y;
                    hA[(k4*4 + 2) * LDH + tid] = v.z;
                    hA[(k4*4 + 3) * LDH + tid] = v.w;
                }
            } else {
                const float* Ar = feats + (row0 + tid) * 256 + 64 + (z - 1);
#pragma unroll 8
                for (int k = 0; k < 64; k++)
                    hA[k * LDH + tid] = Ar[k * 3];
            }
            stage_B(Bs, (z == 0) ? Wups : Wupv, 64, 64, tid);
            __syncthreads();
            tile_mm<64>(hA, Bs, acc, tx, ty);
            if (z == 0)
                write_gmem(g_S + row0 * 64, 64, acc, 0.125f, tx, ty);
            else
                write_gmem(g_V + row0 * 192 + (z - 1) * 64, 192, acc, 0.125f, tx, ty);
        }
        return;
    }

    // ====== edge-path block ======
    const size_t e0 = (size_t)blockIdx.x * 128;
    {
        size_t e = e0 + tid;
        float4 a = *(const float4*)(EF + e * 8);
        float4 b = *(const float4*)(EF + e * 8 + 4);
        int snd = EI[e];
        int rcv = EI[N_EDGES + e];
        atomicAdd(&g_CNT[rcv], 1);
        float4 c = *(const float4*)(MI + (size_t)snd * 8);
        float4 d = *(const float4*)(MI + (size_t)snd * 8 + 4);
        hA[ 0*LDH+tid]=a.x; hA[ 1*LDH+tid]=a.y; hA[ 2*LDH+tid]=a.z; hA[ 3*LDH+tid]=a.w;
        hA[ 4*LDH+tid]=b.x; hA[ 5*LDH+tid]=b.y; hA[ 6*LDH+tid]=b.z; hA[ 7*LDH+tid]=b.w;
        hA[ 8*LDH+tid]=c.x; hA[ 9*LDH+tid]=c.y; hA[10*LDH+tid]=c.z; hA[11*LDH+tid]=c.w;
        hA[12*LDH+tid]=d.x; hA[13*LDH+tid]=d.y; hA[14*LDH+tid]=d.z; hA[15*LDH+tid]=d.w;
        float dd = a.x*DW[0] + a.y*DW[1] + a.z*DW[2] + a.w*DW[3]
                 + b.x*DW[4] + b.y*DW[5] + b.z*DW[6] + b.w*DW[7];
        dd *= 0.3535533905932738f;
        g_EDN[e] = tanhf(dd * dd);
    }
    stage_B(Bs, magw, 832, 16, tid);       // magw j=0 -> half 0
    __syncthreads();

    ull acc[32];

    // magw x13, double-buffered in the two 16x68 halves of Bs
    for (int j = 0; j < 13; j++) {
        float* cur = Bs + (j & 1) * (16 * 68);
        float* nxt = Bs + ((j + 1) & 1) * (16 * 68);
        if (j < 12) stage_B(nxt, magw + (j + 1) * 64, 832, 16, tid);
        else        stage_B(nxt, w0, 64, 16, tid);
        tile_mm<16>(hA, cur, acc, tx, ty);
        write_gmem_h(g_WM + e0 * 832 + j * 64, 832, acc, 0.25f, tx, ty);
        __syncthreads();
    }

    // layer 0 (w0 staged in half 1)
    tile_mm<16>(hA, Bs + 16 * 68, acc, tx, ty);
    __syncthreads();
    write_h(hA, acc, 0.25f, tx, ty);
    stage_B(Bs, w1, 64, 64, tid);
    __syncthreads();

    // layer 1
    tile_mm<64>(hA, Bs, acc, tx, ty);
    __syncthreads();
    write_h(hA, acc, 0.125f, tx, ty);
    stage_B(Bs, w2, 64, 64, tid);
    __syncthreads();

    // layer 2
    tile_mm<64>(hA, Bs, acc, tx, ty);
    __syncthreads();
    write_h(hA, acc, 0.125f, tx, ty);
    stage_B(Bs, w3, 320, 64, tid);
    __syncthreads();

    // TP x5 (fp16 store)
    for (int j = 0; j < 5; j++) {
        tile_mm<64>(hA, Bs, acc, tx, ty);
        __syncthreads();
        write_gmem_h(g_TP + e0 * 320 + j * 64, 320, acc, 0.125f, tx, ty);
        if (j < 4) stage_B(Bs, w3 + (j + 1) * 64, 320, 64, tid);
        __syncthreads();
    }
}

// ================= fused tail (128-row tile, 8x8 microtile) ==========
// Block = (128-row tile, z). Phase 1: Msel(smem) = MS@lins (K=320) or MV_z@linv (K=512).
// Phase 2: out_z = (Msel*ai) @ skip (K=640). One wave: 64 x 4 = 256 blocks @ 2/SM.
#define TLD 65
#define SM_TAIL ((2*32*LDH + 2*32*68 + 128*TLD) * 4)   // 84.5 KB

__global__ void __launch_bounds__(128, 2) k_tail(
    const float* __restrict__ lins, const float* __restrict__ linv,
    const float* __restrict__ skips, const float* __restrict__ skipv,
    float* __restrict__ out)
{
    extern __shared__ float smt[];
    float* As   = smt;                         // 2 x 32 x LDH
    float* Bs   = smt + 2 * 32 * LDH;          // 2 x 32 x 68
    float* Msel = smt + 2 * 32 * LDH + 2 * 32 * 68;  // 128 x TLD

    const int tid = threadIdx.x;
    const int tx = tid & 7;
    const int ty = tid >> 3;
    const long row0 = (long)blockIdx.x * 128;
    const int z = blockIdx.z;

    ull acc[32];

    // ---------- phase 1 ----------
    const float* Arow;
    const float* B1;
    int K1; float a1;
    if (z == 0) {
        Arow = g_MS + (row0 + tid) * 320;
        B1 = lins; K1 = 320; a1 = 0.05590169943749474f;       // 1/sqrt(320)
    } else {
        Arow = g_MV + (row0 + tid) * 1536 + (z - 1) * 512;
        B1 = linv; K1 = 512; a1 = 0.044194173824159216f;      // 1/sqrt(512)
    }

#pragma unroll
    for (int i = 0; i < 32; i++) acc[i] = 0ull;

    // stage tile 0 (A: thread owns row tid, stages 32 kk; B: 32x64)
#pragma unroll
    for (int c = 0; c < 8; c++) {
        float4 v = *(const float4*)(Arow + c * 4);
        As[(c*4+0)*LDH + tid] = v.x; As[(c*4+1)*LDH + tid] = v.y;
        As[(c*4+2)*LDH + tid] = v.z; As[(c*4+3)*LDH + tid] = v.w;
    }
    stage_B(Bs, B1, 64, 32, tid);
    __syncthreads();

    const int NT1 = K1 / 32;
    for (int t = 0; t < NT1; t++) {
        const float* Ab = As + (t & 1) * (32 * LDH);
        const float* Bb = Bs + (t & 1) * (32 * 68);
        if (t + 1 < NT1) {
            float* Ad = As + ((t + 1) & 1) * (32 * LDH);
            float* Bd = Bs + ((t + 1) & 1) * (32 * 68);
            int k0 = (t + 1) * 32;
#pragma unroll
            for (int c = 0; c < 8; c++) {
                float4 v = *(const float4*)(Arow + k0 + c * 4);
                Ad[(c*4+0)*LDH + tid] = v.x; Ad[(c*4+1)*LDH + tid] = v.y;
                Ad[(c*4+2)*LDH + tid] = v.z; Ad[(c*4+3)*LDH + tid] = v.w;
            }
            stage_B(Bd, B1 + (size_t)k0 * 64, 64, 32, tid);
        }
        tile_acc<32>(Ab, Bb, acc, tx, ty);
        __syncthreads();
    }
    // epilogue phase 1 -> Msel
#pragma unroll
    for (int rp = 0; rp < 4; rp++) {
        int r = ty * 8 + rp * 2;
#pragma unroll
        for (int c = 0; c < 8; c++) {
            ull av = acc[rp * 8 + c];
            Msel[r * TLD + tx * 8 + c]       = lo2(av) * a1;
            Msel[(r + 1) * TLD + tx * 8 + c] = hi2(av) * a1;
        }
    }
    __syncthreads();

    // ---------- phase 2: skip GEMM (K=640) ----------
    float ai[10];
#pragma unroll
    for (int v = 0; v < 10; v++) ai[v] = g_AI[(row0 + tid) * 10 + v];
    const float* B2 = (z == 0) ? skips : skipv;
    const float* mrow = Msel + tid * TLD;

#pragma unroll
    for (int i = 0; i < 32; i++) acc[i] = 0ull;

    // stage tile 0
#pragma unroll 8
    for (int c = 0; c < 32; c++) {
        int u = (c * 6554) >> 16;
        int v = c - u * 10;
        As[c * LDH + tid] = mrow[u] * ai[v];
    }
    stage_B(Bs, B2, 64, 32, tid);
    __syncthreads();

    for (int t = 0; t < 20; t++) {
        const float* Ab = As + (t & 1) * (32 * LDH);
        const float* Bb = Bs + (t & 1) * (32 * 68);
        if (t + 1 < 20) {
            float* Ad = As + ((t + 1) & 1) * (32 * LDH);
            float* Bd = Bs + ((t + 1) & 1) * (32 * 68);
            int k0 = (t + 1) * 32;
#pragma unroll 8
            for (int c = 0; c < 32; c++) {
                int k = k0 + c;
                int u = (k * 6554) >> 16;
                int v = k - u * 10;
                Ad[c * LDH + tid] = mrow[u] * ai[v];
            }
            stage_B(Bd, B2 + (size_t)k0 * 64, 64, 32, tid);
        }
        tile_acc<32>(Ab, Bb, acc, tx, ty);
        __syncthreads();
    }

    // epilogue phase 2 -> out (crs=256, ccs=4, +z)
    const float a640 = 0.03952847075210474f;  // 1/sqrt(640)
#pragma unroll
    for (int rp = 0; rp < 4; rp++) {
        long r = row0 + ty * 8 + rp * 2;
#pragma unroll
        for (int c = 0; c < 8; c++) {
            ull av = acc[rp * 8 + c];
            long col = (long)(tx * 8 + c) * 4 + z;
            out[r * 256 + col]       = lo2(av) * a640;
            out[(r + 1) * 256 + col] = hi2(av) * a640;
        }
    }
}

// ---------------- scan (re-zero CNT) + scatter (sorted copies) ----------------
__global__ void k_scan()
{
    __shared__ int part[1024];
    int t = threadIdx.x;
    int loc[8]; int s = 0;
#pragma unroll
    for (int j = 0; j < 8; j++) { loc[j] = s; s += g_CNT[t * 8 + j]; }
    part[t] = s;
    __syncthreads();
    for (int off = 1; off < 1024; off <<= 1) {
        int v = (t >= off) ? part[t - off] : 0;
        __syncthreads();
        part[t] += v;
        __syncthreads();
    }
    int excl = part[t] - s;
#pragma unroll
    for (int j = 0; j < 8; j++) {
        g_OFF[t * 8 + j] = excl + loc[j];
        g_CNT[t * 8 + j] = 0;
    }
    if (t == 1023) g_OFF[N_NODES] = part[1023];
}
__global__ void k_scatter(const int* __restrict__ EI, const float* __restrict__ EA)
{
    int e = blockIdx.x * 256 + threadIdx.x;
    int r = EI[N_EDGES + e];
    int p = g_OFF[r] + atomicAdd(&g_CUR[r], 1);
    g_SORT[p] = e;
    g_SNDS[p] = EI[e];
    g_EAS[p]  = *(const float4*)(EA + (size_t)e * 4);
    g_EDNS[p] = g_EDN[e];
}

// ---------------- per-node combine (fp16 TP/WM loads) ----------
__global__ void __launch_bounds__(64) k_mm(const float* __restrict__ MA,
                                           const float* __restrict__ ATTR)
{
    const int n = blockIdx.x;
    const int u = threadIdx.x;
    const int beg = g_OFF[n], end = g_OFF[n + 1];

    float as0 = 0, as1 = 0, as2 = 0, as3 = 0, as4 = 0;
    float av[8][3];
#pragma unroll
    for (int j = 0; j < 8; j++)
#pragma unroll
        for (int i = 0; i < 3; i++) av[j][i] = 0.f;
    float dens = 0.f;

    const float I3 = 0.5773502691896258f;
    const float I2 = 0.7071067811865476f;

    int e_n = 0;
    float4 ea_c = make_float4(0,0,0,0), ma_c = make_float4(0,0,0,0);
    float xs_c = 0, vx_c = 0, vy_c = 0, vz_c = 0, ed_c = 0;
    float t_c[5], w_c[13];
#pragma unroll
    for (int i = 0; i < 5; i++) t_c[i] = 0.f;
#pragma unroll
    for (int i = 0; i < 13; i++) w_c[i] = 0.f;

    if (beg < end) {
        int ec = g_SORT[beg];
        if (beg + 1 < end) e_n = g_SORT[beg + 1];
        int sc = g_SNDS[beg];
        ea_c = g_EAS[beg];
        ed_c = g_EDNS[beg];
        ma_c = *(const float4*)(MA + (size_t)sc * 4);
        xs_c = g_S[(size_t)sc * 64 + u];
        const float* vp = g_V + (size_t)sc * 192 + u;
        vx_c = vp[0]; vy_c = vp[64]; vz_c = vp[128];
        const __half* tp = g_TP + (size_t)ec * 320 + u;
#pragma unroll
        for (int i = 0; i < 5; i++) t_c[i] = __half2float(tp[i * 64]);
        const __half* wm = g_WM + (size_t)ec * 832 + u;
#pragma unroll
        for (int i = 0; i < 13; i++) w_c[i] = __half2float(wm[i * 64]);
    }

    for (int q = beg; q < end; q++) {
        float4 ea_nn = make_float4(0,0,0,0), ma_nn = make_float4(0,0,0,0);
        float xs_nn = 0, vx_nn = 0, vy_nn = 0, vz_nn = 0, ed_nn = 0;
        float t_nn[5], w_nn[13];
#pragma unroll
        for (int i = 0; i < 5; i++) t_nn[i] = 0.f;
#pragma unroll
        for (int i = 0; i < 13; i++) w_nn[i] = 0.f;
        int e_2 = 0;
        if (q + 1 < end) {
            if (q + 2 < end) e_2 = g_SORT[q + 2];
            int sn = g_SNDS[q + 1];
            ea_nn = g_EAS[q + 1];
            ed_nn = g_EDNS[q + 1];
            ma_nn = *(const float4*)(MA + (size_t)sn * 4);
            xs_nn = g_S[(size_t)sn * 64 + u];
            const float* vp = g_V + (size_t)sn * 192 + u;
            vx_nn = vp[0]; vy_nn = vp[64]; vz_nn = vp[128];
            const __half* tp = g_TP + (size_t)e_n * 320 + u;
#pragma unroll
            for (int i = 0; i < 5; i++) t_nn[i] = __half2float(tp[i * 64]);
            const __half* wm = g_WM + (size_t)e_n * 832 + u;
#pragma unroll
            for (int i = 0; i < 13; i++) w_nn[i] = __half2float(wm[i * 64]);
        }

        const float y0 = ea_c.x, yx = ea_c.y, yy = ea_c.z, yz = ea_c.w;
        const float m0 = ma_c.x, mx = ma_c.y, my = ma_c.z, mz = ma_c.w;
        const float xs = xs_c, vx = vx_c, vy = vy_c, vz = vz_c;

        const float ms0 = t_c[0] * xs * y0;
        const float A0x = t_c[1] * xs * yx, A0y = t_c[1] * xs * yy, A0z = t_c[1] * xs * yz;
        const float B0x = t_c[2] * vx * y0, B0y = t_c[2] * vy * y0, B0z = t_c[2] * vz * y0;
        const float ms1 = t_c[3] * (vx * yx + vy * yy + vz * yz) * I3;
        const float cx = vy * yz - vz * yy;
        const float cy = vz * yx - vx * yz;
        const float cz = vx * yy - vy * yx;
        const float C0x = t_c[4] * cx * I2, C0y = t_c[4] * cy * I2, C0z = t_c[4] * cz * I2;

        as0 += w_c[0] * ms0 * m0;
        { float w_ = w_c[1] * ms0;  av[0][0] += w_ * mx; av[0][1] += w_ * my; av[0][2] += w_ * mz; }
        as1 += w_c[2] * ms1 * m0;
        { float w_ = w_c[3] * ms1;  av[1][0] += w_ * mx; av[1][1] += w_ * my; av[1][2] += w_ * mz; }

        { float w_ = w_c[4] * m0;   av[2][0] += w_ * A0x; av[2][1] += w_ * A0y; av[2][2] += w_ * A0z; }
        as2 += w_c[5] * (A0x * mx + A0y * my + A0z * mz) * I3;
        { float w_ = w_c[6] * I2;
          av[3][0] += w_ * (A0y * mz - A0z * my);
          av[3][1] += w_ * (A0z * mx - A0x * mz);
          av[3][2] += w_ * (A0x * my - A0y * mx); }

        { float w_ = w_c[7] * m0;   av[4][0] += w_ * B0x; av[4][1] += w_ * B0y; av[4][2] += w_ * B0z; }
        as3 += w_c[8] * (B0x * mx + B0y * my + B0z * mz) * I3;
        { float w_ = w_c[9] * I2;
          av[5][0] += w_ * (B0y * mz - B0z * my);
          av[5][1] += w_ * (B0z * mx - B0x * mz);
          av[5][2] += w_ * (B0x * my - B0y * mx); }

        { float w_ = w_c[10] * m0;  av[6][0] += w_ * C0x; av[6][1] += w_ * C0y; av[6][2] += w_ * C0z; }
        as4 += w_c[11] * (C0x * mx + C0y * my + C0z * mz) * I3;
        { float w_ = w_c[12] * I2;
          av[7][0] += w_ * (C0y * mz - C0z * my);
          av[7][1] += w_ * (C0z * mx - C0x * mz);
          av[7][2] += w_ * (C0x * my - C0y * mx); }

        dens += ed_c;

        ea_c = ea_nn; ma_c = ma_nn;
        xs_c = xs_nn; vx_c = vx_nn; vy_c = vy_nn; vz_c = vz_nn; ed_c = ed_nn;
#pragma unroll
        for (int i = 0; i < 5; i++) t_c[i] = t_nn[i];
#pragma unroll
        for (int i = 0; i < 13; i++) w_c[i] = w_nn[i];
        e_n = e_2;
    }

    const size_t b = (size_t)n * 320 + u;
    g_MS[b]       = as0;
    g_MS[b + 64]  = as1;
    g_MS[b + 128] = as2;
    g_MS[b + 192] = as3;
    g_MS[b + 256] = as4;
    const size_t bv = (size_t)n * 1536 + u;
#pragma unroll
    for (int i = 0; i < 3; i++)
#pragma unroll
        for (int j = 0; j < 8; j++)
            g_MV[bv + i * 512 + j * 64] = av[j][i];
    if (u < 10) g_AI[n * 10 + u] = ATTR[n * 10 + u] / (dens + 1.f);
    if (u == 0) g_CUR[n] = 0;
}

// ---------------- launcher ----------------
extern "C" void kernel_launch(void* const* d_in, const int* in_sizes, int n_in,
                              void* d_out, int out_size)
{
    (void)in_sizes; (void)n_in; (void)out_size;
    const float* node_attrs = (const float*)d_in[0];
    const float* node_feats = (const float*)d_in[1];
    const float* edge_attrs = (const float*)d_in[2];
    const float* edge_feats = (const float*)d_in[3];
    const int*   edge_index = (const int*)  d_in[4];
    const float* maginv     = (const float*)d_in[5];
    const float* magattr    = (const float*)d_in[6];
    const float* Wups       = (const float*)d_in[7];
    const float* Wupv       = (const float*)d_in[8];
    const float* w0         = (const float*)d_in[9];
    const float* w1         = (const float*)d_in[10];
    const float* w2         = (const float*)d_in[11];
    const float* w3         = (const float*)d_in[12];
    const float* magw       = (const float*)d_in[13];
    const float* densw      = (const float*)d_in[14];
    const float* lins       = (const float*)d_in[15];
    const float* linv       = (const float*)d_in[16];
    const float* skips      = (const float*)d_in[17];
    const float* skipv      = (const float*)d_in[18];
    float* out = (float*)d_out;

    cudaFuncSetAttribute(k_mega, cudaFuncAttributeMaxDynamicSharedMemorySize, SM_MLP);
    cudaFuncSetAttribute(k_tail, cudaFuncAttributeMaxDynamicSharedMemorySize, SM_TAIL);

    // 0: mega (edge path + hist + density + node up-proj), single wave
    k_mega<<<EDGE_BLOCKS + UPB, 128, SM_MLP>>>(
        edge_feats, maginv, edge_index, w0, w1, w2, w3, magw, densw,
        node_feats, Wups, Wupv);
    // 1, 2: sort
    k_scan   <<<1, 1024>>>();
    k_scatter<<<N_EDGES/256, 256>>>(edge_index, edge_attrs);
    // 3: per-node combine (PROFILED SLOT)
    k_mm<<<N_NODES, 64>>>(magattr, node_attrs);
    // 4: fused lin + skip tail (128-row tiles, one wave)
    k_tail<<<dim3(N_NODES/128, 1, 4), 128, SM_TAIL>>>(lins, linv, skips, skipv, out);
}